// round 1
// baseline (speedup 1.0000x reference)
#include <cuda_runtime.h>
#include <cuda_bf16.h>
#include <math.h>

// ---------------- problem constants ----------------
#define B_    8
#define D_    512
#define H_    8
#define DH_   64
#define L_    6
#define DFF_  2048
#define GRIDN 10
#define DMLP_ 1024
#define CIN_  2048
#define SEQ_  912          // 1 + 768 + 108 + 35
#define M_    (B_*SEQ_)    // 7296

// ---------------- scratch (static device globals; no runtime alloc) --------
__device__ float g_xin[M_*CIN_];      // embed input, padded rows (t=0 unused)
__device__ float g_h1 [M_*DFF_];     // FFN intermediate
__device__ float g_x  [M_*D_];
__device__ float g_q  [M_*D_];
__device__ float g_k  [M_*D_];
__device__ float g_v  [M_*D_];
__device__ float g_ctx[M_*D_];
__device__ float g_att[M_*D_];
__device__ float g_scores[(size_t)B_*H_*SEQ_*SEQ_];   // ~213 MB
__device__ float g_hmlp[B_*DMLP_];

__device__ __forceinline__ float gelu_f(float x) {
    return 0.5f * x * (1.0f + erff(x * 0.70710678118654752f));
}

// ---------------- gather: feat [B,CIN,HW] -> xin [B,SEQ,CIN] (transpose) ----
__global__ void gather_transpose_k(const float* __restrict__ feat, int HW, int t0,
                                   float* __restrict__ xin) {
    __shared__ float tile[32][33];
    int b   = blockIdx.z;
    int hw0 = blockIdx.x * 32, c0 = blockIdx.y * 32;
    const float* fb = feat + (size_t)b * CIN_ * HW;
    #pragma unroll
    for (int kk = 0; kk < 32; kk += 8) {
        int c  = c0 + threadIdx.y + kk;
        int hw = hw0 + threadIdx.x;
        tile[threadIdx.y + kk][threadIdx.x] = (hw < HW) ? fb[(size_t)c * HW + hw] : 0.f;
    }
    __syncthreads();
    #pragma unroll
    for (int kk = 0; kk < 32; kk += 8) {
        int hw = hw0 + threadIdx.y + kk;
        int c  = c0 + threadIdx.x;
        if (hw < HW)
            xin[((size_t)b * SEQ_ + t0 + hw) * CIN_ + c] = tile[threadIdx.x][threadIdx.y + kk];
    }
}

// ---------------- SGEMM NT: C[M,N] = A[M,K] @ B[N,K]^T + bias, opt gelu -----
// M%128==0, N%128==0, K%16==0 guaranteed by caller.
__global__ __launch_bounds__(256) void sgemm_nt_k(
    int M, int N, int K,
    const float* __restrict__ A, const float* __restrict__ Bm,
    const float* __restrict__ bias, float* __restrict__ C, int act) {
    __shared__ float As[16 * 129];
    __shared__ float Bs[16 * 129];
    int bm = blockIdx.y * 128, bn = blockIdx.x * 128;
    int tid = threadIdx.x;
    float acc[8][8] = {};
    int tx = tid & 15, ty = tid >> 4;
    for (int k0 = 0; k0 < K; k0 += 16) {
        #pragma unroll
        for (int i = 0; i < 2; i++) {
            int s = tid + i * 256;
            int r = s >> 2;
            int kc = (s & 3) << 2;
            float4 va = *(const float4*)(A  + (size_t)(bm + r) * K + k0 + kc);
            float4 vb = *(const float4*)(Bm + (size_t)(bn + r) * K + k0 + kc);
            As[(kc + 0) * 129 + r] = va.x; As[(kc + 1) * 129 + r] = va.y;
            As[(kc + 2) * 129 + r] = va.z; As[(kc + 3) * 129 + r] = va.w;
            Bs[(kc + 0) * 129 + r] = vb.x; Bs[(kc + 1) * 129 + r] = vb.y;
            Bs[(kc + 2) * 129 + r] = vb.z; Bs[(kc + 3) * 129 + r] = vb.w;
        }
        __syncthreads();
        #pragma unroll
        for (int kk = 0; kk < 16; kk++) {
            float a[8], bv[8];
            #pragma unroll
            for (int u = 0; u < 8; u++) {
                a[u]  = As[kk * 129 + ty * 8 + u];
                bv[u] = Bs[kk * 129 + tx * 8 + u];
            }
            #pragma unroll
            for (int i = 0; i < 8; i++)
                #pragma unroll
                for (int j = 0; j < 8; j++)
                    acc[i][j] += a[i] * bv[j];
        }
        __syncthreads();
    }
    #pragma unroll
    for (int i = 0; i < 8; i++) {
        int row = bm + ty * 8 + i;
        #pragma unroll
        for (int j = 0; j < 8; j++) {
            int col = bn + tx * 8 + j;
            float v = acc[i][j] + (bias ? bias[col] : 0.f);
            if (act == 1) v = gelu_f(v);
            C[(size_t)row * N + col] = v;
        }
    }
}

// ---------------- embed epilogue: + conv_b + chan_emb + pos_emb -------------
__global__ void embed_add_k(const float* __restrict__ conv_b,
                            const float* __restrict__ e_org,
                            const float* __restrict__ e_r1,
                            const float* __restrict__ e_r2,
                            const float* __restrict__ pos,
                            float* __restrict__ x) {
    int idx = blockIdx.x * 256 + threadIdx.x;
    const int total = B_ * 911 * D_;
    if (idx >= total) return;
    int d = idx & 511;
    int rest = idx >> 9;
    int tt = rest % 911;
    int b  = rest / 911;
    int ti, tj; const float* ce;
    if (tt < 768)      { int hh = tt >> 5,  ww = tt & 31;  ce = e_org; ti = hh*GRIDN/24; tj = ww*GRIDN/32; }
    else if (tt < 876) { int u = tt - 768;  int hh = u/12, ww = u%12; ce = e_r1; ti = hh*GRIDN/9;  tj = ww*GRIDN/12; }
    else               { int u = tt - 876;  int hh = u/7,  ww = u%7;  ce = e_r2; ti = hh*GRIDN/5;  tj = ww*GRIDN/7;  }
    x[((size_t)(b * SEQ_ + tt + 1)) * D_ + d] += conv_b[d] + ce[d] + pos[(size_t)(ti * GRIDN + tj) * D_ + d];
}

__global__ void cls_set_k(const float* __restrict__ c, float* __restrict__ x) {
    int idx = blockIdx.x * 256 + threadIdx.x;
    if (idx >= B_ * D_) return;
    int b = idx >> 9, d = idx & 511;
    x[(size_t)b * SEQ_ * D_ + d] = c[d];
}

// ---------------- attention scores: per (b,h) 64x64 tiles, K=64 ------------
__global__ __launch_bounds__(256) void attn_scores_k(
    const float* __restrict__ q, const float* __restrict__ k,
    const int* __restrict__ mask, float* __restrict__ scores) {
    __shared__ float Qs[64][65];
    __shared__ float Ks[64][65];
    int bh = blockIdx.z, b = bh >> 3, h = bh & 7;
    int i0 = blockIdx.y * 64, j0 = blockIdx.x * 64;
    int tid = threadIdx.x;
    for (int s = tid; s < 1024; s += 256) {
        int r = s >> 4, c = (s & 15) << 2;
        int gi = i0 + r, gj = j0 + r;
        float4 va = make_float4(0, 0, 0, 0), vb = va;
        if (gi < SEQ_) va = *(const float4*)(q + ((size_t)(b * SEQ_ + gi)) * D_ + h * DH_ + c);
        if (gj < SEQ_) vb = *(const float4*)(k + ((size_t)(b * SEQ_ + gj)) * D_ + h * DH_ + c);
        Qs[r][c] = va.x; Qs[r][c + 1] = va.y; Qs[r][c + 2] = va.z; Qs[r][c + 3] = va.w;
        Ks[r][c] = vb.x; Ks[r][c + 1] = vb.y; Ks[r][c + 2] = vb.z; Ks[r][c + 3] = vb.w;
    }
    __syncthreads();
    int tx = tid & 15, ty = tid >> 4;
    float acc[4][4] = {};
    #pragma unroll 16
    for (int d = 0; d < 64; d++) {
        float a[4], bb[4];
        #pragma unroll
        for (int u = 0; u < 4; u++) { a[u] = Qs[ty * 4 + u][d]; bb[u] = Ks[tx * 4 + u][d]; }
        #pragma unroll
        for (int i = 0; i < 4; i++)
            #pragma unroll
            for (int j = 0; j < 4; j++)
                acc[i][j] += a[i] * bb[j];
    }
    #pragma unroll
    for (int i = 0; i < 4; i++) {
        int gi = i0 + ty * 4 + i;
        if (gi >= SEQ_) continue;
        #pragma unroll
        for (int j = 0; j < 4; j++) {
            int gj = j0 + tx * 4 + j;
            if (gj >= SEQ_) continue;
            float v = (mask[b * SEQ_ + gj] == 0) ? -1e9f : acc[i][j] * 0.125f;
            scores[((size_t)bh * SEQ_ + gi) * SEQ_ + gj] = v;
        }
    }
}

// ---------------- softmax over rows of length SEQ_ --------------------------
__global__ __launch_bounds__(256) void softmax_k(float* __restrict__ scores) {
    __shared__ float red[8];
    __shared__ float bval;
    float* p = scores + (size_t)blockIdx.x * SEQ_;
    int tid = threadIdx.x;
    float mx = -3.4e38f;
    for (int j = tid; j < SEQ_; j += 256) mx = fmaxf(mx, p[j]);
    #pragma unroll
    for (int o = 16; o > 0; o >>= 1) mx = fmaxf(mx, __shfl_xor_sync(~0u, mx, o));
    if ((tid & 31) == 0) red[tid >> 5] = mx;
    __syncthreads();
    if (tid == 0) { float m = red[0]; for (int w = 1; w < 8; w++) m = fmaxf(m, red[w]); bval = m; }
    __syncthreads();
    mx = bval;
    float sum = 0.f;
    for (int j = tid; j < SEQ_; j += 256) { float e = expf(p[j] - mx); p[j] = e; sum += e; }
    #pragma unroll
    for (int o = 16; o > 0; o >>= 1) sum += __shfl_xor_sync(~0u, sum, o);
    __syncthreads();
    if ((tid & 31) == 0) red[tid >> 5] = sum;
    __syncthreads();
    if (tid == 0) { float s = 0; for (int w = 0; w < 8; w++) s += red[w]; bval = 1.f / s; }
    __syncthreads();
    float inv = bval;
    for (int j = tid; j < SEQ_; j += 256) p[j] *= inv;
}

// ---------------- ctx = prob @ v : per (b,h), 64-row tiles, K=SEQ_ ----------
__global__ __launch_bounds__(256) void attn_ctx_k(
    const float* __restrict__ scores, const float* __restrict__ v,
    float* __restrict__ ctx) {
    __shared__ float Ps[64][65];
    __shared__ float Vs[64][65];
    int bh = blockIdx.y, b = bh >> 3, h = bh & 7;
    int i0 = blockIdx.x * 64;
    int tid = threadIdx.x, tx = tid & 15, ty = tid >> 4;
    float acc[4][4] = {};
    for (int j0 = 0; j0 < SEQ_; j0 += 64) {
        for (int s = tid; s < 1024; s += 256) {
            int r = s >> 4, c = (s & 15) << 2;
            int gi = i0 + r, gj = j0 + c, gr = j0 + r;
            float4 vp = make_float4(0, 0, 0, 0), vv = vp;
            if (gi < SEQ_ && gj < SEQ_) vp = *(const float4*)(scores + ((size_t)bh * SEQ_ + gi) * SEQ_ + gj);
            if (gr < SEQ_)              vv = *(const float4*)(v + ((size_t)(b * SEQ_ + gr)) * D_ + h * DH_ + c);
            Ps[r][c] = vp.x; Ps[r][c + 1] = vp.y; Ps[r][c + 2] = vp.z; Ps[r][c + 3] = vp.w;
            Vs[r][c] = vv.x; Vs[r][c + 1] = vv.y; Vs[r][c + 2] = vv.z; Vs[r][c + 3] = vv.w;
        }
        __syncthreads();
        #pragma unroll 16
        for (int kk = 0; kk < 64; kk++) {
            float a[4], bb[4];
            #pragma unroll
            for (int u = 0; u < 4; u++) { a[u] = Ps[ty * 4 + u][kk]; bb[u] = Vs[kk][tx * 4 + u]; }
            #pragma unroll
            for (int i = 0; i < 4; i++)
                #pragma unroll
                for (int j = 0; j < 4; j++)
                    acc[i][j] += a[i] * bb[j];
        }
        __syncthreads();
    }
    #pragma unroll
    for (int i = 0; i < 4; i++) {
        int gi = i0 + ty * 4 + i;
        if (gi >= SEQ_) continue;
        #pragma unroll
        for (int j = 0; j < 4; j++)
            ctx[((size_t)(b * SEQ_ + gi)) * D_ + h * DH_ + tx * 4 + j] = acc[i][j];
    }
}

// ---------------- residual + LayerNorm (row = one block of 128) -------------
__global__ __launch_bounds__(128) void add_ln_k(
    const float* __restrict__ xin, const float* __restrict__ add,
    const float* __restrict__ g, const float* __restrict__ beta,
    float* __restrict__ xout) {
    __shared__ float red[4];
    __shared__ float bval;
    int row = blockIdx.x, tid = threadIdx.x;
    float4 xv = ((const float4*)(xin + (size_t)row * D_))[tid];
    float4 av = ((const float4*)(add + (size_t)row * D_))[tid];
    float4 s;
    s.x = xv.x + av.x; s.y = xv.y + av.y; s.z = xv.z + av.z; s.w = xv.w + av.w;
    float sum = s.x + s.y + s.z + s.w;
    #pragma unroll
    for (int o = 16; o > 0; o >>= 1) sum += __shfl_xor_sync(~0u, sum, o);
    if ((tid & 31) == 0) red[tid >> 5] = sum;
    __syncthreads();
    if (tid == 0) bval = (red[0] + red[1] + red[2] + red[3]) * (1.f / D_);
    __syncthreads();
    float m = bval;
    float d0 = s.x - m, d1 = s.y - m, d2 = s.z - m, d3 = s.w - m;
    float sq = d0 * d0 + d1 * d1 + d2 * d2 + d3 * d3;
    #pragma unroll
    for (int o = 16; o > 0; o >>= 1) sq += __shfl_xor_sync(~0u, sq, o);
    __syncthreads();
    if ((tid & 31) == 0) red[tid >> 5] = sq;
    __syncthreads();
    if (tid == 0) bval = rsqrtf((red[0] + red[1] + red[2] + red[3]) * (1.f / D_) + 1e-6f);
    __syncthreads();
    float rs = bval;
    float4 gv = ((const float4*)g)[tid];
    float4 bv = ((const float4*)beta)[tid];
    float4 o;
    o.x = d0 * rs * gv.x + bv.x; o.y = d1 * rs * gv.y + bv.y;
    o.z = d2 * rs * gv.z + bv.z; o.w = d3 * rs * gv.w + bv.w;
    ((float4*)(xout + (size_t)row * D_))[tid] = o;
}

// ---------------- head ------------------------------------------------------
__global__ __launch_bounds__(256) void head_mlp_k(
    const float* __restrict__ x, const float* __restrict__ w1,
    float* __restrict__ hm) {
    __shared__ float cls[512];
    int b = blockIdx.x;
    for (int d = threadIdx.x; d < 512; d += 256) cls[d] = x[(size_t)b * SEQ_ * D_ + d];
    __syncthreads();
    for (int n = threadIdx.x; n < DMLP_; n += 256) {
        const float* w = w1 + (size_t)n * 512;
        float s = 0.f;
        for (int d = 0; d < 512; d++) s += cls[d] * w[d];
        hm[b * DMLP_ + n] = gelu_f(s);
    }
}

__global__ __launch_bounds__(256) void head_out_k(
    const float* __restrict__ hm, const float* __restrict__ w2,
    float* __restrict__ out) {
    __shared__ float red[8];
    int b = blockIdx.x, tid = threadIdx.x;
    float s = 0.f;
    for (int n = tid; n < DMLP_; n += 256) s += hm[b * DMLP_ + n] * w2[n];
    #pragma unroll
    for (int o = 16; o > 0; o >>= 1) s += __shfl_xor_sync(~0u, s, o);
    if ((tid & 31) == 0) red[tid >> 5] = s;
    __syncthreads();
    if (tid == 0) {
        float t = 0; for (int w = 0; w < 8; w++) t += red[w];
        out[b] = t;
    }
}

// ---------------- host orchestration ----------------------------------------
extern "C" void kernel_launch(void* const* d_in, const int* in_sizes, int n_in,
                              void* d_out, int out_size) {
    const float* feat_org = (const float*)d_in[0];
    const float* feat_r1  = (const float*)d_in[1];
    const float* feat_r2  = (const float*)d_in[2];
    const float* conv_w   = (const float*)d_in[3];
    const float* conv_b   = (const float*)d_in[4];
    const float* e_org    = (const float*)d_in[5];
    const float* e_r1     = (const float*)d_in[6];
    const float* e_r2     = (const float*)d_in[7];
    const float* pos      = (const float*)d_in[8];
    const float* cls_tok  = (const float*)d_in[9];
    const float* Wq = (const float*)d_in[10]; const float* bq = (const float*)d_in[11];
    const float* Wk = (const float*)d_in[12]; const float* bk = (const float*)d_in[13];
    const float* Wv = (const float*)d_in[14]; const float* bv = (const float*)d_in[15];
    const float* Wo = (const float*)d_in[16]; const float* bo = (const float*)d_in[17];
    const float* ln1g = (const float*)d_in[18]; const float* ln1b = (const float*)d_in[19];
    const float* w1 = (const float*)d_in[20]; const float* b1 = (const float*)d_in[21];
    const float* w2 = (const float*)d_in[22]; const float* b2 = (const float*)d_in[23];
    const float* ln2g = (const float*)d_in[24]; const float* ln2b = (const float*)d_in[25];
    const float* pw1 = (const float*)d_in[26]; const float* pw2 = (const float*)d_in[27];
    const int*   mask = (const int*)d_in[28];

    float *xin, *h1, *x, *q, *k, *v, *ctx, *att, *scores, *hmlp;
    cudaGetSymbolAddress((void**)&xin, g_xin);
    cudaGetSymbolAddress((void**)&h1, g_h1);
    cudaGetSymbolAddress((void**)&x, g_x);
    cudaGetSymbolAddress((void**)&q, g_q);
    cudaGetSymbolAddress((void**)&k, g_k);
    cudaGetSymbolAddress((void**)&v, g_v);
    cudaGetSymbolAddress((void**)&ctx, g_ctx);
    cudaGetSymbolAddress((void**)&att, g_att);
    cudaGetSymbolAddress((void**)&scores, g_scores);
    cudaGetSymbolAddress((void**)&hmlp, g_hmlp);

    dim3 tb32(32, 8);
    gather_transpose_k<<<dim3(24, CIN_ / 32, B_), tb32>>>(feat_org, 768, 1,   xin);
    gather_transpose_k<<<dim3(4,  CIN_ / 32, B_), tb32>>>(feat_r1,  108, 769, xin);
    gather_transpose_k<<<dim3(2,  CIN_ / 32, B_), tb32>>>(feat_r2,  35,  877, xin);

    sgemm_nt_k<<<dim3(D_ / 128, M_ / 128), 256>>>(M_, D_, CIN_, xin, conv_w, nullptr, x, 0);
    embed_add_k<<<(B_ * 911 * D_ + 255) / 256, 256>>>(conv_b, e_org, e_r1, e_r2, pos, x);
    cls_set_k<<<(B_ * D_ + 255) / 256, 256>>>(cls_tok, x);

    const int TILES = (SEQ_ + 63) / 64;   // 15
    for (int i = 0; i < L_; i++) {
        const float* Wqi = Wq + (size_t)i * D_ * D_;
        const float* Wki = Wk + (size_t)i * D_ * D_;
        const float* Wvi = Wv + (size_t)i * D_ * D_;
        const float* Woi = Wo + (size_t)i * D_ * D_;
        sgemm_nt_k<<<dim3(D_ / 128, M_ / 128), 256>>>(M_, D_, D_, x, Wqi, bq + i * D_, q, 0);
        sgemm_nt_k<<<dim3(D_ / 128, M_ / 128), 256>>>(M_, D_, D_, x, Wki, bk + i * D_, k, 0);
        sgemm_nt_k<<<dim3(D_ / 128, M_ / 128), 256>>>(M_, D_, D_, x, Wvi, bv + i * D_, v, 0);

        attn_scores_k<<<dim3(TILES, TILES, B_ * H_), 256>>>(q, k, mask, scores);
        softmax_k<<<B_ * H_ * SEQ_, 256>>>(scores);
        attn_ctx_k<<<dim3(TILES, B_ * H_), 256>>>(scores, v, ctx);

        sgemm_nt_k<<<dim3(D_ / 128, M_ / 128), 256>>>(M_, D_, D_, ctx, Woi, bo + i * D_, att, 0);
        add_ln_k<<<M_, 128>>>(x, att, ln1g + i * D_, ln1b + i * D_, x);

        sgemm_nt_k<<<dim3(DFF_ / 128, M_ / 128), 256>>>(M_, DFF_, D_, x, w1 + (size_t)i * DFF_ * D_, b1 + i * DFF_, h1, 1);
        sgemm_nt_k<<<dim3(D_ / 128, M_ / 128), 256>>>(M_, D_, DFF_, h1, w2 + (size_t)i * D_ * DFF_, b2 + i * D_, att, 0);
        add_ln_k<<<M_, 128>>>(x, att, ln2g + i * D_, ln2b + i * D_, x);
    }

    head_mlp_k<<<B_, 256>>>(x, pw1, hmlp);
    head_out_k<<<B_, 256>>>(hmlp, pw2, (float*)d_out);
}

// round 3
// speedup vs baseline: 1.7249x; 1.7249x over previous
#include <cuda_runtime.h>
#include <cuda_bf16.h>
#include <math.h>
#include <cstdint>

// ---------------- problem constants ----------------
#define B_    8
#define D_    512
#define H_    8
#define DH_   64
#define L_    6
#define DFF_  2048
#define GRIDN 10
#define DMLP_ 1024
#define CIN_  2048
#define SEQ_  912          // 1 + 768 + 108 + 35
#define M_    (B_*SEQ_)    // 7296

// ---------------- scratch (static device globals; no runtime alloc) --------
__device__ float g_xin[M_*CIN_];
__device__ float g_h1 [M_*DFF_];
__device__ float g_x  [M_*D_];
__device__ float g_q  [M_*D_];
__device__ float g_k  [M_*D_];
__device__ float g_v  [M_*D_];
__device__ float g_ctx[M_*D_];
__device__ float g_att[M_*D_];
__device__ float g_scores[(size_t)B_*H_*SEQ_*SEQ_];
__device__ float g_hmlp[B_*DMLP_];

__device__ __forceinline__ float gelu_f(float x) {
    return 0.5f * x * (1.0f + erff(x * 0.70710678118654752f));
}

__device__ __forceinline__ uint32_t smem_u32(const void* p) {
    uint32_t a;
    asm("{ .reg .u64 t; cvta.to.shared.u64 t, %1; cvt.u32.u64 %0, t; }" : "=r"(a) : "l"(p));
    return a;
}

// ---------------- mma.sync helpers (plain sm_80+ ISA, works on sm_103) ------
__device__ __forceinline__ void mma16816(float* c, const uint32_t* a, const uint32_t* b) {
    asm volatile(
        "mma.sync.aligned.m16n8k16.row.col.f32.bf16.bf16.f32 "
        "{%0,%1,%2,%3}, {%4,%5,%6,%7}, {%8,%9}, {%0,%1,%2,%3};"
        : "+f"(c[0]), "+f"(c[1]), "+f"(c[2]), "+f"(c[3])
        : "r"(a[0]), "r"(a[1]), "r"(a[2]), "r"(a[3]), "r"(b[0]), "r"(b[1]));
}
__device__ __forceinline__ void ldsm4(uint32_t* r, uint32_t addr) {
    asm volatile("ldmatrix.sync.aligned.m8n8.x4.shared.b16 {%0,%1,%2,%3}, [%4];"
        : "=r"(r[0]), "=r"(r[1]), "=r"(r[2]), "=r"(r[3]) : "r"(addr));
}
__device__ __forceinline__ void ldsm2(uint32_t* r, uint32_t addr) {
    asm volatile("ldmatrix.sync.aligned.m8n8.x2.shared.b16 {%0,%1}, [%2];"
        : "=r"(r[0]), "=r"(r[1]) : "r"(addr));
}

__device__ __forceinline__ void pack_hilo(float4 v, uint2& h, uint2& l) {
    __nv_bfloat16 h0 = __float2bfloat16(v.x);
    __nv_bfloat16 h1 = __float2bfloat16(v.y);
    __nv_bfloat16 h2 = __float2bfloat16(v.z);
    __nv_bfloat16 h3 = __float2bfloat16(v.w);
    __nv_bfloat16 l0 = __float2bfloat16(v.x - __bfloat162float(h0));
    __nv_bfloat16 l1 = __float2bfloat16(v.y - __bfloat162float(h1));
    __nv_bfloat16 l2 = __float2bfloat16(v.z - __bfloat162float(h2));
    __nv_bfloat16 l3 = __float2bfloat16(v.w - __bfloat162float(h3));
    __nv_bfloat162 H01(h0, h1), H23(h2, h3), L01(l0, l1), L23(l2, l3);
    h.x = *(uint32_t*)&H01; h.y = *(uint32_t*)&H23;
    l.x = *(uint32_t*)&L01; l.y = *(uint32_t*)&L23;
}

// smem geometry: per-tile region 128 rows x 40 bf16 (stride 40 elems = 80 B)
#define TSTRIDE   40
#define TILE_ELEM (128 * TSTRIDE)          // 5120 bf16
#define TILE_BYTE (TILE_ELEM * 2)          // 10240 B
// regions per buffer: 0=Ah 1=Al 2=Bh 3=Bl ; two buffers
#define SMEM_GEMM_BYTES (8 * TILE_BYTE)    // 81920 B

// ---------------- tensor-core (HMMA) GEMM NT, bf16x3 compensated ------------
// C[M,N] = A[M,K] @ B[N,K]^T (+bias, opt gelu). M,N mult of 128; K mult of 32.
__global__ void __launch_bounds__(256, 1) mma_gemm_nt(
    int M, int N, int K,
    const float* __restrict__ A, const float* __restrict__ Bm,
    const float* __restrict__ bias, float* __restrict__ C, int act) {
    extern __shared__ char smc[];
    __nv_bfloat16* smb = (__nv_bfloat16*)smc;
    uint32_t sb = smem_u32(smc);
    int tid = threadIdx.x, lane = tid & 31, wid = tid >> 5;
    int wm = wid & 1, wn = wid >> 1;         // warp tile: 64(m) x 32(n)
    int bm = blockIdx.y * 128, bn = blockIdx.x * 128;

    float acc[4][4][4];
    #pragma unroll
    for (int i = 0; i < 4; i++)
        #pragma unroll
        for (int j = 0; j < 4; j++)
            #pragma unroll
            for (int e = 0; e < 4; e++) acc[i][j][e] = 0.f;

    // per-thread staging coords: lin = i*256+tid ; row = lin>>3 ; c4 = lin&7
    float4 ga[4], gb[4];

    #define LOAD_CHUNK(k0)                                                     \
        do {                                                                   \
            _Pragma("unroll")                                                  \
            for (int i = 0; i < 4; i++) {                                      \
                int lin = i * 256 + tid;                                       \
                int row = lin >> 3, c4 = lin & 7;                              \
                ga[i] = *(const float4*)(A  + (size_t)(bm + row) * K + (k0) + c4 * 4); \
                gb[i] = *(const float4*)(Bm + (size_t)(bn + row) * K + (k0) + c4 * 4); \
            }                                                                  \
        } while (0)

    #define STORE_CHUNK(buf)                                                   \
        do {                                                                    \
            __nv_bfloat16* base = smb + (size_t)(buf) * 4 * TILE_ELEM;          \
            _Pragma("unroll")                                                   \
            for (int i = 0; i < 4; i++) {                                       \
                int lin = i * 256 + tid;                                        \
                int row = lin >> 3, c4 = lin & 7;                               \
                int off = row * TSTRIDE + c4 * 4;                               \
                uint2 h, l;                                                     \
                pack_hilo(ga[i], h, l);                                         \
                *(uint2*)(base + off)                 = h;                      \
                *(uint2*)(base + TILE_ELEM + off)     = l;                      \
                pack_hilo(gb[i], h, l);                                         \
                *(uint2*)(base + 2 * TILE_ELEM + off) = h;                      \
                *(uint2*)(base + 3 * TILE_ELEM + off) = l;                      \
            }                                                                   \
        } while (0)

    LOAD_CHUNK(0);
    STORE_CHUNK(0);
    __syncthreads();

    int nch = K >> 5;
    // precomputed intra-warp ldmatrix offsets (bf16 elems)
    int a_r = wm * 64 + (lane & 15);         // + mt*16
    int a_c = (lane >> 4) * 8;               // + ks*16
    int b_r = wn * 32 + (lane & 7);          // + nt*8
    int b_c = ((lane >> 3) & 1) * 8;         // + ks*16

    for (int c = 0; c < nch; c++) {
        int buf = c & 1;
        if (c + 1 < nch) LOAD_CHUNK((c + 1) * 32);

        uint32_t rbase = sb + buf * 4 * TILE_BYTE;
        #pragma unroll
        for (int ks = 0; ks < 2; ks++) {
            uint32_t af[4][4], bh[4][2], bl[4][2];
            #pragma unroll
            for (int mt = 0; mt < 4; mt++)
                ldsm4(af[mt], rbase + ((a_r + mt * 16) * TSTRIDE + ks * 16 + a_c) * 2);
            #pragma unroll
            for (int nt = 0; nt < 4; nt++)
                ldsm2(bh[nt], rbase + 2 * TILE_BYTE + ((b_r + nt * 8) * TSTRIDE + ks * 16 + b_c) * 2);
            #pragma unroll
            for (int mt = 0; mt < 4; mt++)
                #pragma unroll
                for (int nt = 0; nt < 4; nt++)
                    mma16816(acc[mt][nt], af[mt], bh[nt]);          // Ah*Bh
            #pragma unroll
            for (int nt = 0; nt < 4; nt++)
                ldsm2(bl[nt], rbase + 3 * TILE_BYTE + ((b_r + nt * 8) * TSTRIDE + ks * 16 + b_c) * 2);
            #pragma unroll
            for (int mt = 0; mt < 4; mt++)
                #pragma unroll
                for (int nt = 0; nt < 4; nt++)
                    mma16816(acc[mt][nt], af[mt], bl[nt]);          // Ah*Bl
            #pragma unroll
            for (int mt = 0; mt < 4; mt++)
                ldsm4(af[mt], rbase + TILE_BYTE + ((a_r + mt * 16) * TSTRIDE + ks * 16 + a_c) * 2);
            #pragma unroll
            for (int mt = 0; mt < 4; mt++)
                #pragma unroll
                for (int nt = 0; nt < 4; nt++)
                    mma16816(acc[mt][nt], af[mt], bh[nt]);          // Al*Bh
        }
        if (c + 1 < nch) STORE_CHUNK(buf ^ 1);
        __syncthreads();
    }

    // epilogue
    #pragma unroll
    for (int mt = 0; mt < 4; mt++) {
        int m0 = bm + wm * 64 + mt * 16 + (lane >> 2);
        #pragma unroll
        for (int nt = 0; nt < 4; nt++) {
            int col = bn + wn * 32 + nt * 8 + (lane & 3) * 2;
            float b0 = bias ? bias[col]     : 0.f;
            float b1 = bias ? bias[col + 1] : 0.f;
            float v0 = acc[mt][nt][0] + b0, v1 = acc[mt][nt][1] + b1;
            float v2 = acc[mt][nt][2] + b0, v3 = acc[mt][nt][3] + b1;
            if (act == 1) { v0 = gelu_f(v0); v1 = gelu_f(v1); v2 = gelu_f(v2); v3 = gelu_f(v3); }
            float2 p0; p0.x = v0; p0.y = v1;
            float2 p1; p1.x = v2; p1.y = v3;
            *(float2*)(C + (size_t)m0 * N + col)       = p0;
            *(float2*)(C + (size_t)(m0 + 8) * N + col) = p1;
        }
    }
    #undef LOAD_CHUNK
    #undef STORE_CHUNK
}

// ---------------- gather: feat [B,CIN,HW] -> xin [B,SEQ,CIN] (transpose) ----
__global__ void gather_transpose_k(const float* __restrict__ feat, int HW, int t0,
                                   float* __restrict__ xin) {
    __shared__ float tile[32][33];
    int b   = blockIdx.z;
    int hw0 = blockIdx.x * 32, c0 = blockIdx.y * 32;
    const float* fb = feat + (size_t)b * CIN_ * HW;
    #pragma unroll
    for (int kk = 0; kk < 32; kk += 8) {
        int c  = c0 + threadIdx.y + kk;
        int hw = hw0 + threadIdx.x;
        tile[threadIdx.y + kk][threadIdx.x] = (hw < HW) ? fb[(size_t)c * HW + hw] : 0.f;
    }
    __syncthreads();
    #pragma unroll
    for (int kk = 0; kk < 32; kk += 8) {
        int hw = hw0 + threadIdx.y + kk;
        int c  = c0 + threadIdx.x;
        if (hw < HW)
            xin[((size_t)b * SEQ_ + t0 + hw) * CIN_ + c] = tile[threadIdx.x][threadIdx.y + kk];
    }
}

// ---------------- embed epilogue: + conv_b + chan_emb + pos_emb -------------
__global__ void embed_add_k(const float* __restrict__ conv_b,
                            const float* __restrict__ e_org,
                            const float* __restrict__ e_r1,
                            const float* __restrict__ e_r2,
                            const float* __restrict__ pos,
                            float* __restrict__ x) {
    int idx = blockIdx.x * 256 + threadIdx.x;
    const int total = B_ * 911 * D_;
    if (idx >= total) return;
    int d = idx & 511;
    int rest = idx >> 9;
    int tt = rest % 911;
    int b  = rest / 911;
    int ti, tj; const float* ce;
    if (tt < 768)      { int hh = tt >> 5,  ww = tt & 31;  ce = e_org; ti = hh*GRIDN/24; tj = ww*GRIDN/32; }
    else if (tt < 876) { int u = tt - 768;  int hh = u/12, ww = u%12; ce = e_r1; ti = hh*GRIDN/9;  tj = ww*GRIDN/12; }
    else               { int u = tt - 876;  int hh = u/7,  ww = u%7;  ce = e_r2; ti = hh*GRIDN/5;  tj = ww*GRIDN/7;  }
    x[((size_t)(b * SEQ_ + tt + 1)) * D_ + d] += conv_b[d] + ce[d] + pos[(size_t)(ti * GRIDN + tj) * D_ + d];
}

__global__ void cls_set_k(const float* __restrict__ c, float* __restrict__ x) {
    int idx = blockIdx.x * 256 + threadIdx.x;
    if (idx >= B_ * D_) return;
    int b = idx >> 9, d = idx & 511;
    x[(size_t)b * SEQ_ * D_ + d] = c[d];
}

// ---------------- attention scores: per (b,h) 64x64 tiles, K=64 ------------
__global__ __launch_bounds__(256) void attn_scores_k(
    const float* __restrict__ q, const float* __restrict__ k,
    const int* __restrict__ mask, float* __restrict__ scores) {
    __shared__ float Qs[64][65];
    __shared__ float Ks[64][65];
    int bh = blockIdx.z, b = bh >> 3, h = bh & 7;
    int i0 = blockIdx.y * 64, j0 = blockIdx.x * 64;
    int tid = threadIdx.x;
    for (int s = tid; s < 1024; s += 256) {
        int r = s >> 4, c = (s & 15) << 2;
        int gi = i0 + r, gj = j0 + r;
        float4 va = make_float4(0, 0, 0, 0), vb = va;
        if (gi < SEQ_) va = *(const float4*)(q + ((size_t)(b * SEQ_ + gi)) * D_ + h * DH_ + c);
        if (gj < SEQ_) vb = *(const float4*)(k + ((size_t)(b * SEQ_ + gj)) * D_ + h * DH_ + c);
        Qs[r][c] = va.x; Qs[r][c + 1] = va.y; Qs[r][c + 2] = va.z; Qs[r][c + 3] = va.w;
        Ks[r][c] = vb.x; Ks[r][c + 1] = vb.y; Ks[r][c + 2] = vb.z; Ks[r][c + 3] = vb.w;
    }
    __syncthreads();
    int tx = tid & 15, ty = tid >> 4;
    float acc[4][4] = {};
    #pragma unroll 16
    for (int d = 0; d < 64; d++) {
        float a[4], bb[4];
        #pragma unroll
        for (int u = 0; u < 4; u++) { a[u] = Qs[ty * 4 + u][d]; bb[u] = Ks[tx * 4 + u][d]; }
        #pragma unroll
        for (int i = 0; i < 4; i++)
            #pragma unroll
            for (int j = 0; j < 4; j++)
                acc[i][j] += a[i] * bb[j];
    }
    #pragma unroll
    for (int i = 0; i < 4; i++) {
        int gi = i0 + ty * 4 + i;
        if (gi >= SEQ_) continue;
        #pragma unroll
        for (int j = 0; j < 4; j++) {
            int gj = j0 + tx * 4 + j;
            if (gj >= SEQ_) continue;
            float v = (mask[b * SEQ_ + gj] == 0) ? -1e9f : acc[i][j] * 0.125f;
            scores[((size_t)bh * SEQ_ + gi) * SEQ_ + gj] = v;
        }
    }
}

// ---------------- softmax over rows of length SEQ_ --------------------------
__global__ __launch_bounds__(256) void softmax_k(float* __restrict__ scores) {
    __shared__ float red[8];
    __shared__ float bval;
    float* p = scores + (size_t)blockIdx.x * SEQ_;
    int tid = threadIdx.x;
    float mx = -3.4e38f;
    for (int j = tid; j < SEQ_; j += 256) mx = fmaxf(mx, p[j]);
    #pragma unroll
    for (int o = 16; o > 0; o >>= 1) mx = fmaxf(mx, __shfl_xor_sync(~0u, mx, o));
    if ((tid & 31) == 0) red[tid >> 5] = mx;
    __syncthreads();
    if (tid == 0) { float m = red[0]; for (int w = 1; w < 8; w++) m = fmaxf(m, red[w]); bval = m; }
    __syncthreads();
    mx = bval;
    float sum = 0.f;
    for (int j = tid; j < SEQ_; j += 256) { float e = expf(p[j] - mx); p[j] = e; sum += e; }
    #pragma unroll
    for (int o = 16; o > 0; o >>= 1) sum += __shfl_xor_sync(~0u, sum, o);
    __syncthreads();
    if ((tid & 31) == 0) red[tid >> 5] = sum;
    __syncthreads();
    if (tid == 0) { float s = 0; for (int w = 0; w < 8; w++) s += red[w]; bval = 1.f / s; }
    __syncthreads();
    float inv = bval;
    for (int j = tid; j < SEQ_; j += 256) p[j] *= inv;
}

// ---------------- ctx = prob @ v : per (b,h), 64-row tiles, K=SEQ_ ----------
__global__ __launch_bounds__(256) void attn_ctx_k(
    const float* __restrict__ scores, const float* __restrict__ v,
    float* __restrict__ ctx) {
    __shared__ float Ps[64][65];
    __shared__ float Vs[64][65];
    int bh = blockIdx.y, b = bh >> 3, h = bh & 7;
    int i0 = blockIdx.x * 64;
    int tid = threadIdx.x, tx = tid & 15, ty = tid >> 4;
    float acc[4][4] = {};
    for (int j0 = 0; j0 < SEQ_; j0 += 64) {
        for (int s = tid; s < 1024; s += 256) {
            int r = s >> 4, c = (s & 15) << 2;
            int gi = i0 + r, gj = j0 + c, gr = j0 + r;
            float4 vp = make_float4(0, 0, 0, 0), vv = vp;
            if (gi < SEQ_ && gj < SEQ_) vp = *(const float4*)(scores + ((size_t)bh * SEQ_ + gi) * SEQ_ + gj);
            if (gr < SEQ_)              vv = *(const float4*)(v + ((size_t)(b * SEQ_ + gr)) * D_ + h * DH_ + c);
            Ps[r][c] = vp.x; Ps[r][c + 1] = vp.y; Ps[r][c + 2] = vp.z; Ps[r][c + 3] = vp.w;
            Vs[r][c] = vv.x; Vs[r][c + 1] = vv.y; Vs[r][c + 2] = vv.z; Vs[r][c + 3] = vv.w;
        }
        __syncthreads();
        #pragma unroll 16
        for (int kk = 0; kk < 64; kk++) {
            float a[4], bb[4];
            #pragma unroll
            for (int u = 0; u < 4; u++) { a[u] = Ps[ty * 4 + u][kk]; bb[u] = Vs[kk][tx * 4 + u]; }
            #pragma unroll
            for (int i = 0; i < 4; i++)
                #pragma unroll
                for (int j = 0; j < 4; j++)
                    acc[i][j] += a[i] * bb[j];
        }
        __syncthreads();
    }
    #pragma unroll
    for (int i = 0; i < 4; i++) {
        int gi = i0 + ty * 4 + i;
        if (gi >= SEQ_) continue;
        #pragma unroll
        for (int j = 0; j < 4; j++)
            ctx[((size_t)(b * SEQ_ + gi)) * D_ + h * DH_ + tx * 4 + j] = acc[i][j];
    }
}

// ---------------- residual + LayerNorm (row = one block of 128) -------------
__global__ __launch_bounds__(128) void add_ln_k(
    const float* __restrict__ xin, const float* __restrict__ add,
    const float* __restrict__ g, const float* __restrict__ beta,
    float* __restrict__ xout) {
    __shared__ float red[4];
    __shared__ float bval;
    int row = blockIdx.x, tid = threadIdx.x;
    float4 xv = ((const float4*)(xin + (size_t)row * D_))[tid];
    float4 av = ((const float4*)(add + (size_t)row * D_))[tid];
    float4 s;
    s.x = xv.x + av.x; s.y = xv.y + av.y; s.z = xv.z + av.z; s.w = xv.w + av.w;
    float sum = s.x + s.y + s.z + s.w;
    #pragma unroll
    for (int o = 16; o > 0; o >>= 1) sum += __shfl_xor_sync(~0u, sum, o);
    if ((tid & 31) == 0) red[tid >> 5] = sum;
    __syncthreads();
    if (tid == 0) bval = (red[0] + red[1] + red[2] + red[3]) * (1.f / D_);
    __syncthreads();
    float m = bval;
    float d0 = s.x - m, d1 = s.y - m, d2 = s.z - m, d3 = s.w - m;
    float sq = d0 * d0 + d1 * d1 + d2 * d2 + d3 * d3;
    #pragma unroll
    for (int o = 16; o > 0; o >>= 1) sq += __shfl_xor_sync(~0u, sq, o);
    __syncthreads();
    if ((tid & 31) == 0) red[tid >> 5] = sq;
    __syncthreads();
    if (tid == 0) bval = rsqrtf((red[0] + red[1] + red[2] + red[3]) * (1.f / D_) + 1e-6f);
    __syncthreads();
    float rs = bval;
    float4 gv = ((const float4*)g)[tid];
    float4 bv = ((const float4*)beta)[tid];
    float4 o;
    o.x = d0 * rs * gv.x + bv.x; o.y = d1 * rs * gv.y + bv.y;
    o.z = d2 * rs * gv.z + bv.z; o.w = d3 * rs * gv.w + bv.w;
    ((float4*)(xout + (size_t)row * D_))[tid] = o;
}

// ---------------- head ------------------------------------------------------
__global__ __launch_bounds__(256) void head_mlp_k(
    const float* __restrict__ x, const float* __restrict__ w1,
    float* __restrict__ hm) {
    __shared__ float cls[512];
    int b = blockIdx.x;
    for (int d = threadIdx.x; d < 512; d += 256) cls[d] = x[(size_t)b * SEQ_ * D_ + d];
    __syncthreads();
    for (int n = threadIdx.x; n < DMLP_; n += 256) {
        const float* w = w1 + (size_t)n * 512;
        float s = 0.f;
        for (int d = 0; d < 512; d++) s += cls[d] * w[d];
        hm[b * DMLP_ + n] = gelu_f(s);
    }
}

__global__ __launch_bounds__(256) void head_out_k(
    const float* __restrict__ hm, const float* __restrict__ w2,
    float* __restrict__ out) {
    __shared__ float red[8];
    int b = blockIdx.x, tid = threadIdx.x;
    float s = 0.f;
    for (int n = tid; n < DMLP_; n += 256) s += hm[b * DMLP_ + n] * w2[n];
    #pragma unroll
    for (int o = 16; o > 0; o >>= 1) s += __shfl_xor_sync(~0u, s, o);
    if ((tid & 31) == 0) red[tid >> 5] = s;
    __syncthreads();
    if (tid == 0) {
        float t = 0; for (int w = 0; w < 8; w++) t += red[w];
        out[b] = t;
    }
}

// ---------------- host orchestration ----------------------------------------
extern "C" void kernel_launch(void* const* d_in, const int* in_sizes, int n_in,
                              void* d_out, int out_size) {
    const float* feat_org = (const float*)d_in[0];
    const float* feat_r1  = (const float*)d_in[1];
    const float* feat_r2  = (const float*)d_in[2];
    const float* conv_w   = (const float*)d_in[3];
    const float* conv_b   = (const float*)d_in[4];
    const float* e_org    = (const float*)d_in[5];
    const float* e_r1     = (const float*)d_in[6];
    const float* e_r2     = (const float*)d_in[7];
    const float* pos      = (const float*)d_in[8];
    const float* cls_tok  = (const float*)d_in[9];
    const float* Wq = (const float*)d_in[10]; const float* bq = (const float*)d_in[11];
    const float* Wk = (const float*)d_in[12]; const float* bk = (const float*)d_in[13];
    const float* Wv = (const float*)d_in[14]; const float* bv = (const float*)d_in[15];
    const float* Wo = (const float*)d_in[16]; const float* bo = (const float*)d_in[17];
    const float* ln1g = (const float*)d_in[18]; const float* ln1b = (const float*)d_in[19];
    const float* w1 = (const float*)d_in[20]; const float* b1 = (const float*)d_in[21];
    const float* w2 = (const float*)d_in[22]; const float* b2 = (const float*)d_in[23];
    const float* ln2g = (const float*)d_in[24]; const float* ln2b = (const float*)d_in[25];
    const float* pw1 = (const float*)d_in[26]; const float* pw2 = (const float*)d_in[27];
    const int*   mask = (const int*)d_in[28];

    float *xin, *h1, *x, *q, *k, *v, *ctx, *att, *scores, *hmlp;
    cudaGetSymbolAddress((void**)&xin, g_xin);
    cudaGetSymbolAddress((void**)&h1, g_h1);
    cudaGetSymbolAddress((void**)&x, g_x);
    cudaGetSymbolAddress((void**)&q, g_q);
    cudaGetSymbolAddress((void**)&k, g_k);
    cudaGetSymbolAddress((void**)&v, g_v);
    cudaGetSymbolAddress((void**)&ctx, g_ctx);
    cudaGetSymbolAddress((void**)&att, g_att);
    cudaGetSymbolAddress((void**)&scores, g_scores);
    cudaGetSymbolAddress((void**)&hmlp, g_hmlp);

    cudaFuncSetAttribute(mma_gemm_nt, cudaFuncAttributeMaxDynamicSharedMemorySize, SMEM_GEMM_BYTES);

    dim3 tb32(32, 8);
    gather_transpose_k<<<dim3(24, CIN_ / 32, B_), tb32>>>(feat_org, 768, 1,   xin);
    gather_transpose_k<<<dim3(4,  CIN_ / 32, B_), tb32>>>(feat_r1,  108, 769, xin);
    gather_transpose_k<<<dim3(2,  CIN_ / 32, B_), tb32>>>(feat_r2,  35,  877, xin);

    mma_gemm_nt<<<dim3(D_ / 128, M_ / 128), 256, SMEM_GEMM_BYTES>>>(M_, D_, CIN_, xin, conv_w, nullptr, x, 0);
    embed_add_k<<<(B_ * 911 * D_ + 255) / 256, 256>>>(conv_b, e_org, e_r1, e_r2, pos, x);
    cls_set_k<<<(B_ * D_ + 255) / 256, 256>>>(cls_tok, x);

    const int TILES = (SEQ_ + 63) / 64;   // 15
    for (int i = 0; i < L_; i++) {
        const float* Wqi = Wq + (size_t)i * D_ * D_;
        const float* Wki = Wk + (size_t)i * D_ * D_;
        const float* Wvi = Wv + (size_t)i * D_ * D_;
        const float* Woi = Wo + (size_t)i * D_ * D_;
        mma_gemm_nt<<<dim3(D_ / 128, M_ / 128), 256, SMEM_GEMM_BYTES>>>(M_, D_, D_, x, Wqi, bq + i * D_, q, 0);
        mma_gemm_nt<<<dim3(D_ / 128, M_ / 128), 256, SMEM_GEMM_BYTES>>>(M_, D_, D_, x, Wki, bk + i * D_, k, 0);
        mma_gemm_nt<<<dim3(D_ / 128, M_ / 128), 256, SMEM_GEMM_BYTES>>>(M_, D_, D_, x, Wvi, bv + i * D_, v, 0);

        attn_scores_k<<<dim3(TILES, TILES, B_ * H_), 256>>>(q, k, mask, scores);
        softmax_k<<<B_ * H_ * SEQ_, 256>>>(scores);
        attn_ctx_k<<<dim3(TILES, B_ * H_), 256>>>(scores, v, ctx);

        mma_gemm_nt<<<dim3(D_ / 128, M_ / 128), 256, SMEM_GEMM_BYTES>>>(M_, D_, D_, ctx, Woi, bo + i * D_, att, 0);
        add_ln_k<<<M_, 128>>>(x, att, ln1g + i * D_, ln1b + i * D_, x);

        mma_gemm_nt<<<dim3(DFF_ / 128, M_ / 128), 256, SMEM_GEMM_BYTES>>>(M_, DFF_, D_, x, w1 + (size_t)i * DFF_ * D_, b1 + i * DFF_, h1, 1);
        mma_gemm_nt<<<dim3(D_ / 128, M_ / 128), 256, SMEM_GEMM_BYTES>>>(M_, D_, DFF_, h1, w2 + (size_t)i * D_ * DFF_, b2 + i * D_, att, 0);
        add_ln_k<<<M_, 128>>>(x, att, ln2g + i * D_, ln2b + i * D_, x);
    }

    head_mlp_k<<<B_, 256>>>(x, pw1, hmlp);
    head_out_k<<<B_, 256>>>(hmlp, pw2, (float*)d_out);
}

// round 4
// speedup vs baseline: 2.8132x; 1.6309x over previous
#include <cuda_runtime.h>
#include <cuda_bf16.h>
#include <math.h>
#include <cstdint>

// ---------------- problem constants ----------------
#define B_    8
#define D_    512
#define H_    8
#define DH_   64
#define L_    6
#define DFF_  2048
#define GRIDN 10
#define DMLP_ 1024
#define CIN_  2048
#define SEQ_  912          // 1 + 768 + 108 + 35
#define M_    (B_*SEQ_)    // 7296

// ---------------- scratch (static device globals; no runtime alloc) --------
__device__ float g_xin[M_*CIN_];
__device__ float g_h1 [M_*DFF_];
__device__ float g_x  [M_*D_];
__device__ float g_q  [M_*D_];
__device__ float g_k  [M_*D_];
__device__ float g_v  [M_*D_];
__device__ float g_ctx[M_*D_];
__device__ float g_att[M_*D_];
__device__ float g_hmlp[B_*DMLP_];

__device__ __forceinline__ float gelu_f(float x) {
    return 0.5f * x * (1.0f + erff(x * 0.70710678118654752f));
}

__device__ __forceinline__ uint32_t smem_u32(const void* p) {
    uint32_t a;
    asm("{ .reg .u64 t; cvta.to.shared.u64 t, %1; cvt.u32.u64 %0, t; }" : "=r"(a) : "l"(p));
    return a;
}

// ---------------- mma.sync helpers (plain sm_80+ ISA) -----------------------
__device__ __forceinline__ void mma16816(float* c, const uint32_t* a, const uint32_t* b) {
    asm volatile(
        "mma.sync.aligned.m16n8k16.row.col.f32.bf16.bf16.f32 "
        "{%0,%1,%2,%3}, {%4,%5,%6,%7}, {%8,%9}, {%0,%1,%2,%3};"
        : "+f"(c[0]), "+f"(c[1]), "+f"(c[2]), "+f"(c[3])
        : "r"(a[0]), "r"(a[1]), "r"(a[2]), "r"(a[3]), "r"(b[0]), "r"(b[1]));
}
__device__ __forceinline__ void ldsm4(uint32_t* r, uint32_t addr) {
    asm volatile("ldmatrix.sync.aligned.m8n8.x4.shared.b16 {%0,%1,%2,%3}, [%4];"
        : "=r"(r[0]), "=r"(r[1]), "=r"(r[2]), "=r"(r[3]) : "r"(addr));
}
__device__ __forceinline__ void ldsm2(uint32_t* r, uint32_t addr) {
    asm volatile("ldmatrix.sync.aligned.m8n8.x2.shared.b16 {%0,%1}, [%2];"
        : "=r"(r[0]), "=r"(r[1]) : "r"(addr));
}

__device__ __forceinline__ void pack_hilo(float4 v, uint2& h, uint2& l) {
    __nv_bfloat16 h0 = __float2bfloat16(v.x);
    __nv_bfloat16 h1 = __float2bfloat16(v.y);
    __nv_bfloat16 h2 = __float2bfloat16(v.z);
    __nv_bfloat16 h3 = __float2bfloat16(v.w);
    __nv_bfloat16 l0 = __float2bfloat16(v.x - __bfloat162float(h0));
    __nv_bfloat16 l1 = __float2bfloat16(v.y - __bfloat162float(h1));
    __nv_bfloat16 l2 = __float2bfloat16(v.z - __bfloat162float(h2));
    __nv_bfloat16 l3 = __float2bfloat16(v.w - __bfloat162float(h3));
    __nv_bfloat162 H01(h0, h1), H23(h2, h3), L01(l0, l1), L23(l2, l3);
    h.x = *(uint32_t*)&H01; h.y = *(uint32_t*)&H23;
    l.x = *(uint32_t*)&L01; l.y = *(uint32_t*)&L23;
}

// ============================================================================
// Linear GEMM (bf16x3 compensated), unchanged from round 3
// ============================================================================
#define TSTRIDE   40
#define TILE_ELEM (128 * TSTRIDE)
#define TILE_BYTE (TILE_ELEM * 2)
#define SMEM_GEMM_BYTES (8 * TILE_BYTE)    // 81920 B

__global__ void __launch_bounds__(256, 1) mma_gemm_nt(
    int M, int N, int K,
    const float* __restrict__ A, const float* __restrict__ Bm,
    const float* __restrict__ bias, float* __restrict__ C, int act) {
    extern __shared__ char smc[];
    __nv_bfloat16* smb = (__nv_bfloat16*)smc;
    uint32_t sb = smem_u32(smc);
    int tid = threadIdx.x, lane = tid & 31, wid = tid >> 5;
    int wm = wid & 1, wn = wid >> 1;
    int bm = blockIdx.y * 128, bn = blockIdx.x * 128;

    float acc[4][4][4];
    #pragma unroll
    for (int i = 0; i < 4; i++)
        #pragma unroll
        for (int j = 0; j < 4; j++)
            #pragma unroll
            for (int e = 0; e < 4; e++) acc[i][j][e] = 0.f;

    float4 ga[4], gb[4];

    #define LOAD_CHUNK(k0)                                                     \
        do {                                                                   \
            _Pragma("unroll")                                                  \
            for (int i = 0; i < 4; i++) {                                      \
                int lin = i * 256 + tid;                                       \
                int row = lin >> 3, c4 = lin & 7;                              \
                ga[i] = *(const float4*)(A  + (size_t)(bm + row) * K + (k0) + c4 * 4); \
                gb[i] = *(const float4*)(Bm + (size_t)(bn + row) * K + (k0) + c4 * 4); \
            }                                                                  \
        } while (0)

    #define STORE_CHUNK(buf)                                                   \
        do {                                                                    \
            __nv_bfloat16* base = smb + (size_t)(buf) * 4 * TILE_ELEM;          \
            _Pragma("unroll")                                                   \
            for (int i = 0; i < 4; i++) {                                       \
                int lin = i * 256 + tid;                                        \
                int row = lin >> 3, c4 = lin & 7;                               \
                int off = row * TSTRIDE + c4 * 4;                               \
                uint2 h, l;                                                     \
                pack_hilo(ga[i], h, l);                                         \
                *(uint2*)(base + off)                 = h;                      \
                *(uint2*)(base + TILE_ELEM + off)     = l;                      \
                pack_hilo(gb[i], h, l);                                         \
                *(uint2*)(base + 2 * TILE_ELEM + off) = h;                      \
                *(uint2*)(base + 3 * TILE_ELEM + off) = l;                      \
            }                                                                   \
        } while (0)

    LOAD_CHUNK(0);
    STORE_CHUNK(0);
    __syncthreads();

    int nch = K >> 5;
    int a_r = wm * 64 + (lane & 15);
    int a_c = (lane >> 4) * 8;
    int b_r = wn * 32 + (lane & 7);
    int b_c = ((lane >> 3) & 1) * 8;

    for (int c = 0; c < nch; c++) {
        int buf = c & 1;
        if (c + 1 < nch) LOAD_CHUNK((c + 1) * 32);

        uint32_t rbase = sb + buf * 4 * TILE_BYTE;
        #pragma unroll
        for (int ks = 0; ks < 2; ks++) {
            uint32_t af[4][4], bh[4][2], bl[4][2];
            #pragma unroll
            for (int mt = 0; mt < 4; mt++)
                ldsm4(af[mt], rbase + ((a_r + mt * 16) * TSTRIDE + ks * 16 + a_c) * 2);
            #pragma unroll
            for (int nt = 0; nt < 4; nt++)
                ldsm2(bh[nt], rbase + 2 * TILE_BYTE + ((b_r + nt * 8) * TSTRIDE + ks * 16 + b_c) * 2);
            #pragma unroll
            for (int mt = 0; mt < 4; mt++)
                #pragma unroll
                for (int nt = 0; nt < 4; nt++)
                    mma16816(acc[mt][nt], af[mt], bh[nt]);
            #pragma unroll
            for (int nt = 0; nt < 4; nt++)
                ldsm2(bl[nt], rbase + 3 * TILE_BYTE + ((b_r + nt * 8) * TSTRIDE + ks * 16 + b_c) * 2);
            #pragma unroll
            for (int mt = 0; mt < 4; mt++)
                #pragma unroll
                for (int nt = 0; nt < 4; nt++)
                    mma16816(acc[mt][nt], af[mt], bl[nt]);
            #pragma unroll
            for (int mt = 0; mt < 4; mt++)
                ldsm4(af[mt], rbase + TILE_BYTE + ((a_r + mt * 16) * TSTRIDE + ks * 16 + a_c) * 2);
            #pragma unroll
            for (int mt = 0; mt < 4; mt++)
                #pragma unroll
                for (int nt = 0; nt < 4; nt++)
                    mma16816(acc[mt][nt], af[mt], bh[nt]);
        }
        if (c + 1 < nch) STORE_CHUNK(buf ^ 1);
        __syncthreads();
    }

    #pragma unroll
    for (int mt = 0; mt < 4; mt++) {
        int m0 = bm + wm * 64 + mt * 16 + (lane >> 2);
        #pragma unroll
        for (int nt = 0; nt < 4; nt++) {
            int col = bn + wn * 32 + nt * 8 + (lane & 3) * 2;
            float b0 = bias ? bias[col]     : 0.f;
            float b1 = bias ? bias[col + 1] : 0.f;
            float v0 = acc[mt][nt][0] + b0, v1 = acc[mt][nt][1] + b1;
            float v2 = acc[mt][nt][2] + b0, v3 = acc[mt][nt][3] + b1;
            if (act == 1) { v0 = gelu_f(v0); v1 = gelu_f(v1); v2 = gelu_f(v2); v3 = gelu_f(v3); }
            float2 p0; p0.x = v0; p0.y = v1;
            float2 p1; p1.x = v2; p1.y = v3;
            *(float2*)(C + (size_t)m0 * N + col)       = p0;
            *(float2*)(C + (size_t)(m0 + 8) * N + col) = p1;
        }
    }
    #undef LOAD_CHUNK
    #undef STORE_CHUNK
}

// ============================================================================
// Fused flash attention (bf16x3 on tensor cores, online softmax)
// ============================================================================
#define FTS 72                      // smem row stride (bf16 elems), conflict-free
#define FQH 0
#define FQL (64*FTS)
#define FKH (2*64*FTS)
#define FKL (3*64*FTS)
#define FVH (4*64*FTS)
#define FVL (5*64*FTS)
#define FMASK_B (6*64*FTS*2)        // byte offset of mask floats
#define FSMEM_B (FMASK_B + 64*4)    // 55552 B

__global__ void __launch_bounds__(128) flash_attn_k(
    const float* __restrict__ q, const float* __restrict__ k,
    const float* __restrict__ v, const int* __restrict__ mask,
    float* __restrict__ ctx) {
    extern __shared__ char sm[];
    __nv_bfloat16* sb = (__nv_bfloat16*)sm;
    float* maskadd = (float*)(sm + FMASK_B);
    uint32_t sbase = smem_u32(sm);
    int tid = threadIdx.x, lane = tid & 31, w = tid >> 5;
    int bh = blockIdx.y, b = bh >> 3, h = bh & 7;
    int i0 = blockIdx.x * 64;
    const float* qb = q + (size_t)b * SEQ_ * D_ + h * DH_;
    const float* kb = k + (size_t)b * SEQ_ * D_ + h * DH_;
    const float* vb = v + (size_t)b * SEQ_ * D_ + h * DH_;

    // stage Q (scaled by 1/8) as hi/lo bf16
    #pragma unroll
    for (int i = 0; i < 8; i++) {
        int lin = i * 128 + tid;
        int r = lin >> 4, c4 = lin & 15;
        int gr = i0 + r; if (gr >= SEQ_) gr = SEQ_ - 1;
        float4 vq = *(const float4*)(qb + (size_t)gr * D_ + c4 * 4);
        vq.x *= 0.125f; vq.y *= 0.125f; vq.z *= 0.125f; vq.w *= 0.125f;
        uint2 hh, ll;
        pack_hilo(vq, hh, ll);
        *(uint2*)(sb + FQH + r * FTS + c4 * 4) = hh;
        *(uint2*)(sb + FQL + r * FTS + c4 * 4) = ll;
    }

    float m0 = -INFINITY, m1 = -INFINITY, l0 = 0.f, l1 = 0.f;
    float O[8][4];
    #pragma unroll
    for (int nt = 0; nt < 8; nt++)
        #pragma unroll
        for (int e = 0; e < 4; e++) O[nt][e] = 0.f;

    int a_r = w * 16 + (lane & 15);
    int a_c = (lane >> 4) * 8;
    int b_r = lane & 7;
    int b_c = ((lane >> 3) & 1) * 8;
    int g = lane >> 2;

    for (int j0 = 0; j0 < 960; j0 += 64) {
        // ---- stage K (hi/lo), V transposed (hi/lo), mask ----
        #pragma unroll
        for (int i = 0; i < 8; i++) {
            int lin = i * 128 + tid;
            int r = lin >> 4, c4 = lin & 15;
            int gr = j0 + r; if (gr >= SEQ_) gr = SEQ_ - 1;
            float4 vk = *(const float4*)(kb + (size_t)gr * D_ + c4 * 4);
            uint2 hh, ll;
            pack_hilo(vk, hh, ll);
            *(uint2*)(sb + FKH + r * FTS + c4 * 4) = hh;
            *(uint2*)(sb + FKL + r * FTS + c4 * 4) = ll;
            float4 vv = *(const float4*)(vb + (size_t)gr * D_ + c4 * 4);
            pack_hilo(vv, hh, ll);
            // transpose: Vt[d][j] ; d = c4*4+u, j = r
            __nv_bfloat162 h01 = *(__nv_bfloat162*)&hh.x;
            __nv_bfloat162 h23 = *(__nv_bfloat162*)&hh.y;
            __nv_bfloat162 l01 = *(__nv_bfloat162*)&ll.x;
            __nv_bfloat162 l23 = *(__nv_bfloat162*)&ll.y;
            int d0 = c4 * 4;
            sb[FVH + (d0 + 0) * FTS + r] = h01.x;
            sb[FVH + (d0 + 1) * FTS + r] = h01.y;
            sb[FVH + (d0 + 2) * FTS + r] = h23.x;
            sb[FVH + (d0 + 3) * FTS + r] = h23.y;
            sb[FVL + (d0 + 0) * FTS + r] = l01.x;
            sb[FVL + (d0 + 1) * FTS + r] = l01.y;
            sb[FVL + (d0 + 2) * FTS + r] = l23.x;
            sb[FVL + (d0 + 3) * FTS + r] = l23.y;
        }
        if (tid < 64) {
            int j = j0 + tid;
            maskadd[tid] = (j >= SEQ_) ? -INFINITY
                          : (mask[b * SEQ_ + j] == 0 ? -1e9f : 0.f);
        }
        __syncthreads();

        // ---- S = Q K^T (bf16x3) ----
        float S[8][4];
        #pragma unroll
        for (int nt = 0; nt < 8; nt++)
            #pragma unroll
            for (int e = 0; e < 4; e++) S[nt][e] = 0.f;
        #pragma unroll
        for (int kc = 0; kc < 4; kc++) {
            uint32_t aqh[4], aql[4];
            ldsm4(aqh, sbase + (FQH + a_r * FTS + kc * 16 + a_c) * 2);
            ldsm4(aql, sbase + (FQL + a_r * FTS + kc * 16 + a_c) * 2);
            #pragma unroll
            for (int nt = 0; nt < 8; nt++) {
                uint32_t bkh[2], bkl[2];
                ldsm2(bkh, sbase + (FKH + (nt * 8 + b_r) * FTS + kc * 16 + b_c) * 2);
                ldsm2(bkl, sbase + (FKL + (nt * 8 + b_r) * FTS + kc * 16 + b_c) * 2);
                mma16816(S[nt], aqh, bkh);
                mma16816(S[nt], aqh, bkl);
                mma16816(S[nt], aql, bkh);
            }
        }
        // ---- mask ----
        #pragma unroll
        for (int nt = 0; nt < 8; nt++) {
            int col = nt * 8 + (lane & 3) * 2;
            float ma0 = maskadd[col], ma1 = maskadd[col + 1];
            S[nt][0] += ma0; S[nt][1] += ma1;
            S[nt][2] += ma0; S[nt][3] += ma1;
        }
        // ---- online softmax ----
        float rm0 = -INFINITY, rm1 = -INFINITY;
        #pragma unroll
        for (int nt = 0; nt < 8; nt++) {
            rm0 = fmaxf(rm0, fmaxf(S[nt][0], S[nt][1]));
            rm1 = fmaxf(rm1, fmaxf(S[nt][2], S[nt][3]));
        }
        rm0 = fmaxf(rm0, __shfl_xor_sync(~0u, rm0, 1));
        rm0 = fmaxf(rm0, __shfl_xor_sync(~0u, rm0, 2));
        rm1 = fmaxf(rm1, __shfl_xor_sync(~0u, rm1, 1));
        rm1 = fmaxf(rm1, __shfl_xor_sync(~0u, rm1, 2));
        float nm0 = fmaxf(m0, rm0), nm1 = fmaxf(m1, rm1);
        float f0 = expf(m0 - nm0), f1 = expf(m1 - nm1);
        m0 = nm0; m1 = nm1;
        float s0 = 0.f, s1 = 0.f;
        #pragma unroll
        for (int nt = 0; nt < 8; nt++) {
            S[nt][0] = expf(S[nt][0] - m0);
            S[nt][1] = expf(S[nt][1] - m0);
            S[nt][2] = expf(S[nt][2] - m1);
            S[nt][3] = expf(S[nt][3] - m1);
            s0 += S[nt][0] + S[nt][1];
            s1 += S[nt][2] + S[nt][3];
        }
        s0 += __shfl_xor_sync(~0u, s0, 1);
        s0 += __shfl_xor_sync(~0u, s0, 2);
        s1 += __shfl_xor_sync(~0u, s1, 1);
        s1 += __shfl_xor_sync(~0u, s1, 2);
        l0 = l0 * f0 + s0;
        l1 = l1 * f1 + s1;
        #pragma unroll
        for (int nt = 0; nt < 8; nt++) {
            O[nt][0] *= f0; O[nt][1] *= f0;
            O[nt][2] *= f1; O[nt][3] *= f1;
        }
        // ---- O += P V (bf16x3); A-frags built from S accumulators ----
        #pragma unroll
        for (int kc = 0; kc < 4; kc++) {
            uint2 h0, l0r, h1, l1r;
            pack_hilo(make_float4(S[2*kc][0], S[2*kc][1], S[2*kc][2], S[2*kc][3]), h0, l0r);
            pack_hilo(make_float4(S[2*kc+1][0], S[2*kc+1][1], S[2*kc+1][2], S[2*kc+1][3]), h1, l1r);
            uint32_t aph[4] = { h0.x, h0.y, h1.x, h1.y };
            uint32_t apl[4] = { l0r.x, l0r.y, l1r.x, l1r.y };
            #pragma unroll
            for (int nt = 0; nt < 8; nt++) {
                uint32_t bvh[2], bvl[2];
                ldsm2(bvh, sbase + (FVH + (nt * 8 + b_r) * FTS + kc * 16 + b_c) * 2);
                ldsm2(bvl, sbase + (FVL + (nt * 8 + b_r) * FTS + kc * 16 + b_c) * 2);
                mma16816(O[nt], aph, bvh);
                mma16816(O[nt], aph, bvl);
                mma16816(O[nt], apl, bvh);
            }
        }
        __syncthreads();
    }

    // ---- epilogue: normalize and store ctx[b, row, h*64+d] ----
    float inv0 = 1.f / l0, inv1 = 1.f / l1;
    int r0 = i0 + w * 16 + g, r1 = r0 + 8;
    #pragma unroll
    for (int nt = 0; nt < 8; nt++) {
        int d = h * DH_ + nt * 8 + (lane & 3) * 2;
        if (r0 < SEQ_) {
            float2 p; p.x = O[nt][0] * inv0; p.y = O[nt][1] * inv0;
            *(float2*)(ctx + (size_t)(b * SEQ_ + r0) * D_ + d) = p;
        }
        if (r1 < SEQ_) {
            float2 p; p.x = O[nt][2] * inv1; p.y = O[nt][3] * inv1;
            *(float2*)(ctx + (size_t)(b * SEQ_ + r1) * D_ + d) = p;
        }
    }
}

// ---------------- gather: feat [B,CIN,HW] -> xin [B,SEQ,CIN] (transpose) ----
__global__ void gather_transpose_k(const float* __restrict__ feat, int HW, int t0,
                                   float* __restrict__ xin) {
    __shared__ float tile[32][33];
    int b   = blockIdx.z;
    int hw0 = blockIdx.x * 32, c0 = blockIdx.y * 32;
    const float* fb = feat + (size_t)b * CIN_ * HW;
    #pragma unroll
    for (int kk = 0; kk < 32; kk += 8) {
        int c  = c0 + threadIdx.y + kk;
        int hw = hw0 + threadIdx.x;
        tile[threadIdx.y + kk][threadIdx.x] = (hw < HW) ? fb[(size_t)c * HW + hw] : 0.f;
    }
    __syncthreads();
    #pragma unroll
    for (int kk = 0; kk < 32; kk += 8) {
        int hw = hw0 + threadIdx.y + kk;
        int c  = c0 + threadIdx.x;
        if (hw < HW)
            xin[((size_t)b * SEQ_ + t0 + hw) * CIN_ + c] = tile[threadIdx.x][threadIdx.y + kk];
    }
}

// ---------------- embed epilogue --------------------------------------------
__global__ void embed_add_k(const float* __restrict__ conv_b,
                            const float* __restrict__ e_org,
                            const float* __restrict__ e_r1,
                            const float* __restrict__ e_r2,
                            const float* __restrict__ pos,
                            float* __restrict__ x) {
    int idx = blockIdx.x * 256 + threadIdx.x;
    const int total = B_ * 911 * D_;
    if (idx >= total) return;
    int d = idx & 511;
    int rest = idx >> 9;
    int tt = rest % 911;
    int b  = rest / 911;
    int ti, tj; const float* ce;
    if (tt < 768)      { int hh = tt >> 5,  ww = tt & 31;  ce = e_org; ti = hh*GRIDN/24; tj = ww*GRIDN/32; }
    else if (tt < 876) { int u = tt - 768;  int hh = u/12, ww = u%12; ce = e_r1; ti = hh*GRIDN/9;  tj = ww*GRIDN/12; }
    else               { int u = tt - 876;  int hh = u/7,  ww = u%7;  ce = e_r2; ti = hh*GRIDN/5;  tj = ww*GRIDN/7;  }
    x[((size_t)(b * SEQ_ + tt + 1)) * D_ + d] += conv_b[d] + ce[d] + pos[(size_t)(ti * GRIDN + tj) * D_ + d];
}

__global__ void cls_set_k(const float* __restrict__ c, float* __restrict__ x) {
    int idx = blockIdx.x * 256 + threadIdx.x;
    if (idx >= B_ * D_) return;
    int b = idx >> 9, d = idx & 511;
    x[(size_t)b * SEQ_ * D_ + d] = c[d];
}

// ---------------- residual + LayerNorm --------------------------------------
__global__ __launch_bounds__(128) void add_ln_k(
    const float* __restrict__ xin, const float* __restrict__ add,
    const float* __restrict__ g, const float* __restrict__ beta,
    float* __restrict__ xout) {
    __shared__ float red[4];
    __shared__ float bval;
    int row = blockIdx.x, tid = threadIdx.x;
    float4 xv = ((const float4*)(xin + (size_t)row * D_))[tid];
    float4 av = ((const float4*)(add + (size_t)row * D_))[tid];
    float4 s;
    s.x = xv.x + av.x; s.y = xv.y + av.y; s.z = xv.z + av.z; s.w = xv.w + av.w;
    float sum = s.x + s.y + s.z + s.w;
    #pragma unroll
    for (int o = 16; o > 0; o >>= 1) sum += __shfl_xor_sync(~0u, sum, o);
    if ((tid & 31) == 0) red[tid >> 5] = sum;
    __syncthreads();
    if (tid == 0) bval = (red[0] + red[1] + red[2] + red[3]) * (1.f / D_);
    __syncthreads();
    float m = bval;
    float d0 = s.x - m, d1 = s.y - m, d2 = s.z - m, d3 = s.w - m;
    float sq = d0 * d0 + d1 * d1 + d2 * d2 + d3 * d3;
    #pragma unroll
    for (int o = 16; o > 0; o >>= 1) sq += __shfl_xor_sync(~0u, sq, o);
    __syncthreads();
    if ((tid & 31) == 0) red[tid >> 5] = sq;
    __syncthreads();
    if (tid == 0) bval = rsqrtf((red[0] + red[1] + red[2] + red[3]) * (1.f / D_) + 1e-6f);
    __syncthreads();
    float rs = bval;
    float4 gv = ((const float4*)g)[tid];
    float4 bv = ((const float4*)beta)[tid];
    float4 o;
    o.x = d0 * rs * gv.x + bv.x; o.y = d1 * rs * gv.y + bv.y;
    o.z = d2 * rs * gv.z + bv.z; o.w = d3 * rs * gv.w + bv.w;
    ((float4*)(xout + (size_t)row * D_))[tid] = o;
}

// ---------------- head ------------------------------------------------------
__global__ __launch_bounds__(256) void head_mlp_k(
    const float* __restrict__ x, const float* __restrict__ w1,
    float* __restrict__ hm) {
    __shared__ float cls[512];
    int b = blockIdx.x;
    for (int d = threadIdx.x; d < 512; d += 256) cls[d] = x[(size_t)b * SEQ_ * D_ + d];
    __syncthreads();
    for (int n = threadIdx.x; n < DMLP_; n += 256) {
        const float* w = w1 + (size_t)n * 512;
        float s = 0.f;
        for (int d = 0; d < 512; d++) s += cls[d] * w[d];
        hm[b * DMLP_ + n] = gelu_f(s);
    }
}

__global__ __launch_bounds__(256) void head_out_k(
    const float* __restrict__ hm, const float* __restrict__ w2,
    float* __restrict__ out) {
    __shared__ float red[8];
    int b = blockIdx.x, tid = threadIdx.x;
    float s = 0.f;
    for (int n = tid; n < DMLP_; n += 256) s += hm[b * DMLP_ + n] * w2[n];
    #pragma unroll
    for (int o = 16; o > 0; o >>= 1) s += __shfl_xor_sync(~0u, s, o);
    if ((tid & 31) == 0) red[tid >> 5] = s;
    __syncthreads();
    if (tid == 0) {
        float t = 0; for (int w = 0; w < 8; w++) t += red[w];
        out[b] = t;
    }
}

// ---------------- host orchestration ----------------------------------------
extern "C" void kernel_launch(void* const* d_in, const int* in_sizes, int n_in,
                              void* d_out, int out_size) {
    const float* feat_org = (const float*)d_in[0];
    const float* feat_r1  = (const float*)d_in[1];
    const float* feat_r2  = (const float*)d_in[2];
    const float* conv_w   = (const float*)d_in[3];
    const float* conv_b   = (const float*)d_in[4];
    const float* e_org    = (const float*)d_in[5];
    const float* e_r1     = (const float*)d_in[6];
    const float* e_r2     = (const float*)d_in[7];
    const float* pos      = (const float*)d_in[8];
    const float* cls_tok  = (const float*)d_in[9];
    const float* Wq = (const float*)d_in[10]; const float* bq = (const float*)d_in[11];
    const float* Wk = (const float*)d_in[12]; const float* bk = (const float*)d_in[13];
    const float* Wv = (const float*)d_in[14]; const float* bv = (const float*)d_in[15];
    const float* Wo = (const float*)d_in[16]; const float* bo = (const float*)d_in[17];
    const float* ln1g = (const float*)d_in[18]; const float* ln1b = (const float*)d_in[19];
    const float* w1 = (const float*)d_in[20]; const float* b1 = (const float*)d_in[21];
    const float* w2 = (const float*)d_in[22]; const float* b2 = (const float*)d_in[23];
    const float* ln2g = (const float*)d_in[24]; const float* ln2b = (const float*)d_in[25];
    const float* pw1 = (const float*)d_in[26]; const float* pw2 = (const float*)d_in[27];
    const int*   mask = (const int*)d_in[28];

    float *xin, *h1, *x, *q, *k, *v, *ctx, *att, *hmlp;
    cudaGetSymbolAddress((void**)&xin, g_xin);
    cudaGetSymbolAddress((void**)&h1, g_h1);
    cudaGetSymbolAddress((void**)&x, g_x);
    cudaGetSymbolAddress((void**)&q, g_q);
    cudaGetSymbolAddress((void**)&k, g_k);
    cudaGetSymbolAddress((void**)&v, g_v);
    cudaGetSymbolAddress((void**)&ctx, g_ctx);
    cudaGetSymbolAddress((void**)&att, g_att);
    cudaGetSymbolAddress((void**)&hmlp, g_hmlp);

    cudaFuncSetAttribute(mma_gemm_nt, cudaFuncAttributeMaxDynamicSharedMemorySize, SMEM_GEMM_BYTES);
    cudaFuncSetAttribute(flash_attn_k, cudaFuncAttributeMaxDynamicSharedMemorySize, FSMEM_B);

    dim3 tb32(32, 8);
    gather_transpose_k<<<dim3(24, CIN_ / 32, B_), tb32>>>(feat_org, 768, 1,   xin);
    gather_transpose_k<<<dim3(4,  CIN_ / 32, B_), tb32>>>(feat_r1,  108, 769, xin);
    gather_transpose_k<<<dim3(2,  CIN_ / 32, B_), tb32>>>(feat_r2,  35,  877, xin);

    mma_gemm_nt<<<dim3(D_ / 128, M_ / 128), 256, SMEM_GEMM_BYTES>>>(M_, D_, CIN_, xin, conv_w, nullptr, x, 0);
    embed_add_k<<<(B_ * 911 * D_ + 255) / 256, 256>>>(conv_b, e_org, e_r1, e_r2, pos, x);
    cls_set_k<<<(B_ * D_ + 255) / 256, 256>>>(cls_tok, x);

    for (int i = 0; i < L_; i++) {
        const float* Wqi = Wq + (size_t)i * D_ * D_;
        const float* Wki = Wk + (size_t)i * D_ * D_;
        const float* Wvi = Wv + (size_t)i * D_ * D_;
        const float* Woi = Wo + (size_t)i * D_ * D_;
        mma_gemm_nt<<<dim3(D_ / 128, M_ / 128), 256, SMEM_GEMM_BYTES>>>(M_, D_, D_, x, Wqi, bq + i * D_, q, 0);
        mma_gemm_nt<<<dim3(D_ / 128, M_ / 128), 256, SMEM_GEMM_BYTES>>>(M_, D_, D_, x, Wki, bk + i * D_, k, 0);
        mma_gemm_nt<<<dim3(D_ / 128, M_ / 128), 256, SMEM_GEMM_BYTES>>>(M_, D_, D_, x, Wvi, bv + i * D_, v, 0);

        flash_attn_k<<<dim3(15, B_ * H_), 128, FSMEM_B>>>(q, k, v, mask, ctx);

        mma_gemm_nt<<<dim3(D_ / 128, M_ / 128), 256, SMEM_GEMM_BYTES>>>(M_, D_, D_, ctx, Woi, bo + i * D_, att, 0);
        add_ln_k<<<M_, 128>>>(x, att, ln1g + i * D_, ln1b + i * D_, x);

        mma_gemm_nt<<<dim3(DFF_ / 128, M_ / 128), 256, SMEM_GEMM_BYTES>>>(M_, DFF_, D_, x, w1 + (size_t)i * DFF_ * D_, b1 + i * DFF_, h1, 1);
        mma_gemm_nt<<<dim3(D_ / 128, M_ / 128), 256, SMEM_GEMM_BYTES>>>(M_, D_, DFF_, h1, w2 + (size_t)i * D_ * DFF_, b2 + i * D_, att, 0);
        add_ln_k<<<M_, 128>>>(x, att, ln2g + i * D_, ln2b + i * D_, x);
    }

    head_mlp_k<<<B_, 256>>>(x, pw1, hmlp);
    head_out_k<<<B_, 256>>>(hmlp, pw2, (float*)d_out);
}

// round 5
// speedup vs baseline: 2.8603x; 1.0167x over previous
#include <cuda_runtime.h>
#include <cuda_bf16.h>
#include <math.h>
#include <cstdint>

// ---------------- problem constants ----------------
#define B_    8
#define D_    512
#define H_    8
#define DH_   64
#define L_    6
#define DFF_  2048
#define GRIDN 10
#define DMLP_ 1024
#define CIN_  2048
#define SEQ_  912
#define M_    (B_*SEQ_)    // 7296
#define NQKV  1536

// ---------------- weight plane offsets (elements) ----------------
#define OFF_CONV   0
#define WPER_L     3145728
#define OFF_QKV(i) (1048576 + (size_t)(i)*WPER_L)
#define OFF_WO(i)  (OFF_QKV(i) + 786432)
#define OFF_W1(i)  (OFF_WO(i)  + 262144)
#define OFF_W2(i)  (OFF_W1(i)  + 1048576)
#define WTOTAL     (1048576 + 6*WPER_L)   // 19,922,944

// ---------------- scratch ----------------
__device__ __nv_bfloat16 g_wh[WTOTAL];
__device__ __nv_bfloat16 g_wl[WTOTAL];
__device__ __nv_bfloat16 g_xinh[M_*CIN_];
__device__ __nv_bfloat16 g_xinl[M_*CIN_];
__device__ __nv_bfloat16 g_xh[M_*D_];
__device__ __nv_bfloat16 g_xl[M_*D_];
__device__ __nv_bfloat16 g_qkvh[(size_t)M_*NQKV];
__device__ __nv_bfloat16 g_qkvl[(size_t)M_*NQKV];
__device__ __nv_bfloat16 g_ctxh[M_*D_];
__device__ __nv_bfloat16 g_ctxl[M_*D_];
__device__ __nv_bfloat16 g_h1h[M_*DFF_];
__device__ __nv_bfloat16 g_h1l[M_*DFF_];
__device__ float g_x  [M_*D_];
__device__ float g_att[M_*D_];
__device__ float g_bqkv[L_*NQKV];
__device__ float g_hmlp[B_*DMLP_];

__device__ __forceinline__ float gelu_f(float x) {
    return 0.5f * x * (1.0f + erff(x * 0.70710678118654752f));
}
__device__ __forceinline__ uint32_t smem_u32(const void* p) {
    uint32_t a;
    asm("{ .reg .u64 t; cvta.to.shared.u64 t, %1; cvt.u32.u64 %0, t; }" : "=r"(a) : "l"(p));
    return a;
}
__device__ __forceinline__ void mma16816(float* c, const uint32_t* a, const uint32_t* b) {
    asm volatile(
        "mma.sync.aligned.m16n8k16.row.col.f32.bf16.bf16.f32 "
        "{%0,%1,%2,%3}, {%4,%5,%6,%7}, {%8,%9}, {%0,%1,%2,%3};"
        : "+f"(c[0]), "+f"(c[1]), "+f"(c[2]), "+f"(c[3])
        : "r"(a[0]), "r"(a[1]), "r"(a[2]), "r"(a[3]), "r"(b[0]), "r"(b[1]));
}
__device__ __forceinline__ void ldsm4(uint32_t* r, uint32_t addr) {
    asm volatile("ldmatrix.sync.aligned.m8n8.x4.shared.b16 {%0,%1,%2,%3}, [%4];"
        : "=r"(r[0]), "=r"(r[1]), "=r"(r[2]), "=r"(r[3]) : "r"(addr));
}
__device__ __forceinline__ void ldsm2(uint32_t* r, uint32_t addr) {
    asm volatile("ldmatrix.sync.aligned.m8n8.x2.shared.b16 {%0,%1}, [%2];"
        : "=r"(r[0]), "=r"(r[1]) : "r"(addr));
}
__device__ __forceinline__ void cpasync16(uint32_t dst, const void* src) {
    asm volatile("cp.async.cg.shared.global [%0], [%1], 16;" :: "r"(dst), "l"(src));
}
__device__ __forceinline__ void pack_hilo(float4 v, uint2& h, uint2& l) {
    __nv_bfloat16 h0 = __float2bfloat16(v.x);
    __nv_bfloat16 h1 = __float2bfloat16(v.y);
    __nv_bfloat16 h2 = __float2bfloat16(v.z);
    __nv_bfloat16 h3 = __float2bfloat16(v.w);
    __nv_bfloat16 l0 = __float2bfloat16(v.x - __bfloat162float(h0));
    __nv_bfloat16 l1 = __float2bfloat16(v.y - __bfloat162float(h1));
    __nv_bfloat16 l2 = __float2bfloat16(v.z - __bfloat162float(h2));
    __nv_bfloat16 l3 = __float2bfloat16(v.w - __bfloat162float(h3));
    __nv_bfloat162 H01(h0, h1), H23(h2, h3), L01(l0, l1), L23(l2, l3);
    h.x = *(uint32_t*)&H01; h.y = *(uint32_t*)&H23;
    l.x = *(uint32_t*)&L01; l.y = *(uint32_t*)&L23;
}

// ---------------- conversion helpers ----------------------------------------
__global__ void cvt_hilo_k(const float* __restrict__ s,
                           __nv_bfloat16* __restrict__ h,
                           __nv_bfloat16* __restrict__ l, int n) {
    int i = (blockIdx.x * 256 + threadIdx.x) * 4;
    if (i >= n) return;
    float4 v = *(const float4*)(s + i);
    uint2 hh, ll;
    pack_hilo(v, hh, ll);
    *(uint2*)(h + i) = hh;
    *(uint2*)(l + i) = ll;
}

__global__ void stack_bias_k(const float* __restrict__ bq, const float* __restrict__ bk,
                             const float* __restrict__ bv, float* __restrict__ out) {
    int i = blockIdx.x * 256 + threadIdx.x;
    if (i >= L_ * NQKV) return;
    int layer = i / NQKV, c = i % NQKV;
    float v = (c < 512) ? bq[layer * 512 + c]
            : (c < 1024) ? bk[layer * 512 + c - 512]
                         : bv[layer * 512 + c - 1024];
    out[i] = v;
}

// ============================================================================
// bf16 plane GEMM NT with cp.async double-buffer, 2 CTAs/SM
// C[M,N] = (Ah+Al)[M,K] @ (Bh+Bl)[N,K]^T  (3-term compensation)
// ============================================================================
#define GTS 40
#define GTILE_E (128*GTS)
#define GTILE_B (GTILE_E*2)        // 10240
#define GSTAGE_B (4*GTILE_B)       // 40960
#define GSMEM_B (2*GSTAGE_B)       // 81920

__global__ void __launch_bounds__(256, 2) bf16_gemm_nt(
    int M, int N, int K,
    const __nv_bfloat16* __restrict__ Ah, const __nv_bfloat16* __restrict__ Al,
    const __nv_bfloat16* __restrict__ Bh, const __nv_bfloat16* __restrict__ Bl,
    const float* __restrict__ bias,
    float* __restrict__ outF, __nv_bfloat16* __restrict__ outH,
    __nv_bfloat16* __restrict__ outL, int act) {
    extern __shared__ char smc[];
    uint32_t sb = smem_u32(smc);
    int tid = threadIdx.x, lane = tid & 31, wid = tid >> 5;
    int wm = wid & 1, wn = wid >> 1;
    int bm = blockIdx.y * 128, bn = blockIdx.x * 128;

    float acc[4][4][4];
    #pragma unroll
    for (int i = 0; i < 4; i++)
        #pragma unroll
        for (int j = 0; j < 4; j++)
            #pragma unroll
            for (int e = 0; e < 4; e++) acc[i][j][e] = 0.f;

    #define ISSUE(c) do {                                                      \
        int k0 = (c) * 32;                                                     \
        uint32_t dst = sb + ((c) & 1) * GSTAGE_B;                              \
        _Pragma("unroll")                                                      \
        for (int i = 0; i < 2; i++) {                                          \
            int seg = tid + i * 256;                                           \
            int row = seg >> 2, s4 = seg & 3;                                  \
            uint32_t off = (uint32_t)(row * GTS + s4 * 8) * 2;                 \
            cpasync16(dst + off,               Ah + (size_t)(bm + row) * K + k0 + s4 * 8); \
            cpasync16(dst + GTILE_B + off,     Al + (size_t)(bm + row) * K + k0 + s4 * 8); \
            cpasync16(dst + 2 * GTILE_B + off, Bh + (size_t)(bn + row) * K + k0 + s4 * 8); \
            cpasync16(dst + 3 * GTILE_B + off, Bl + (size_t)(bn + row) * K + k0 + s4 * 8); \
        }                                                                      \
        asm volatile("cp.async.commit_group;" ::: "memory");                   \
    } while (0)

    int nch = K >> 5;
    ISSUE(0);
    ISSUE(1);

    int a_r = wm * 64 + (lane & 15);
    int a_c = (lane >> 4) * 8;
    int b_r = wn * 32 + (lane & 7);
    int b_c = ((lane >> 3) & 1) * 8;

    for (int c = 0; c < nch; c++) {
        asm volatile("cp.async.wait_group 1;" ::: "memory");
        __syncthreads();
        uint32_t rbase = sb + (c & 1) * GSTAGE_B;
        #pragma unroll
        for (int ks = 0; ks < 2; ks++) {
            uint32_t af[4][4], bh[4][2], bl[4][2];
            #pragma unroll
            for (int mt = 0; mt < 4; mt++)
                ldsm4(af[mt], rbase + ((a_r + mt * 16) * GTS + ks * 16 + a_c) * 2);
            #pragma unroll
            for (int nt = 0; nt < 4; nt++)
                ldsm2(bh[nt], rbase + 2 * GTILE_B + ((b_r + nt * 8) * GTS + ks * 16 + b_c) * 2);
            #pragma unroll
            for (int mt = 0; mt < 4; mt++)
                #pragma unroll
                for (int nt = 0; nt < 4; nt++)
                    mma16816(acc[mt][nt], af[mt], bh[nt]);          // Ah*Bh
            #pragma unroll
            for (int nt = 0; nt < 4; nt++)
                ldsm2(bl[nt], rbase + 3 * GTILE_B + ((b_r + nt * 8) * GTS + ks * 16 + b_c) * 2);
            #pragma unroll
            for (int mt = 0; mt < 4; mt++)
                #pragma unroll
                for (int nt = 0; nt < 4; nt++)
                    mma16816(acc[mt][nt], af[mt], bl[nt]);          // Ah*Bl
            #pragma unroll
            for (int mt = 0; mt < 4; mt++)
                ldsm4(af[mt], rbase + GTILE_B + ((a_r + mt * 16) * GTS + ks * 16 + a_c) * 2);
            #pragma unroll
            for (int mt = 0; mt < 4; mt++)
                #pragma unroll
                for (int nt = 0; nt < 4; nt++)
                    mma16816(acc[mt][nt], af[mt], bh[nt]);          // Al*Bh
        }
        __syncthreads();
        if (c + 2 < nch) ISSUE(c + 2);
        else asm volatile("cp.async.commit_group;" ::: "memory");
    }

    #pragma unroll
    for (int mt = 0; mt < 4; mt++) {
        int m0 = bm + wm * 64 + mt * 16 + (lane >> 2);
        #pragma unroll
        for (int nt = 0; nt < 4; nt++) {
            int col = bn + wn * 32 + nt * 8 + (lane & 3) * 2;
            float b0 = bias ? bias[col]     : 0.f;
            float b1 = bias ? bias[col + 1] : 0.f;
            float v0 = acc[mt][nt][0] + b0, v1 = acc[mt][nt][1] + b1;
            float v2 = acc[mt][nt][2] + b0, v3 = acc[mt][nt][3] + b1;
            if (act == 1) { v0 = gelu_f(v0); v1 = gelu_f(v1); v2 = gelu_f(v2); v3 = gelu_f(v3); }
            if (outF) {
                float2 p0; p0.x = v0; p0.y = v1;
                float2 p1; p1.x = v2; p1.y = v3;
                *(float2*)(outF + (size_t)m0 * N + col)       = p0;
                *(float2*)(outF + (size_t)(m0 + 8) * N + col) = p1;
            } else {
                __nv_bfloat16 h0 = __float2bfloat16(v0), h1 = __float2bfloat16(v1);
                __nv_bfloat16 h2 = __float2bfloat16(v2), h3 = __float2bfloat16(v3);
                __nv_bfloat16 q0 = __float2bfloat16(v0 - __bfloat162float(h0));
                __nv_bfloat16 q1 = __float2bfloat16(v1 - __bfloat162float(h1));
                __nv_bfloat16 q2 = __float2bfloat16(v2 - __bfloat162float(h2));
                __nv_bfloat16 q3 = __float2bfloat16(v3 - __bfloat162float(h3));
                __nv_bfloat162 H01(h0, h1), H23(h2, h3), L01(q0, q1), L23(q2, q3);
                *(uint32_t*)(outH + (size_t)m0 * N + col)       = *(uint32_t*)&H01;
                *(uint32_t*)(outH + (size_t)(m0 + 8) * N + col) = *(uint32_t*)&H23;
                *(uint32_t*)(outL + (size_t)m0 * N + col)       = *(uint32_t*)&L01;
                *(uint32_t*)(outL + (size_t)(m0 + 8) * N + col) = *(uint32_t*)&L23;
            }
        }
    }
    #undef ISSUE
}

// ============================================================================
// Fused flash attention reading bf16 planes from fused qkv buffer
// ============================================================================
#define FTS 72
#define FQH 0
#define FQL (64*FTS)
#define FKH (2*64*FTS)
#define FKL (3*64*FTS)
#define FVH (4*64*FTS)
#define FVL (5*64*FTS)
#define FMASK_B (6*64*FTS*2)
#define FSMEM_B (FMASK_B + 64*4)

__global__ void __launch_bounds__(128) flash_attn_k(
    const __nv_bfloat16* __restrict__ qkvh, const __nv_bfloat16* __restrict__ qkvl,
    const int* __restrict__ mask,
    __nv_bfloat16* __restrict__ ctxh, __nv_bfloat16* __restrict__ ctxl) {
    extern __shared__ char sm[];
    __nv_bfloat16* sb = (__nv_bfloat16*)sm;
    float* maskadd = (float*)(sm + FMASK_B);
    uint32_t sbase = smem_u32(sm);
    int tid = threadIdx.x, lane = tid & 31, w = tid >> 5;
    int bh = blockIdx.y, b = bh >> 3, h = bh & 7;
    int i0 = blockIdx.x * 64;

    // stage Q (hi/lo)
    #pragma unroll
    for (int i = 0; i < 4; i++) {
        int lin = i * 128 + tid;
        int r = lin >> 3, c8 = lin & 7;
        int gr = i0 + r; if (gr >= SEQ_) gr = SEQ_ - 1;
        size_t base = (size_t)(b * SEQ_ + gr) * NQKV + h * 64 + c8 * 8;
        *(uint4*)(sb + FQH + r * FTS + c8 * 8) = *(const uint4*)(qkvh + base);
        *(uint4*)(sb + FQL + r * FTS + c8 * 8) = *(const uint4*)(qkvl + base);
    }

    float m0 = -INFINITY, m1 = -INFINITY, l0 = 0.f, l1 = 0.f;
    float O[8][4];
    #pragma unroll
    for (int nt = 0; nt < 8; nt++)
        #pragma unroll
        for (int e = 0; e < 4; e++) O[nt][e] = 0.f;

    int a_r = w * 16 + (lane & 15);
    int a_c = (lane >> 4) * 8;
    int b_r = lane & 7;
    int b_c = ((lane >> 3) & 1) * 8;
    int g = lane >> 2;

    for (int j0 = 0; j0 < 960; j0 += 64) {
        #pragma unroll
        for (int i = 0; i < 4; i++) {
            int lin = i * 128 + tid;
            int r = lin >> 3, c8 = lin & 7;
            int gr = j0 + r; if (gr >= SEQ_) gr = SEQ_ - 1;
            size_t base = (size_t)(b * SEQ_ + gr) * NQKV + h * 64 + c8 * 8;
            *(uint4*)(sb + FKH + r * FTS + c8 * 8) = *(const uint4*)(qkvh + base + 512);
            *(uint4*)(sb + FKL + r * FTS + c8 * 8) = *(const uint4*)(qkvl + base + 512);
            uint4 vh4 = *(const uint4*)(qkvh + base + 1024);
            uint4 vl4 = *(const uint4*)(qkvl + base + 1024);
            const __nv_bfloat16* ph = (const __nv_bfloat16*)&vh4;
            const __nv_bfloat16* pl = (const __nv_bfloat16*)&vl4;
            int d0 = c8 * 8;
            #pragma unroll
            for (int u = 0; u < 8; u++) {
                sb[FVH + (d0 + u) * FTS + r] = ph[u];
                sb[FVL + (d0 + u) * FTS + r] = pl[u];
            }
        }
        if (tid < 64) {
            int j = j0 + tid;
            maskadd[tid] = (j >= SEQ_) ? -INFINITY
                          : (mask[b * SEQ_ + j] == 0 ? -1e9f : 0.f);
        }
        __syncthreads();

        // S = (Q K^T) * 0.125 + mask
        float S[8][4];
        #pragma unroll
        for (int nt = 0; nt < 8; nt++)
            #pragma unroll
            for (int e = 0; e < 4; e++) S[nt][e] = 0.f;
        #pragma unroll
        for (int kc = 0; kc < 4; kc++) {
            uint32_t aqh[4], aql[4];
            ldsm4(aqh, sbase + (FQH + a_r * FTS + kc * 16 + a_c) * 2);
            ldsm4(aql, sbase + (FQL + a_r * FTS + kc * 16 + a_c) * 2);
            #pragma unroll
            for (int nt = 0; nt < 8; nt++) {
                uint32_t bkh[2], bkl[2];
                ldsm2(bkh, sbase + (FKH + (nt * 8 + b_r) * FTS + kc * 16 + b_c) * 2);
                ldsm2(bkl, sbase + (FKL + (nt * 8 + b_r) * FTS + kc * 16 + b_c) * 2);
                mma16816(S[nt], aqh, bkh);
                mma16816(S[nt], aqh, bkl);
                mma16816(S[nt], aql, bkh);
            }
        }
        #pragma unroll
        for (int nt = 0; nt < 8; nt++) {
            int col = nt * 8 + (lane & 3) * 2;
            float ma0 = maskadd[col], ma1 = maskadd[col + 1];
            S[nt][0] = fmaf(S[nt][0], 0.125f, ma0);
            S[nt][1] = fmaf(S[nt][1], 0.125f, ma1);
            S[nt][2] = fmaf(S[nt][2], 0.125f, ma0);
            S[nt][3] = fmaf(S[nt][3], 0.125f, ma1);
        }
        float rm0 = -INFINITY, rm1 = -INFINITY;
        #pragma unroll
        for (int nt = 0; nt < 8; nt++) {
            rm0 = fmaxf(rm0, fmaxf(S[nt][0], S[nt][1]));
            rm1 = fmaxf(rm1, fmaxf(S[nt][2], S[nt][3]));
        }
        rm0 = fmaxf(rm0, __shfl_xor_sync(~0u, rm0, 1));
        rm0 = fmaxf(rm0, __shfl_xor_sync(~0u, rm0, 2));
        rm1 = fmaxf(rm1, __shfl_xor_sync(~0u, rm1, 1));
        rm1 = fmaxf(rm1, __shfl_xor_sync(~0u, rm1, 2));
        float nm0 = fmaxf(m0, rm0), nm1 = fmaxf(m1, rm1);
        float f0 = expf(m0 - nm0), f1 = expf(m1 - nm1);
        m0 = nm0; m1 = nm1;
        float s0 = 0.f, s1 = 0.f;
        #pragma unroll
        for (int nt = 0; nt < 8; nt++) {
            S[nt][0] = expf(S[nt][0] - m0);
            S[nt][1] = expf(S[nt][1] - m0);
            S[nt][2] = expf(S[nt][2] - m1);
            S[nt][3] = expf(S[nt][3] - m1);
            s0 += S[nt][0] + S[nt][1];
            s1 += S[nt][2] + S[nt][3];
        }
        s0 += __shfl_xor_sync(~0u, s0, 1);
        s0 += __shfl_xor_sync(~0u, s0, 2);
        s1 += __shfl_xor_sync(~0u, s1, 1);
        s1 += __shfl_xor_sync(~0u, s1, 2);
        l0 = l0 * f0 + s0;
        l1 = l1 * f1 + s1;
        #pragma unroll
        for (int nt = 0; nt < 8; nt++) {
            O[nt][0] *= f0; O[nt][1] *= f0;
            O[nt][2] *= f1; O[nt][3] *= f1;
        }
        #pragma unroll
        for (int kc = 0; kc < 4; kc++) {
            uint2 h0, l0r, h1, l1r;
            pack_hilo(make_float4(S[2*kc][0], S[2*kc][1], S[2*kc][2], S[2*kc][3]), h0, l0r);
            pack_hilo(make_float4(S[2*kc+1][0], S[2*kc+1][1], S[2*kc+1][2], S[2*kc+1][3]), h1, l1r);
            uint32_t aph[4] = { h0.x, h0.y, h1.x, h1.y };
            uint32_t apl[4] = { l0r.x, l0r.y, l1r.x, l1r.y };
            #pragma unroll
            for (int nt = 0; nt < 8; nt++) {
                uint32_t bvh[2], bvl[2];
                ldsm2(bvh, sbase + (FVH + (nt * 8 + b_r) * FTS + kc * 16 + b_c) * 2);
                ldsm2(bvl, sbase + (FVL + (nt * 8 + b_r) * FTS + kc * 16 + b_c) * 2);
                mma16816(O[nt], aph, bvh);
                mma16816(O[nt], aph, bvl);
                mma16816(O[nt], apl, bvh);
            }
        }
        __syncthreads();
    }

    float inv0 = 1.f / l0, inv1 = 1.f / l1;
    int r0 = i0 + w * 16 + g, r1 = r0 + 8;
    #pragma unroll
    for (int nt = 0; nt < 8; nt++) {
        int d = h * DH_ + nt * 8 + (lane & 3) * 2;
        if (r0 < SEQ_) {
            float v0 = O[nt][0] * inv0, v1 = O[nt][1] * inv0;
            __nv_bfloat16 h0 = __float2bfloat16(v0), h1 = __float2bfloat16(v1);
            __nv_bfloat16 q0 = __float2bfloat16(v0 - __bfloat162float(h0));
            __nv_bfloat16 q1 = __float2bfloat16(v1 - __bfloat162float(h1));
            __nv_bfloat162 H(h0, h1), Lw(q0, q1);
            *(uint32_t*)(ctxh + (size_t)(b * SEQ_ + r0) * D_ + d) = *(uint32_t*)&H;
            *(uint32_t*)(ctxl + (size_t)(b * SEQ_ + r0) * D_ + d) = *(uint32_t*)&Lw;
        }
        if (r1 < SEQ_) {
            float v0 = O[nt][2] * inv1, v1 = O[nt][3] * inv1;
            __nv_bfloat16 h0 = __float2bfloat16(v0), h1 = __float2bfloat16(v1);
            __nv_bfloat16 q0 = __float2bfloat16(v0 - __bfloat162float(h0));
            __nv_bfloat16 q1 = __float2bfloat16(v1 - __bfloat162float(h1));
            __nv_bfloat162 H(h0, h1), Lw(q0, q1);
            *(uint32_t*)(ctxh + (size_t)(b * SEQ_ + r1) * D_ + d) = *(uint32_t*)&H;
            *(uint32_t*)(ctxl + (size_t)(b * SEQ_ + r1) * D_ + d) = *(uint32_t*)&Lw;
        }
    }
}

// ---------------- gather: feat [B,CIN,HW] -> xin planes [B,SEQ,CIN] ---------
__global__ void gather_transpose_k(const float* __restrict__ feat, int HW, int t0,
                                   __nv_bfloat16* __restrict__ xh,
                                   __nv_bfloat16* __restrict__ xl) {
    __shared__ float tile[32][33];
    int b   = blockIdx.z;
    int hw0 = blockIdx.x * 32, c0 = blockIdx.y * 32;
    const float* fb = feat + (size_t)b * CIN_ * HW;
    #pragma unroll
    for (int kk = 0; kk < 32; kk += 8) {
        int c  = c0 + threadIdx.y + kk;
        int hw = hw0 + threadIdx.x;
        tile[threadIdx.y + kk][threadIdx.x] = (hw < HW) ? fb[(size_t)c * HW + hw] : 0.f;
    }
    __syncthreads();
    #pragma unroll
    for (int kk = 0; kk < 32; kk += 8) {
        int hw = hw0 + threadIdx.y + kk;
        int c  = c0 + threadIdx.x;
        if (hw < HW) {
            float v = tile[threadIdx.x][threadIdx.y + kk];
            __nv_bfloat16 h = __float2bfloat16(v);
            __nv_bfloat16 l = __float2bfloat16(v - __bfloat162float(h));
            size_t idx = ((size_t)b * SEQ_ + t0 + hw) * CIN_ + c;
            xh[idx] = h; xl[idx] = l;
        }
    }
}

// zero pad row t=0 of xin planes (cls handled separately after GEMM)
__global__ void zero_xin_row0_k(__nv_bfloat16* __restrict__ xh,
                                __nv_bfloat16* __restrict__ xl) {
    int idx = blockIdx.x * 256 + threadIdx.x;
    if (idx >= B_ * CIN_) return;
    int b = idx / CIN_, c = idx % CIN_;
    size_t o = (size_t)b * SEQ_ * CIN_ + c;
    xh[o] = __float2bfloat16(0.f);
    xl[o] = __float2bfloat16(0.f);
}

// ---------------- embed epilogue --------------------------------------------
__global__ void embed_add_k(const float* __restrict__ conv_b,
                            const float* __restrict__ e_org,
                            const float* __restrict__ e_r1,
                            const float* __restrict__ e_r2,
                            const float* __restrict__ pos,
                            float* __restrict__ x) {
    int idx = blockIdx.x * 256 + threadIdx.x;
    const int total = B_ * 911 * D_;
    if (idx >= total) return;
    int d = idx & 511;
    int rest = idx >> 9;
    int tt = rest % 911;
    int b  = rest / 911;
    int ti, tj; const float* ce;
    if (tt < 768)      { int hh = tt >> 5,  ww = tt & 31;  ce = e_org; ti = hh*GRIDN/24; tj = ww*GRIDN/32; }
    else if (tt < 876) { int u = tt - 768;  int hh = u/12, ww = u%12; ce = e_r1; ti = hh*GRIDN/9;  tj = ww*GRIDN/12; }
    else               { int u = tt - 876;  int hh = u/7,  ww = u%7;  ce = e_r2; ti = hh*GRIDN/5;  tj = ww*GRIDN/7;  }
    x[((size_t)(b * SEQ_ + tt + 1)) * D_ + d] += conv_b[d] + ce[d] + pos[(size_t)(ti * GRIDN + tj) * D_ + d];
}

__global__ void cls_set_k(const float* __restrict__ c, float* __restrict__ x) {
    int idx = blockIdx.x * 256 + threadIdx.x;
    if (idx >= B_ * D_) return;
    int b = idx >> 9, d = idx & 511;
    x[(size_t)b * SEQ_ * D_ + d] = c[d];
}

// ---------------- residual + LayerNorm (also emits hi/lo planes) ------------
__global__ __launch_bounds__(128) void add_ln_k(
    const float* __restrict__ xin, const float* __restrict__ add,
    const float* __restrict__ g, const float* __restrict__ beta,
    float* __restrict__ xout, __nv_bfloat16* __restrict__ xh,
    __nv_bfloat16* __restrict__ xl) {
    __shared__ float red[4];
    __shared__ float bval;
    int row = blockIdx.x, tid = threadIdx.x;
    float4 xv = ((const float4*)(xin + (size_t)row * D_))[tid];
    float4 av = ((const float4*)(add + (size_t)row * D_))[tid];
    float4 s;
    s.x = xv.x + av.x; s.y = xv.y + av.y; s.z = xv.z + av.z; s.w = xv.w + av.w;
    float sum = s.x + s.y + s.z + s.w;
    #pragma unroll
    for (int o = 16; o > 0; o >>= 1) sum += __shfl_xor_sync(~0u, sum, o);
    if ((tid & 31) == 0) red[tid >> 5] = sum;
    __syncthreads();
    if (tid == 0) bval = (red[0] + red[1] + red[2] + red[3]) * (1.f / D_);
    __syncthreads();
    float m = bval;
    float d0 = s.x - m, d1 = s.y - m, d2 = s.z - m, d3 = s.w - m;
    float sq = d0 * d0 + d1 * d1 + d2 * d2 + d3 * d3;
    #pragma unroll
    for (int o = 16; o > 0; o >>= 1) sq += __shfl_xor_sync(~0u, sq, o);
    __syncthreads();
    if ((tid & 31) == 0) red[tid >> 5] = sq;
    __syncthreads();
    if (tid == 0) bval = rsqrtf((red[0] + red[1] + red[2] + red[3]) * (1.f / D_) + 1e-6f);
    __syncthreads();
    float rs = bval;
    float4 gv = ((const float4*)g)[tid];
    float4 bv = ((const float4*)beta)[tid];
    float4 o;
    o.x = d0 * rs * gv.x + bv.x; o.y = d1 * rs * gv.y + bv.y;
    o.z = d2 * rs * gv.z + bv.z; o.w = d3 * rs * gv.w + bv.w;
    ((float4*)(xout + (size_t)row * D_))[tid] = o;
    uint2 hh, ll;
    pack_hilo(o, hh, ll);
    *(uint2*)(xh + (size_t)row * D_ + tid * 4) = hh;
    *(uint2*)(xl + (size_t)row * D_ + tid * 4) = ll;
}

// ---------------- head ------------------------------------------------------
__global__ __launch_bounds__(256) void head_mlp_k(
    const float* __restrict__ x, const float* __restrict__ w1,
    float* __restrict__ hm) {
    __shared__ float cls[512];
    int b = blockIdx.x;
    for (int d = threadIdx.x; d < 512; d += 256) cls[d] = x[(size_t)b * SEQ_ * D_ + d];
    __syncthreads();
    for (int n = threadIdx.x; n < DMLP_; n += 256) {
        const float* w = w1 + (size_t)n * 512;
        float s = 0.f;
        for (int d = 0; d < 512; d++) s += cls[d] * w[d];
        hm[b * DMLP_ + n] = gelu_f(s);
    }
}

__global__ __launch_bounds__(256) void head_out_k(
    const float* __restrict__ hm, const float* __restrict__ w2,
    float* __restrict__ out) {
    __shared__ float red[8];
    int b = blockIdx.x, tid = threadIdx.x;
    float s = 0.f;
    for (int n = tid; n < DMLP_; n += 256) s += hm[b * DMLP_ + n] * w2[n];
    #pragma unroll
    for (int o = 16; o > 0; o >>= 1) s += __shfl_xor_sync(~0u, s, o);
    if ((tid & 31) == 0) red[tid >> 5] = s;
    __syncthreads();
    if (tid == 0) {
        float t = 0; for (int w = 0; w < 8; w++) t += red[w];
        out[b] = t;
    }
}

// ---------------- host orchestration ----------------------------------------
extern "C" void kernel_launch(void* const* d_in, const int* in_sizes, int n_in,
                              void* d_out, int out_size) {
    const float* feat_org = (const float*)d_in[0];
    const float* feat_r1  = (const float*)d_in[1];
    const float* feat_r2  = (const float*)d_in[2];
    const float* conv_w   = (const float*)d_in[3];
    const float* conv_b   = (const float*)d_in[4];
    const float* e_org    = (const float*)d_in[5];
    const float* e_r1     = (const float*)d_in[6];
    const float* e_r2     = (const float*)d_in[7];
    const float* pos      = (const float*)d_in[8];
    const float* cls_tok  = (const float*)d_in[9];
    const float* Wq = (const float*)d_in[10]; const float* bq = (const float*)d_in[11];
    const float* Wk = (const float*)d_in[12]; const float* bk = (const float*)d_in[13];
    const float* Wv = (const float*)d_in[14]; const float* bv = (const float*)d_in[15];
    const float* Wo = (const float*)d_in[16]; const float* bo = (const float*)d_in[17];
    const float* ln1g = (const float*)d_in[18]; const float* ln1b = (const float*)d_in[19];
    const float* w1 = (const float*)d_in[20]; const float* b1 = (const float*)d_in[21];
    const float* w2 = (const float*)d_in[22]; const float* b2 = (const float*)d_in[23];
    const float* ln2g = (const float*)d_in[24]; const float* ln2b = (const float*)d_in[25];
    const float* pw1 = (const float*)d_in[26]; const float* pw2 = (const float*)d_in[27];
    const int*   mask = (const int*)d_in[28];

    __nv_bfloat16 *wh, *wl, *xinh, *xinl, *xh, *xl, *qkvh, *qkvl, *ctxh, *ctxl, *h1h, *h1l;
    float *x, *att, *bqkv, *hmlp;
    cudaGetSymbolAddress((void**)&wh, g_wh);
    cudaGetSymbolAddress((void**)&wl, g_wl);
    cudaGetSymbolAddress((void**)&xinh, g_xinh);
    cudaGetSymbolAddress((void**)&xinl, g_xinl);
    cudaGetSymbolAddress((void**)&xh, g_xh);
    cudaGetSymbolAddress((void**)&xl, g_xl);
    cudaGetSymbolAddress((void**)&qkvh, g_qkvh);
    cudaGetSymbolAddress((void**)&qkvl, g_qkvl);
    cudaGetSymbolAddress((void**)&ctxh, g_ctxh);
    cudaGetSymbolAddress((void**)&ctxl, g_ctxl);
    cudaGetSymbolAddress((void**)&h1h, g_h1h);
    cudaGetSymbolAddress((void**)&h1l, g_h1l);
    cudaGetSymbolAddress((void**)&x, g_x);
    cudaGetSymbolAddress((void**)&att, g_att);
    cudaGetSymbolAddress((void**)&bqkv, g_bqkv);
    cudaGetSymbolAddress((void**)&hmlp, g_hmlp);

    cudaFuncSetAttribute(bf16_gemm_nt, cudaFuncAttributeMaxDynamicSharedMemorySize, GSMEM_B);
    cudaFuncSetAttribute(flash_attn_k, cudaFuncAttributeMaxDynamicSharedMemorySize, FSMEM_B);

    // ---- weight conversions ----
    #define CVT(src, off, n) cvt_hilo_k<<<((n)/4 + 255)/256, 256>>>(src, wh + (off), wl + (off), n)
    CVT(conv_w, OFF_CONV, D_*CIN_);
    for (int i = 0; i < L_; i++) {
        CVT(Wq + (size_t)i*D_*D_,   OFF_QKV(i),            D_*D_);
        CVT(Wk + (size_t)i*D_*D_,   OFF_QKV(i) + 262144,   D_*D_);
        CVT(Wv + (size_t)i*D_*D_,   OFF_QKV(i) + 524288,   D_*D_);
        CVT(Wo + (size_t)i*D_*D_,   OFF_WO(i),             D_*D_);
        CVT(w1 + (size_t)i*DFF_*D_, OFF_W1(i),             DFF_*D_);
        CVT(w2 + (size_t)i*D_*DFF_, OFF_W2(i),             D_*DFF_);
    }
    #undef CVT
    stack_bias_k<<<(L_*NQKV + 255)/256, 256>>>(bq, bk, bv, bqkv);

    // ---- embed ----
    dim3 tb32(32, 8);
    gather_transpose_k<<<dim3(24, CIN_ / 32, B_), tb32>>>(feat_org, 768, 1,   xinh, xinl);
    gather_transpose_k<<<dim3(4,  CIN_ / 32, B_), tb32>>>(feat_r1,  108, 769, xinh, xinl);
    gather_transpose_k<<<dim3(2,  CIN_ / 32, B_), tb32>>>(feat_r2,  35,  877, xinh, xinl);
    zero_xin_row0_k<<<(B_*CIN_ + 255)/256, 256>>>(xinh, xinl);

    bf16_gemm_nt<<<dim3(4, 57), 256, GSMEM_B>>>(M_, D_, CIN_, xinh, xinl,
        wh + OFF_CONV, wl + OFF_CONV, nullptr, x, nullptr, nullptr, 0);
    embed_add_k<<<(B_ * 911 * D_ + 255) / 256, 256>>>(conv_b, e_org, e_r1, e_r2, pos, x);
    cls_set_k<<<(B_ * D_ + 255) / 256, 256>>>(cls_tok, x);
    cvt_hilo_k<<<(M_*D_/4 + 255)/256, 256>>>(x, xh, xl, M_*D_);

    for (int i = 0; i < L_; i++) {
        // QKV fused: [M,1536]
        bf16_gemm_nt<<<dim3(12, 57), 256, GSMEM_B>>>(M_, NQKV, D_, xh, xl,
            wh + OFF_QKV(i), wl + OFF_QKV(i), bqkv + i*NQKV, nullptr, qkvh, qkvl, 0);

        flash_attn_k<<<dim3(15, B_ * H_), 128, FSMEM_B>>>(qkvh, qkvl, mask, ctxh, ctxl);

        bf16_gemm_nt<<<dim3(4, 57), 256, GSMEM_B>>>(M_, D_, D_, ctxh, ctxl,
            wh + OFF_WO(i), wl + OFF_WO(i), bo + i*D_, att, nullptr, nullptr, 0);
        add_ln_k<<<M_, 128>>>(x, att, ln1g + i*D_, ln1b + i*D_, x, xh, xl);

        bf16_gemm_nt<<<dim3(16, 57), 256, GSMEM_B>>>(M_, DFF_, D_, xh, xl,
            wh + OFF_W1(i), wl + OFF_W1(i), b1 + i*DFF_, nullptr, h1h, h1l, 1);
        bf16_gemm_nt<<<dim3(4, 57), 256, GSMEM_B>>>(M_, D_, DFF_, h1h, h1l,
            wh + OFF_W2(i), wl + OFF_W2(i), b2 + i*D_, att, nullptr, nullptr, 0);
        add_ln_k<<<M_, 128>>>(x, att, ln2g + i*D_, ln2b + i*D_, x, xh, xl);
    }

    head_mlp_k<<<B_, 256>>>(x, pw1, hmlp);
    head_out_k<<<B_, 256>>>(hmlp, pw2, (float*)d_out);
}

// round 6
// speedup vs baseline: 3.4733x; 1.2143x over previous
#include <cuda_runtime.h>
#include <cuda_bf16.h>
#include <cuda_fp16.h>
#include <math.h>
#include <cstdint>

// ---------------- problem constants ----------------
#define B_    8
#define D_    512
#define H_    8
#define DH_   64
#define L_    6
#define DFF_  2048
#define GRIDN 10
#define DMLP_ 1024
#define CIN_  2048
#define SEQ_  912
#define M_    (B_*SEQ_)    // 7296
#define NQKV  1536

// ---------------- scratch ----------------
__device__ __half g_wconv[D_*CIN_];
__device__ __half g_wqkv [L_*NQKV*D_];
__device__ __half g_wo   [L_*D_*D_];
__device__ __half g_w1   [L_*DFF_*D_];
__device__ __half g_w2   [L_*D_*DFF_];
__device__ __half g_xinh[M_*CIN_];
__device__ __half g_xinl[M_*CIN_];
__device__ __half g_xh[M_*D_];
__device__ __half g_xl[M_*D_];
__device__ __nv_bfloat16 g_qkvh[(size_t)M_*NQKV];
__device__ __nv_bfloat16 g_qkvl[(size_t)M_*NQKV];
__device__ __half g_ctxh[M_*D_];
__device__ __half g_ctxl[M_*D_];
__device__ __half g_h1h[M_*DFF_];
__device__ __half g_h1l[M_*DFF_];
__device__ float g_x  [M_*D_];
__device__ float g_att[M_*D_];
__device__ float g_bqkv[L_*NQKV];
__device__ float g_hmlp[B_*DMLP_];

__device__ __forceinline__ float gelu_f(float x) {
    return 0.5f * x * (1.0f + erff(x * 0.70710678118654752f));
}
__device__ __forceinline__ uint32_t smem_u32(const void* p) {
    uint32_t a;
    asm("{ .reg .u64 t; cvta.to.shared.u64 t, %1; cvt.u32.u64 %0, t; }" : "=r"(a) : "l"(p));
    return a;
}
// fp16 MMA
__device__ __forceinline__ void mma16816h(float* c, const uint32_t* a, const uint32_t* b) {
    asm volatile(
        "mma.sync.aligned.m16n8k16.row.col.f32.f16.f16.f32 "
        "{%0,%1,%2,%3}, {%4,%5,%6,%7}, {%8,%9}, {%0,%1,%2,%3};"
        : "+f"(c[0]), "+f"(c[1]), "+f"(c[2]), "+f"(c[3])
        : "r"(a[0]), "r"(a[1]), "r"(a[2]), "r"(a[3]), "r"(b[0]), "r"(b[1]));
}
// bf16 MMA (flash)
__device__ __forceinline__ void mma16816(float* c, const uint32_t* a, const uint32_t* b) {
    asm volatile(
        "mma.sync.aligned.m16n8k16.row.col.f32.bf16.bf16.f32 "
        "{%0,%1,%2,%3}, {%4,%5,%6,%7}, {%8,%9}, {%0,%1,%2,%3};"
        : "+f"(c[0]), "+f"(c[1]), "+f"(c[2]), "+f"(c[3])
        : "r"(a[0]), "r"(a[1]), "r"(a[2]), "r"(a[3]), "r"(b[0]), "r"(b[1]));
}
__device__ __forceinline__ void ldsm4(uint32_t* r, uint32_t addr) {
    asm volatile("ldmatrix.sync.aligned.m8n8.x4.shared.b16 {%0,%1,%2,%3}, [%4];"
        : "=r"(r[0]), "=r"(r[1]), "=r"(r[2]), "=r"(r[3]) : "r"(addr));
}
__device__ __forceinline__ void ldsm2(uint32_t* r, uint32_t addr) {
    asm volatile("ldmatrix.sync.aligned.m8n8.x2.shared.b16 {%0,%1}, [%2];"
        : "=r"(r[0]), "=r"(r[1]) : "r"(addr));
}
__device__ __forceinline__ void cpasync16(uint32_t dst, const void* src) {
    asm volatile("cp.async.cg.shared.global [%0], [%1], 16;" :: "r"(dst), "l"(src));
}
// bf16 hi/lo pack (flash P split)
__device__ __forceinline__ void pack_hilo(float4 v, uint2& h, uint2& l) {
    __nv_bfloat16 h0 = __float2bfloat16(v.x);
    __nv_bfloat16 h1 = __float2bfloat16(v.y);
    __nv_bfloat16 h2 = __float2bfloat16(v.z);
    __nv_bfloat16 h3 = __float2bfloat16(v.w);
    __nv_bfloat16 l0 = __float2bfloat16(v.x - __bfloat162float(h0));
    __nv_bfloat16 l1 = __float2bfloat16(v.y - __bfloat162float(h1));
    __nv_bfloat16 l2 = __float2bfloat16(v.z - __bfloat162float(h2));
    __nv_bfloat16 l3 = __float2bfloat16(v.w - __bfloat162float(h3));
    __nv_bfloat162 H01(h0, h1), H23(h2, h3), L01(l0, l1), L23(l2, l3);
    h.x = *(uint32_t*)&H01; h.y = *(uint32_t*)&H23;
    l.x = *(uint32_t*)&L01; l.y = *(uint32_t*)&L23;
}
// fp16 hi/lo pack (activation planes)
__device__ __forceinline__ void pack_hilo_h(float4 v, uint2& h, uint2& l) {
    __half h0 = __float2half(v.x), h1 = __float2half(v.y);
    __half h2 = __float2half(v.z), h3 = __float2half(v.w);
    __half l0 = __float2half(v.x - __half2float(h0));
    __half l1 = __float2half(v.y - __half2float(h1));
    __half l2 = __float2half(v.z - __half2float(h2));
    __half l3 = __float2half(v.w - __half2float(h3));
    __half2 H01(h0, h1), H23(h2, h3), L01(l0, l1), L23(l2, l3);
    h.x = *(uint32_t*)&H01; h.y = *(uint32_t*)&H23;
    l.x = *(uint32_t*)&L01; l.y = *(uint32_t*)&L23;
}

// ---------------- conversion kernels ----------------------------------------
__global__ void cvt_h_k(const float* __restrict__ s, __half* __restrict__ d, int n) {
    int i = (blockIdx.x * 256 + threadIdx.x) * 4;
    if (i >= n) return;
    float4 v = *(const float4*)(s + i);
    __half2 a(__float2half(v.x), __float2half(v.y));
    __half2 b(__float2half(v.z), __float2half(v.w));
    uint2 u; u.x = *(uint32_t*)&a; u.y = *(uint32_t*)&b;
    *(uint2*)(d + i) = u;
}
// Wq/Wk/Wv [L,512,512] -> wqkv [L,1536,512] at rowbase
__global__ void cvt_qkv_h_k(const float* __restrict__ s, __half* __restrict__ d, int rowbase) {
    int i = (blockIdx.x * 256 + threadIdx.x) * 4;
    if (i >= L_ * D_ * D_) return;
    int layer = i >> 18;
    int rem = i & 262143;
    int row = rem >> 9, col = rem & 511;
    float4 v = *(const float4*)(s + i);
    __half2 a(__float2half(v.x), __float2half(v.y));
    __half2 b(__float2half(v.z), __float2half(v.w));
    uint2 u; u.x = *(uint32_t*)&a; u.y = *(uint32_t*)&b;
    *(uint2*)(d + (size_t)layer * NQKV * D_ + (size_t)(rowbase + row) * D_ + col) = u;
}
__global__ void cvt_hilo_h_k(const float* __restrict__ s,
                             __half* __restrict__ h, __half* __restrict__ l, int n) {
    int i = (blockIdx.x * 256 + threadIdx.x) * 4;
    if (i >= n) return;
    float4 v = *(const float4*)(s + i);
    uint2 hh, ll;
    pack_hilo_h(v, hh, ll);
    *(uint2*)(h + i) = hh;
    *(uint2*)(l + i) = ll;
}
__global__ void stack_bias_k(const float* __restrict__ bq, const float* __restrict__ bk,
                             const float* __restrict__ bv, float* __restrict__ out) {
    int i = blockIdx.x * 256 + threadIdx.x;
    if (i >= L_ * NQKV) return;
    int layer = i / NQKV, c = i % NQKV;
    float v = (c < 512) ? bq[layer * 512 + c]
            : (c < 1024) ? bk[layer * 512 + c - 512]
                         : bv[layer * 512 + c - 1024];
    out[i] = v;
}

// ============================================================================
// fp16 2-term GEMM NT: C = (Ah+Al)[M,K] @ Bf[N,K]^T  ; 3-stage cp.async
// ============================================================================
#define GTS 40
#define GTILE_E (128*GTS)
#define GTILE_B (GTILE_E*2)        // 10240
#define GSTAGE_B (3*GTILE_B)       // 30720 (Ah, Al, Bf)
#define GSMEM_B (3*GSTAGE_B)       // 92160

__global__ void __launch_bounds__(256, 2) fp16_gemm_nt(
    int M, int N, int K,
    const __half* __restrict__ Ah, const __half* __restrict__ Al,
    const __half* __restrict__ Bf,
    const float* __restrict__ bias,
    float* __restrict__ outF, void* __restrict__ outH, void* __restrict__ outL,
    int outdt, int act) {
    extern __shared__ char smc[];
    uint32_t sb = smem_u32(smc);
    int tid = threadIdx.x, lane = tid & 31, wid = tid >> 5;
    int wm = wid & 1, wn = wid >> 1;
    int bm = blockIdx.y * 128, bn = blockIdx.x * 128;

    float acc[4][4][4];
    #pragma unroll
    for (int i = 0; i < 4; i++)
        #pragma unroll
        for (int j = 0; j < 4; j++)
            #pragma unroll
            for (int e = 0; e < 4; e++) acc[i][j][e] = 0.f;

    #define ISSUE(c) do {                                                      \
        int k0 = (c) * 32;                                                     \
        uint32_t dst = sb + ((c) % 3) * GSTAGE_B;                              \
        _Pragma("unroll")                                                      \
        for (int i = 0; i < 2; i++) {                                          \
            int seg = tid + i * 256;                                           \
            int row = seg >> 2, s4 = seg & 3;                                  \
            uint32_t off = (uint32_t)(row * GTS + s4 * 8) * 2;                 \
            cpasync16(dst + off,               Ah + (size_t)(bm + row) * K + k0 + s4 * 8); \
            cpasync16(dst + GTILE_B + off,     Al + (size_t)(bm + row) * K + k0 + s4 * 8); \
            cpasync16(dst + 2 * GTILE_B + off, Bf + (size_t)(bn + row) * K + k0 + s4 * 8); \
        }                                                                      \
        asm volatile("cp.async.commit_group;" ::: "memory");                   \
    } while (0)

    int nch = K >> 5;
    ISSUE(0); ISSUE(1); ISSUE(2);

    int a_r = wm * 64 + (lane & 15);
    int a_c = (lane >> 4) * 8;
    int b_r = wn * 32 + (lane & 7);
    int b_c = ((lane >> 3) & 1) * 8;

    for (int c = 0; c < nch; c++) {
        asm volatile("cp.async.wait_group 2;" ::: "memory");
        __syncthreads();
        uint32_t rbase = sb + (c % 3) * GSTAGE_B;
        #pragma unroll
        for (int ks = 0; ks < 2; ks++) {
            uint32_t af[4][4], bf[4][2];
            #pragma unroll
            for (int nt = 0; nt < 4; nt++)
                ldsm2(bf[nt], rbase + 2 * GTILE_B + ((b_r + nt * 8) * GTS + ks * 16 + b_c) * 2);
            #pragma unroll
            for (int mt = 0; mt < 4; mt++)
                ldsm4(af[mt], rbase + ((a_r + mt * 16) * GTS + ks * 16 + a_c) * 2);
            #pragma unroll
            for (int mt = 0; mt < 4; mt++)
                #pragma unroll
                for (int nt = 0; nt < 4; nt++)
                    mma16816h(acc[mt][nt], af[mt], bf[nt]);         // Ah*Bf
            #pragma unroll
            for (int mt = 0; mt < 4; mt++)
                ldsm4(af[mt], rbase + GTILE_B + ((a_r + mt * 16) * GTS + ks * 16 + a_c) * 2);
            #pragma unroll
            for (int mt = 0; mt < 4; mt++)
                #pragma unroll
                for (int nt = 0; nt < 4; nt++)
                    mma16816h(acc[mt][nt], af[mt], bf[nt]);         // Al*Bf
        }
        __syncthreads();
        if (c + 3 < nch) ISSUE(c + 3);
    }

    #pragma unroll
    for (int mt = 0; mt < 4; mt++) {
        int m0 = bm + wm * 64 + mt * 16 + (lane >> 2);
        #pragma unroll
        for (int nt = 0; nt < 4; nt++) {
            int col = bn + wn * 32 + nt * 8 + (lane & 3) * 2;
            float b0 = bias ? bias[col]     : 0.f;
            float b1 = bias ? bias[col + 1] : 0.f;
            float v0 = acc[mt][nt][0] + b0, v1 = acc[mt][nt][1] + b1;
            float v2 = acc[mt][nt][2] + b0, v3 = acc[mt][nt][3] + b1;
            if (act == 1) { v0 = gelu_f(v0); v1 = gelu_f(v1); v2 = gelu_f(v2); v3 = gelu_f(v3); }
            if (outF) {
                float2 p0; p0.x = v0; p0.y = v1;
                float2 p1; p1.x = v2; p1.y = v3;
                *(float2*)(outF + (size_t)m0 * N + col)       = p0;
                *(float2*)(outF + (size_t)(m0 + 8) * N + col) = p1;
            } else if (outdt == 1) {   // fp16 planes
                __half h0 = __float2half(v0), h1 = __float2half(v1);
                __half h2 = __float2half(v2), h3 = __float2half(v3);
                __half q0 = __float2half(v0 - __half2float(h0));
                __half q1 = __float2half(v1 - __half2float(h1));
                __half q2 = __float2half(v2 - __half2float(h2));
                __half q3 = __float2half(v3 - __half2float(h3));
                __half2 H01(h0, h1), H23(h2, h3), L01(q0, q1), L23(q2, q3);
                *(uint32_t*)((__half*)outH + (size_t)m0 * N + col)       = *(uint32_t*)&H01;
                *(uint32_t*)((__half*)outH + (size_t)(m0 + 8) * N + col) = *(uint32_t*)&H23;
                *(uint32_t*)((__half*)outL + (size_t)m0 * N + col)       = *(uint32_t*)&L01;
                *(uint32_t*)((__half*)outL + (size_t)(m0 + 8) * N + col) = *(uint32_t*)&L23;
            } else {                   // bf16 planes
                __nv_bfloat16 h0 = __float2bfloat16(v0), h1 = __float2bfloat16(v1);
                __nv_bfloat16 h2 = __float2bfloat16(v2), h3 = __float2bfloat16(v3);
                __nv_bfloat16 q0 = __float2bfloat16(v0 - __bfloat162float(h0));
                __nv_bfloat16 q1 = __float2bfloat16(v1 - __bfloat162float(h1));
                __nv_bfloat16 q2 = __float2bfloat16(v2 - __bfloat162float(h2));
                __nv_bfloat16 q3 = __float2bfloat16(v3 - __bfloat162float(h3));
                __nv_bfloat162 H01(h0, h1), H23(h2, h3), L01(q0, q1), L23(q2, q3);
                *(uint32_t*)((__nv_bfloat16*)outH + (size_t)m0 * N + col)       = *(uint32_t*)&H01;
                *(uint32_t*)((__nv_bfloat16*)outH + (size_t)(m0 + 8) * N + col) = *(uint32_t*)&H23;
                *(uint32_t*)((__nv_bfloat16*)outL + (size_t)m0 * N + col)       = *(uint32_t*)&L01;
                *(uint32_t*)((__nv_bfloat16*)outL + (size_t)(m0 + 8) * N + col) = *(uint32_t*)&L23;
            }
        }
    }
    #undef ISSUE
}

// ============================================================================
// Fused flash attention (bf16x3 on tensor cores) — ctx out as fp16 planes
// ============================================================================
#define FTS 72
#define FQH 0
#define FQL (64*FTS)
#define FKH (2*64*FTS)
#define FKL (3*64*FTS)
#define FVH (4*64*FTS)
#define FVL (5*64*FTS)
#define FMASK_B (6*64*FTS*2)
#define FSMEM_B (FMASK_B + 64*4)

__global__ void __launch_bounds__(128) flash_attn_k(
    const __nv_bfloat16* __restrict__ qkvh, const __nv_bfloat16* __restrict__ qkvl,
    const int* __restrict__ mask,
    __half* __restrict__ ctxh, __half* __restrict__ ctxl) {
    extern __shared__ char sm[];
    __nv_bfloat16* sb = (__nv_bfloat16*)sm;
    float* maskadd = (float*)(sm + FMASK_B);
    uint32_t sbase = smem_u32(sm);
    int tid = threadIdx.x, lane = tid & 31, w = tid >> 5;
    int bh = blockIdx.y, b = bh >> 3, h = bh & 7;
    int i0 = blockIdx.x * 64;

    #pragma unroll
    for (int i = 0; i < 4; i++) {
        int lin = i * 128 + tid;
        int r = lin >> 3, c8 = lin & 7;
        int gr = i0 + r; if (gr >= SEQ_) gr = SEQ_ - 1;
        size_t base = (size_t)(b * SEQ_ + gr) * NQKV + h * 64 + c8 * 8;
        *(uint4*)(sb + FQH + r * FTS + c8 * 8) = *(const uint4*)(qkvh + base);
        *(uint4*)(sb + FQL + r * FTS + c8 * 8) = *(const uint4*)(qkvl + base);
    }

    float m0 = -INFINITY, m1 = -INFINITY, l0 = 0.f, l1 = 0.f;
    float O[8][4];
    #pragma unroll
    for (int nt = 0; nt < 8; nt++)
        #pragma unroll
        for (int e = 0; e < 4; e++) O[nt][e] = 0.f;

    int a_r = w * 16 + (lane & 15);
    int a_c = (lane >> 4) * 8;
    int b_r = lane & 7;
    int b_c = ((lane >> 3) & 1) * 8;
    int g = lane >> 2;

    for (int j0 = 0; j0 < 960; j0 += 64) {
        #pragma unroll
        for (int i = 0; i < 4; i++) {
            int lin = i * 128 + tid;
            int r = lin >> 3, c8 = lin & 7;
            int gr = j0 + r; if (gr >= SEQ_) gr = SEQ_ - 1;
            size_t base = (size_t)(b * SEQ_ + gr) * NQKV + h * 64 + c8 * 8;
            *(uint4*)(sb + FKH + r * FTS + c8 * 8) = *(const uint4*)(qkvh + base + 512);
            *(uint4*)(sb + FKL + r * FTS + c8 * 8) = *(const uint4*)(qkvl + base + 512);
            uint4 vh4 = *(const uint4*)(qkvh + base + 1024);
            uint4 vl4 = *(const uint4*)(qkvl + base + 1024);
            const __nv_bfloat16* ph = (const __nv_bfloat16*)&vh4;
            const __nv_bfloat16* pl = (const __nv_bfloat16*)&vl4;
            int d0 = c8 * 8;
            #pragma unroll
            for (int u = 0; u < 8; u++) {
                sb[FVH + (d0 + u) * FTS + r] = ph[u];
                sb[FVL + (d0 + u) * FTS + r] = pl[u];
            }
        }
        if (tid < 64) {
            int j = j0 + tid;
            maskadd[tid] = (j >= SEQ_) ? -INFINITY
                          : (mask[b * SEQ_ + j] == 0 ? -1e9f : 0.f);
        }
        __syncthreads();

        float S[8][4];
        #pragma unroll
        for (int nt = 0; nt < 8; nt++)
            #pragma unroll
            for (int e = 0; e < 4; e++) S[nt][e] = 0.f;
        #pragma unroll
        for (int kc = 0; kc < 4; kc++) {
            uint32_t aqh[4], aql[4];
            ldsm4(aqh, sbase + (FQH + a_r * FTS + kc * 16 + a_c) * 2);
            ldsm4(aql, sbase + (FQL + a_r * FTS + kc * 16 + a_c) * 2);
            #pragma unroll
            for (int nt = 0; nt < 8; nt++) {
                uint32_t bkh[2], bkl[2];
                ldsm2(bkh, sbase + (FKH + (nt * 8 + b_r) * FTS + kc * 16 + b_c) * 2);
                ldsm2(bkl, sbase + (FKL + (nt * 8 + b_r) * FTS + kc * 16 + b_c) * 2);
                mma16816(S[nt], aqh, bkh);
                mma16816(S[nt], aqh, bkl);
                mma16816(S[nt], aql, bkh);
            }
        }
        #pragma unroll
        for (int nt = 0; nt < 8; nt++) {
            int col = nt * 8 + (lane & 3) * 2;
            float ma0 = maskadd[col], ma1 = maskadd[col + 1];
            S[nt][0] = fmaf(S[nt][0], 0.125f, ma0);
            S[nt][1] = fmaf(S[nt][1], 0.125f, ma1);
            S[nt][2] = fmaf(S[nt][2], 0.125f, ma0);
            S[nt][3] = fmaf(S[nt][3], 0.125f, ma1);
        }
        float rm0 = -INFINITY, rm1 = -INFINITY;
        #pragma unroll
        for (int nt = 0; nt < 8; nt++) {
            rm0 = fmaxf(rm0, fmaxf(S[nt][0], S[nt][1]));
            rm1 = fmaxf(rm1, fmaxf(S[nt][2], S[nt][3]));
        }
        rm0 = fmaxf(rm0, __shfl_xor_sync(~0u, rm0, 1));
        rm0 = fmaxf(rm0, __shfl_xor_sync(~0u, rm0, 2));
        rm1 = fmaxf(rm1, __shfl_xor_sync(~0u, rm1, 1));
        rm1 = fmaxf(rm1, __shfl_xor_sync(~0u, rm1, 2));
        float nm0 = fmaxf(m0, rm0), nm1 = fmaxf(m1, rm1);
        float f0 = expf(m0 - nm0), f1 = expf(m1 - nm1);
        m0 = nm0; m1 = nm1;
        float s0 = 0.f, s1 = 0.f;
        #pragma unroll
        for (int nt = 0; nt < 8; nt++) {
            S[nt][0] = expf(S[nt][0] - m0);
            S[nt][1] = expf(S[nt][1] - m0);
            S[nt][2] = expf(S[nt][2] - m1);
            S[nt][3] = expf(S[nt][3] - m1);
            s0 += S[nt][0] + S[nt][1];
            s1 += S[nt][2] + S[nt][3];
        }
        s0 += __shfl_xor_sync(~0u, s0, 1);
        s0 += __shfl_xor_sync(~0u, s0, 2);
        s1 += __shfl_xor_sync(~0u, s1, 1);
        s1 += __shfl_xor_sync(~0u, s1, 2);
        l0 = l0 * f0 + s0;
        l1 = l1 * f1 + s1;
        #pragma unroll
        for (int nt = 0; nt < 8; nt++) {
            O[nt][0] *= f0; O[nt][1] *= f0;
            O[nt][2] *= f1; O[nt][3] *= f1;
        }
        #pragma unroll
        for (int kc = 0; kc < 4; kc++) {
            uint2 h0, l0r, h1, l1r;
            pack_hilo(make_float4(S[2*kc][0], S[2*kc][1], S[2*kc][2], S[2*kc][3]), h0, l0r);
            pack_hilo(make_float4(S[2*kc+1][0], S[2*kc+1][1], S[2*kc+1][2], S[2*kc+1][3]), h1, l1r);
            uint32_t aph[4] = { h0.x, h0.y, h1.x, h1.y };
            uint32_t apl[4] = { l0r.x, l0r.y, l1r.x, l1r.y };
            #pragma unroll
            for (int nt = 0; nt < 8; nt++) {
                uint32_t bvh[2], bvl[2];
                ldsm2(bvh, sbase + (FVH + (nt * 8 + b_r) * FTS + kc * 16 + b_c) * 2);
                ldsm2(bvl, sbase + (FVL + (nt * 8 + b_r) * FTS + kc * 16 + b_c) * 2);
                mma16816(O[nt], aph, bvh);
                mma16816(O[nt], aph, bvl);
                mma16816(O[nt], apl, bvh);
            }
        }
        __syncthreads();
    }

    float inv0 = 1.f / l0, inv1 = 1.f / l1;
    int r0 = i0 + w * 16 + g, r1 = r0 + 8;
    #pragma unroll
    for (int nt = 0; nt < 8; nt++) {
        int d = h * DH_ + nt * 8 + (lane & 3) * 2;
        if (r0 < SEQ_) {
            float v0 = O[nt][0] * inv0, v1 = O[nt][1] * inv0;
            __half h0 = __float2half(v0), h1 = __float2half(v1);
            __half q0 = __float2half(v0 - __half2float(h0));
            __half q1 = __float2half(v1 - __half2float(h1));
            __half2 Hh(h0, h1), Lw(q0, q1);
            *(uint32_t*)(ctxh + (size_t)(b * SEQ_ + r0) * D_ + d) = *(uint32_t*)&Hh;
            *(uint32_t*)(ctxl + (size_t)(b * SEQ_ + r0) * D_ + d) = *(uint32_t*)&Lw;
        }
        if (r1 < SEQ_) {
            float v0 = O[nt][2] * inv1, v1 = O[nt][3] * inv1;
            __half h0 = __float2half(v0), h1 = __float2half(v1);
            __half q0 = __float2half(v0 - __half2float(h0));
            __half q1 = __float2half(v1 - __half2float(h1));
            __half2 Hh(h0, h1), Lw(q0, q1);
            *(uint32_t*)(ctxh + (size_t)(b * SEQ_ + r1) * D_ + d) = *(uint32_t*)&Hh;
            *(uint32_t*)(ctxl + (size_t)(b * SEQ_ + r1) * D_ + d) = *(uint32_t*)&Lw;
        }
    }
}

// ---------------- gather: feat [B,CIN,HW] -> xin fp16 planes ----------------
__global__ void gather_transpose_k(const float* __restrict__ feat, int HW, int t0,
                                   __half* __restrict__ xh, __half* __restrict__ xl) {
    __shared__ float tile[32][33];
    int b   = blockIdx.z;
    int hw0 = blockIdx.x * 32, c0 = blockIdx.y * 32;
    const float* fb = feat + (size_t)b * CIN_ * HW;
    #pragma unroll
    for (int kk = 0; kk < 32; kk += 8) {
        int c  = c0 + threadIdx.y + kk;
        int hw = hw0 + threadIdx.x;
        tile[threadIdx.y + kk][threadIdx.x] = (hw < HW) ? fb[(size_t)c * HW + hw] : 0.f;
    }
    __syncthreads();
    #pragma unroll
    for (int kk = 0; kk < 32; kk += 8) {
        int hw = hw0 + threadIdx.y + kk;
        int c  = c0 + threadIdx.x;
        if (hw < HW) {
            float v = tile[threadIdx.x][threadIdx.y + kk];
            __half h = __float2half(v);
            __half l = __float2half(v - __half2float(h));
            size_t idx = ((size_t)b * SEQ_ + t0 + hw) * CIN_ + c;
            xh[idx] = h; xl[idx] = l;
        }
    }
}

__global__ void zero_xin_row0_k(__half* __restrict__ xh, __half* __restrict__ xl) {
    int idx = blockIdx.x * 256 + threadIdx.x;
    if (idx >= B_ * CIN_) return;
    int b = idx / CIN_, c = idx % CIN_;
    size_t o = (size_t)b * SEQ_ * CIN_ + c;
    xh[o] = __float2half(0.f);
    xl[o] = __float2half(0.f);
}

// ---------------- embed epilogue --------------------------------------------
__global__ void embed_add_k(const float* __restrict__ conv_b,
                            const float* __restrict__ e_org,
                            const float* __restrict__ e_r1,
                            const float* __restrict__ e_r2,
                            const float* __restrict__ pos,
                            float* __restrict__ x) {
    int idx = blockIdx.x * 256 + threadIdx.x;
    const int total = B_ * 911 * D_;
    if (idx >= total) return;
    int d = idx & 511;
    int rest = idx >> 9;
    int tt = rest % 911;
    int b  = rest / 911;
    int ti, tj; const float* ce;
    if (tt < 768)      { int hh = tt >> 5,  ww = tt & 31;  ce = e_org; ti = hh*GRIDN/24; tj = ww*GRIDN/32; }
    else if (tt < 876) { int u = tt - 768;  int hh = u/12, ww = u%12; ce = e_r1; ti = hh*GRIDN/9;  tj = ww*GRIDN/12; }
    else               { int u = tt - 876;  int hh = u/7,  ww = u%7;  ce = e_r2; ti = hh*GRIDN/5;  tj = ww*GRIDN/7;  }
    x[((size_t)(b * SEQ_ + tt + 1)) * D_ + d] += conv_b[d] + ce[d] + pos[(size_t)(ti * GRIDN + tj) * D_ + d];
}

__global__ void cls_set_k(const float* __restrict__ c, float* __restrict__ x) {
    int idx = blockIdx.x * 256 + threadIdx.x;
    if (idx >= B_ * D_) return;
    int b = idx >> 9, d = idx & 511;
    x[(size_t)b * SEQ_ * D_ + d] = c[d];
}

// ---------------- residual + LayerNorm (emits fp16 planes) ------------------
__global__ __launch_bounds__(128) void add_ln_k(
    const float* __restrict__ xin, const float* __restrict__ add,
    const float* __restrict__ g, const float* __restrict__ beta,
    float* __restrict__ xout, __half* __restrict__ xh, __half* __restrict__ xl) {
    __shared__ float red[4];
    __shared__ float bval;
    int row = blockIdx.x, tid = threadIdx.x;
    float4 xv = ((const float4*)(xin + (size_t)row * D_))[tid];
    float4 av = ((const float4*)(add + (size_t)row * D_))[tid];
    float4 s;
    s.x = xv.x + av.x; s.y = xv.y + av.y; s.z = xv.z + av.z; s.w = xv.w + av.w;
    float sum = s.x + s.y + s.z + s.w;
    #pragma unroll
    for (int o = 16; o > 0; o >>= 1) sum += __shfl_xor_sync(~0u, sum, o);
    if ((tid & 31) == 0) red[tid >> 5] = sum;
    __syncthreads();
    if (tid == 0) bval = (red[0] + red[1] + red[2] + red[3]) * (1.f / D_);
    __syncthreads();
    float m = bval;
    float d0 = s.x - m, d1 = s.y - m, d2 = s.z - m, d3 = s.w - m;
    float sq = d0 * d0 + d1 * d1 + d2 * d2 + d3 * d3;
    #pragma unroll
    for (int o = 16; o > 0; o >>= 1) sq += __shfl_xor_sync(~0u, sq, o);
    __syncthreads();
    if ((tid & 31) == 0) red[tid >> 5] = sq;
    __syncthreads();
    if (tid == 0) bval = rsqrtf((red[0] + red[1] + red[2] + red[3]) * (1.f / D_) + 1e-6f);
    __syncthreads();
    float rs = bval;
    float4 gv = ((const float4*)g)[tid];
    float4 bv = ((const float4*)beta)[tid];
    float4 o;
    o.x = d0 * rs * gv.x + bv.x; o.y = d1 * rs * gv.y + bv.y;
    o.z = d2 * rs * gv.z + bv.z; o.w = d3 * rs * gv.w + bv.w;
    ((float4*)(xout + (size_t)row * D_))[tid] = o;
    uint2 hh, ll;
    pack_hilo_h(o, hh, ll);
    *(uint2*)(xh + (size_t)row * D_ + tid * 4) = hh;
    *(uint2*)(xl + (size_t)row * D_ + tid * 4) = ll;
}

// ---------------- head ------------------------------------------------------
__global__ __launch_bounds__(256) void head_mlp_k(
    const float* __restrict__ x, const float* __restrict__ w1,
    float* __restrict__ hm) {
    __shared__ float cls[512];
    int b = blockIdx.x;
    for (int d = threadIdx.x; d < 512; d += 256) cls[d] = x[(size_t)b * SEQ_ * D_ + d];
    __syncthreads();
    for (int n = threadIdx.x; n < DMLP_; n += 256) {
        const float* w = w1 + (size_t)n * 512;
        float s = 0.f;
        for (int d = 0; d < 512; d++) s += cls[d] * w[d];
        hm[b * DMLP_ + n] = gelu_f(s);
    }
}

__global__ __launch_bounds__(256) void head_out_k(
    const float* __restrict__ hm, const float* __restrict__ w2,
    float* __restrict__ out) {
    __shared__ float red[8];
    int b = blockIdx.x, tid = threadIdx.x;
    float s = 0.f;
    for (int n = tid; n < DMLP_; n += 256) s += hm[b * DMLP_ + n] * w2[n];
    #pragma unroll
    for (int o = 16; o > 0; o >>= 1) s += __shfl_xor_sync(~0u, s, o);
    if ((tid & 31) == 0) red[tid >> 5] = s;
    __syncthreads();
    if (tid == 0) {
        float t = 0; for (int w = 0; w < 8; w++) t += red[w];
        out[b] = t;
    }
}

// ---------------- host orchestration ----------------------------------------
extern "C" void kernel_launch(void* const* d_in, const int* in_sizes, int n_in,
                              void* d_out, int out_size) {
    const float* feat_org = (const float*)d_in[0];
    const float* feat_r1  = (const float*)d_in[1];
    const float* feat_r2  = (const float*)d_in[2];
    const float* conv_w   = (const float*)d_in[3];
    const float* conv_b   = (const float*)d_in[4];
    const float* e_org    = (const float*)d_in[5];
    const float* e_r1     = (const float*)d_in[6];
    const float* e_r2     = (const float*)d_in[7];
    const float* pos      = (const float*)d_in[8];
    const float* cls_tok  = (const float*)d_in[9];
    const float* Wq = (const float*)d_in[10]; const float* bq = (const float*)d_in[11];
    const float* Wk = (const float*)d_in[12]; const float* bk = (const float*)d_in[13];
    const float* Wv = (const float*)d_in[14]; const float* bv = (const float*)d_in[15];
    const float* Wo = (const float*)d_in[16]; const float* bo = (const float*)d_in[17];
    const float* ln1g = (const float*)d_in[18]; const float* ln1b = (const float*)d_in[19];
    const float* w1 = (const float*)d_in[20]; const float* b1 = (const float*)d_in[21];
    const float* w2 = (const float*)d_in[22]; const float* b2 = (const float*)d_in[23];
    const float* ln2g = (const float*)d_in[24]; const float* ln2b = (const float*)d_in[25];
    const float* pw1 = (const float*)d_in[26]; const float* pw2 = (const float*)d_in[27];
    const int*   mask = (const int*)d_in[28];

    __half *wconv, *wqkv, *wo, *w1h, *w2h, *xinh, *xinl, *xh, *xl, *ctxh, *ctxl, *h1h, *h1l;
    __nv_bfloat16 *qkvh, *qkvl;
    float *x, *att, *bqkv, *hmlp;
    cudaGetSymbolAddress((void**)&wconv, g_wconv);
    cudaGetSymbolAddress((void**)&wqkv, g_wqkv);
    cudaGetSymbolAddress((void**)&wo, g_wo);
    cudaGetSymbolAddress((void**)&w1h, g_w1);
    cudaGetSymbolAddress((void**)&w2h, g_w2);
    cudaGetSymbolAddress((void**)&xinh, g_xinh);
    cudaGetSymbolAddress((void**)&xinl, g_xinl);
    cudaGetSymbolAddress((void**)&xh, g_xh);
    cudaGetSymbolAddress((void**)&xl, g_xl);
    cudaGetSymbolAddress((void**)&qkvh, g_qkvh);
    cudaGetSymbolAddress((void**)&qkvl, g_qkvl);
    cudaGetSymbolAddress((void**)&ctxh, g_ctxh);
    cudaGetSymbolAddress((void**)&ctxl, g_ctxl);
    cudaGetSymbolAddress((void**)&h1h, g_h1h);
    cudaGetSymbolAddress((void**)&h1l, g_h1l);
    cudaGetSymbolAddress((void**)&x, g_x);
    cudaGetSymbolAddress((void**)&att, g_att);
    cudaGetSymbolAddress((void**)&bqkv, g_bqkv);
    cudaGetSymbolAddress((void**)&hmlp, g_hmlp);

    cudaFuncSetAttribute(fp16_gemm_nt, cudaFuncAttributeMaxDynamicSharedMemorySize, GSMEM_B);
    cudaFuncSetAttribute(flash_attn_k, cudaFuncAttributeMaxDynamicSharedMemorySize, FSMEM_B);

    // ---- weight conversions (7 kernels, whole [L,...] tensors) ----
    cvt_h_k<<<(D_*CIN_/4 + 255)/256, 256>>>(conv_w, wconv, D_*CIN_);
    cvt_qkv_h_k<<<(L_*D_*D_/4 + 255)/256, 256>>>(Wq, wqkv, 0);
    cvt_qkv_h_k<<<(L_*D_*D_/4 + 255)/256, 256>>>(Wk, wqkv, 512);
    cvt_qkv_h_k<<<(L_*D_*D_/4 + 255)/256, 256>>>(Wv, wqkv, 1024);
    cvt_h_k<<<(L_*D_*D_/4 + 255)/256, 256>>>(Wo, wo, L_*D_*D_);
    cvt_h_k<<<(L_*DFF_*D_/4 + 255)/256, 256>>>(w1, w1h, L_*DFF_*D_);
    cvt_h_k<<<(L_*D_*DFF_/4 + 255)/256, 256>>>(w2, w2h, L_*D_*DFF_);
    stack_bias_k<<<(L_*NQKV + 255)/256, 256>>>(bq, bk, bv, bqkv);

    // ---- embed ----
    dim3 tb32(32, 8);
    gather_transpose_k<<<dim3(24, CIN_ / 32, B_), tb32>>>(feat_org, 768, 1,   xinh, xinl);
    gather_transpose_k<<<dim3(4,  CIN_ / 32, B_), tb32>>>(feat_r1,  108, 769, xinh, xinl);
    gather_transpose_k<<<dim3(2,  CIN_ / 32, B_), tb32>>>(feat_r2,  35,  877, xinh, xinl);
    zero_xin_row0_k<<<(B_*CIN_ + 255)/256, 256>>>(xinh, xinl);

    fp16_gemm_nt<<<dim3(4, 57), 256, GSMEM_B>>>(M_, D_, CIN_, xinh, xinl, wconv,
        nullptr, x, nullptr, nullptr, 0, 0);
    embed_add_k<<<(B_ * 911 * D_ + 255) / 256, 256>>>(conv_b, e_org, e_r1, e_r2, pos, x);
    cls_set_k<<<(B_ * D_ + 255) / 256, 256>>>(cls_tok, x);
    cvt_hilo_h_k<<<(M_*D_/4 + 255)/256, 256>>>(x, xh, xl, M_*D_);

    for (int i = 0; i < L_; i++) {
        fp16_gemm_nt<<<dim3(12, 57), 256, GSMEM_B>>>(M_, NQKV, D_, xh, xl,
            wqkv + (size_t)i*NQKV*D_, bqkv + i*NQKV, nullptr, qkvh, qkvl, 2, 0);

        flash_attn_k<<<dim3(15, B_ * H_), 128, FSMEM_B>>>(qkvh, qkvl, mask, ctxh, ctxl);

        fp16_gemm_nt<<<dim3(4, 57), 256, GSMEM_B>>>(M_, D_, D_, ctxh, ctxl,
            wo + (size_t)i*D_*D_, bo + i*D_, att, nullptr, nullptr, 0, 0);
        add_ln_k<<<M_, 128>>>(x, att, ln1g + i*D_, ln1b + i*D_, x, xh, xl);

        fp16_gemm_nt<<<dim3(16, 57), 256, GSMEM_B>>>(M_, DFF_, D_, xh, xl,
            w1h + (size_t)i*DFF_*D_, b1 + i*DFF_, nullptr, h1h, h1l, 1, 1);
        fp16_gemm_nt<<<dim3(4, 57), 256, GSMEM_B>>>(M_, D_, DFF_, h1h, h1l,
            w2h + (size_t)i*D_*DFF_, b2 + i*D_, att, nullptr, nullptr, 0, 0);
        add_ln_k<<<M_, 128>>>(x, att, ln2g + i*D_, ln2b + i*D_, x, xh, xl);
    }

    head_mlp_k<<<B_, 256>>>(x, pw1, hmlp);
    head_out_k<<<B_, 256>>>(hmlp, pw2, (float*)d_out);
}

// round 7
// speedup vs baseline: 3.7957x; 1.0928x over previous
#include <cuda_runtime.h>
#include <cuda_bf16.h>
#include <cuda_fp16.h>
#include <math.h>
#include <cstdint>

// ---------------- problem constants ----------------
#define B_    8
#define D_    512
#define H_    8
#define DH_   64
#define L_    6
#define DFF_  2048
#define GRIDN 10
#define DMLP_ 1024
#define CIN_  2048
#define SEQ_  912
#define M_    (B_*SEQ_)    // 7296
#define NQKV  1536

// ---------------- scratch ----------------
__device__ __half g_wconv[D_*CIN_];
__device__ __half g_wqkv [L_*NQKV*D_];
__device__ __half g_wo   [L_*D_*D_];
__device__ __half g_w1   [L_*DFF_*D_];
__device__ __half g_w2   [L_*D_*DFF_];
__device__ __half g_xinh[M_*CIN_];
__device__ __half g_xinl[M_*CIN_];
__device__ __half g_xh[M_*D_];
__device__ __half g_xl[M_*D_];
__device__ __nv_bfloat16 g_qkvh[(size_t)M_*NQKV];
__device__ __nv_bfloat16 g_qkvl[(size_t)M_*NQKV];
__device__ __half g_ctxh[M_*D_];
__device__ __half g_ctxl[M_*D_];
__device__ __half g_h1h[M_*DFF_];
__device__ __half g_h1l[M_*DFF_];
__device__ float g_x  [M_*D_];
__device__ float g_att[M_*D_];
__device__ float g_bqkv[L_*NQKV];
__device__ float g_hmlp[B_*DMLP_];

__device__ __forceinline__ float gelu_f(float x) {
    return 0.5f * x * (1.0f + erff(x * 0.70710678118654752f));
}
__device__ __forceinline__ uint32_t smem_u32(const void* p) {
    uint32_t a;
    asm("{ .reg .u64 t; cvta.to.shared.u64 t, %1; cvt.u32.u64 %0, t; }" : "=r"(a) : "l"(p));
    return a;
}
__device__ __forceinline__ void mma16816h(float* c, const uint32_t* a, const uint32_t* b) {
    asm volatile(
        "mma.sync.aligned.m16n8k16.row.col.f32.f16.f16.f32 "
        "{%0,%1,%2,%3}, {%4,%5,%6,%7}, {%8,%9}, {%0,%1,%2,%3};"
        : "+f"(c[0]), "+f"(c[1]), "+f"(c[2]), "+f"(c[3])
        : "r"(a[0]), "r"(a[1]), "r"(a[2]), "r"(a[3]), "r"(b[0]), "r"(b[1]));
}
__device__ __forceinline__ void mma16816(float* c, const uint32_t* a, const uint32_t* b) {
    asm volatile(
        "mma.sync.aligned.m16n8k16.row.col.f32.bf16.bf16.f32 "
        "{%0,%1,%2,%3}, {%4,%5,%6,%7}, {%8,%9}, {%0,%1,%2,%3};"
        : "+f"(c[0]), "+f"(c[1]), "+f"(c[2]), "+f"(c[3])
        : "r"(a[0]), "r"(a[1]), "r"(a[2]), "r"(a[3]), "r"(b[0]), "r"(b[1]));
}
__device__ __forceinline__ void ldsm4(uint32_t* r, uint32_t addr) {
    asm volatile("ldmatrix.sync.aligned.m8n8.x4.shared.b16 {%0,%1,%2,%3}, [%4];"
        : "=r"(r[0]), "=r"(r[1]), "=r"(r[2]), "=r"(r[3]) : "r"(addr));
}
__device__ __forceinline__ void ldsm2(uint32_t* r, uint32_t addr) {
    asm volatile("ldmatrix.sync.aligned.m8n8.x2.shared.b16 {%0,%1}, [%2];"
        : "=r"(r[0]), "=r"(r[1]) : "r"(addr));
}
__device__ __forceinline__ void cpasync16(uint32_t dst, const void* src) {
    asm volatile("cp.async.cg.shared.global [%0], [%1], 16;" :: "r"(dst), "l"(src));
}
__device__ __forceinline__ void pack_hilo(float4 v, uint2& h, uint2& l) {
    __nv_bfloat16 h0 = __float2bfloat16(v.x);
    __nv_bfloat16 h1 = __float2bfloat16(v.y);
    __nv_bfloat16 h2 = __float2bfloat16(v.z);
    __nv_bfloat16 h3 = __float2bfloat16(v.w);
    __nv_bfloat16 l0 = __float2bfloat16(v.x - __bfloat162float(h0));
    __nv_bfloat16 l1 = __float2bfloat16(v.y - __bfloat162float(h1));
    __nv_bfloat16 l2 = __float2bfloat16(v.z - __bfloat162float(h2));
    __nv_bfloat16 l3 = __float2bfloat16(v.w - __bfloat162float(h3));
    __nv_bfloat162 H01(h0, h1), H23(h2, h3), L01(l0, l1), L23(l2, l3);
    h.x = *(uint32_t*)&H01; h.y = *(uint32_t*)&H23;
    l.x = *(uint32_t*)&L01; l.y = *(uint32_t*)&L23;
}
__device__ __forceinline__ void pack_hilo_h(float4 v, uint2& h, uint2& l) {
    __half h0 = __float2half(v.x), h1 = __float2half(v.y);
    __half h2 = __float2half(v.z), h3 = __float2half(v.w);
    __half l0 = __float2half(v.x - __half2float(h0));
    __half l1 = __float2half(v.y - __half2float(h1));
    __half l2 = __float2half(v.z - __half2float(h2));
    __half l3 = __float2half(v.w - __half2float(h3));
    __half2 H01(h0, h1), H23(h2, h3), L01(l0, l1), L23(l2, l3);
    h.x = *(uint32_t*)&H01; h.y = *(uint32_t*)&H23;
    l.x = *(uint32_t*)&L01; l.y = *(uint32_t*)&L23;
}

// ============================================================================
// mega weight conversion: all weights fp32 -> fp16 (+ qkv stack + bias stack)
// vec4 region table (units of float4):
//   conv [0,262144) | Wq [262144,655360) | Wk [655360,1048576)
//   Wv [1048576,1441792) | Wo [1441792,1835008)
//   w1 [1835008,3407872) | w2 [3407872,4980736)
// blocks >= 19456 handle bias stacking (scalar)
// ============================================================================
__device__ __forceinline__ void cvt4(const float* s, long e, __half* d, long de) {
    float4 v = *(const float4*)(s + e);
    __half2 a(__float2half(v.x), __float2half(v.y));
    __half2 b(__float2half(v.z), __float2half(v.w));
    uint2 u; u.x = *(uint32_t*)&a; u.y = *(uint32_t*)&b;
    *(uint2*)(d + de) = u;
}
__global__ void cvt_all_k(const float* __restrict__ conv_w,
                          const float* __restrict__ Wq, const float* __restrict__ Wk,
                          const float* __restrict__ Wv, const float* __restrict__ Wo,
                          const float* __restrict__ w1, const float* __restrict__ w2,
                          const float* __restrict__ bq, const float* __restrict__ bk,
                          const float* __restrict__ bv,
                          __half* __restrict__ wconv, __half* __restrict__ wqkv,
                          __half* __restrict__ wo, __half* __restrict__ w1h,
                          __half* __restrict__ w2h, float* __restrict__ bqkv) {
    long vb = blockIdx.x;
    int tid = threadIdx.x;
    if (vb >= 19456) {
        int i = (int)(vb - 19456) * 256 + tid;
        if (i < L_ * NQKV) {
            int layer = i / NQKV, c = i % NQKV;
            float v = (c < 512) ? bq[layer * 512 + c]
                    : (c < 1024) ? bk[layer * 512 + c - 512]
                                 : bv[layer * 512 + c - 1024];
            bqkv[i] = v;
        }
        return;
    }
    long v = vb * 256 + tid;
    if (v < 262144) {
        long e = v * 4;
        cvt4(conv_w, e, wconv, e);
    } else if (v < 1441792) {
        const float* src; int rowbase; long e;
        if (v < 655360)      { src = Wq; rowbase = 0;    e = (v - 262144) * 4; }
        else if (v < 1048576){ src = Wk; rowbase = 512;  e = (v - 655360) * 4; }
        else                 { src = Wv; rowbase = 1024; e = (v - 1048576) * 4; }
        long layer = e >> 18;
        long rem = e & 262143;
        long row = rem >> 9, col = rem & 511;
        cvt4(src, e, wqkv, layer * NQKV * D_ + (rowbase + row) * D_ + col);
    } else if (v < 1835008) {
        long e = (v - 1441792) * 4;
        cvt4(Wo, e, wo, e);
    } else if (v < 3407872) {
        long e = (v - 1835008) * 4;
        cvt4(w1, e, w1h, e);
    } else {
        long e = (v - 3407872) * 4;
        cvt4(w2, e, w2h, e);
    }
}

// ============================================================================
// fp16 2-term GEMM NT: C = (Ah+Al)[M,K] @ Bf[N,K]^T  ; 3-stage cp.async
// ============================================================================
#define GTS 40
#define GTILE_E (128*GTS)
#define GTILE_B (GTILE_E*2)
#define GSTAGE_B (3*GTILE_B)
#define GSMEM_B (3*GSTAGE_B)

__global__ void __launch_bounds__(256, 2) fp16_gemm_nt(
    int M, int N, int K,
    const __half* __restrict__ Ah, const __half* __restrict__ Al,
    const __half* __restrict__ Bf,
    const float* __restrict__ bias,
    float* __restrict__ outF, void* __restrict__ outH, void* __restrict__ outL,
    int outdt, int act) {
    extern __shared__ char smc[];
    uint32_t sb = smem_u32(smc);
    int tid = threadIdx.x, lane = tid & 31, wid = tid >> 5;
    int wm = wid & 1, wn = wid >> 1;
    int bm = blockIdx.y * 128, bn = blockIdx.x * 128;

    float acc[4][4][4];
    #pragma unroll
    for (int i = 0; i < 4; i++)
        #pragma unroll
        for (int j = 0; j < 4; j++)
            #pragma unroll
            for (int e = 0; e < 4; e++) acc[i][j][e] = 0.f;

    #define ISSUE(c) do {                                                      \
        int k0 = (c) * 32;                                                     \
        uint32_t dst = sb + ((c) % 3) * GSTAGE_B;                              \
        _Pragma("unroll")                                                      \
        for (int i = 0; i < 2; i++) {                                          \
            int seg = tid + i * 256;                                           \
            int row = seg >> 2, s4 = seg & 3;                                  \
            uint32_t off = (uint32_t)(row * GTS + s4 * 8) * 2;                 \
            cpasync16(dst + off,               Ah + (size_t)(bm + row) * K + k0 + s4 * 8); \
            cpasync16(dst + GTILE_B + off,     Al + (size_t)(bm + row) * K + k0 + s4 * 8); \
            cpasync16(dst + 2 * GTILE_B + off, Bf + (size_t)(bn + row) * K + k0 + s4 * 8); \
        }                                                                      \
        asm volatile("cp.async.commit_group;" ::: "memory");                   \
    } while (0)

    int nch = K >> 5;
    ISSUE(0); ISSUE(1); ISSUE(2);

    int a_r = wm * 64 + (lane & 15);
    int a_c = (lane >> 4) * 8;
    int b_r = wn * 32 + (lane & 7);
    int b_c = ((lane >> 3) & 1) * 8;

    for (int c = 0; c < nch; c++) {
        asm volatile("cp.async.wait_group 2;" ::: "memory");
        __syncthreads();
        uint32_t rbase = sb + (c % 3) * GSTAGE_B;
        #pragma unroll
        for (int ks = 0; ks < 2; ks++) {
            uint32_t af[4][4], bf[4][2];
            #pragma unroll
            for (int nt = 0; nt < 4; nt++)
                ldsm2(bf[nt], rbase + 2 * GTILE_B + ((b_r + nt * 8) * GTS + ks * 16 + b_c) * 2);
            #pragma unroll
            for (int mt = 0; mt < 4; mt++)
                ldsm4(af[mt], rbase + ((a_r + mt * 16) * GTS + ks * 16 + a_c) * 2);
            #pragma unroll
            for (int mt = 0; mt < 4; mt++)
                #pragma unroll
                for (int nt = 0; nt < 4; nt++)
                    mma16816h(acc[mt][nt], af[mt], bf[nt]);
            #pragma unroll
            for (int mt = 0; mt < 4; mt++)
                ldsm4(af[mt], rbase + GTILE_B + ((a_r + mt * 16) * GTS + ks * 16 + a_c) * 2);
            #pragma unroll
            for (int mt = 0; mt < 4; mt++)
                #pragma unroll
                for (int nt = 0; nt < 4; nt++)
                    mma16816h(acc[mt][nt], af[mt], bf[nt]);
        }
        __syncthreads();
        if (c + 3 < nch) ISSUE(c + 3);
    }

    #pragma unroll
    for (int mt = 0; mt < 4; mt++) {
        int m0 = bm + wm * 64 + mt * 16 + (lane >> 2);
        #pragma unroll
        for (int nt = 0; nt < 4; nt++) {
            int col = bn + wn * 32 + nt * 8 + (lane & 3) * 2;
            float b0 = bias ? bias[col]     : 0.f;
            float b1 = bias ? bias[col + 1] : 0.f;
            float v0 = acc[mt][nt][0] + b0, v1 = acc[mt][nt][1] + b1;
            float v2 = acc[mt][nt][2] + b0, v3 = acc[mt][nt][3] + b1;
            if (act == 1) { v0 = gelu_f(v0); v1 = gelu_f(v1); v2 = gelu_f(v2); v3 = gelu_f(v3); }
            if (outF) {
                float2 p0; p0.x = v0; p0.y = v1;
                float2 p1; p1.x = v2; p1.y = v3;
                *(float2*)(outF + (size_t)m0 * N + col)       = p0;
                *(float2*)(outF + (size_t)(m0 + 8) * N + col) = p1;
            } else if (outdt == 1) {
                __half h0 = __float2half(v0), h1 = __float2half(v1);
                __half h2 = __float2half(v2), h3 = __float2half(v3);
                __half q0 = __float2half(v0 - __half2float(h0));
                __half q1 = __float2half(v1 - __half2float(h1));
                __half q2 = __float2half(v2 - __half2float(h2));
                __half q3 = __float2half(v3 - __half2float(h3));
                __half2 H01(h0, h1), H23(h2, h3), L01(q0, q1), L23(q2, q3);
                *(uint32_t*)((__half*)outH + (size_t)m0 * N + col)       = *(uint32_t*)&H01;
                *(uint32_t*)((__half*)outH + (size_t)(m0 + 8) * N + col) = *(uint32_t*)&H23;
                *(uint32_t*)((__half*)outL + (size_t)m0 * N + col)       = *(uint32_t*)&L01;
                *(uint32_t*)((__half*)outL + (size_t)(m0 + 8) * N + col) = *(uint32_t*)&L23;
            } else {
                __nv_bfloat16 h0 = __float2bfloat16(v0), h1 = __float2bfloat16(v1);
                __nv_bfloat16 h2 = __float2bfloat16(v2), h3 = __float2bfloat16(v3);
                __nv_bfloat16 q0 = __float2bfloat16(v0 - __bfloat162float(h0));
                __nv_bfloat16 q1 = __float2bfloat16(v1 - __bfloat162float(h1));
                __nv_bfloat16 q2 = __float2bfloat16(v2 - __bfloat162float(h2));
                __nv_bfloat16 q3 = __float2bfloat16(v3 - __bfloat162float(h3));
                __nv_bfloat162 H01(h0, h1), H23(h2, h3), L01(q0, q1), L23(q2, q3);
                *(uint32_t*)((__nv_bfloat16*)outH + (size_t)m0 * N + col)       = *(uint32_t*)&H01;
                *(uint32_t*)((__nv_bfloat16*)outH + (size_t)(m0 + 8) * N + col) = *(uint32_t*)&H23;
                *(uint32_t*)((__nv_bfloat16*)outL + (size_t)m0 * N + col)       = *(uint32_t*)&L01;
                *(uint32_t*)((__nv_bfloat16*)outL + (size_t)(m0 + 8) * N + col) = *(uint32_t*)&L23;
            }
        }
    }
    #undef ISSUE
}

// ============================================================================
// Fused flash attention (bf16x3) — V smem XOR-swizzled (conflict-free stores)
// V element (d, j) stored at: FV? + d*FTS + (j ^ ((d>>3)<<3))
// ============================================================================
#define FTS 72
#define FQH 0
#define FQL (64*FTS)
#define FKH (2*64*FTS)
#define FKL (3*64*FTS)
#define FVH (4*64*FTS)
#define FVL (5*64*FTS)
#define FMASK_B (6*64*FTS*2)
#define FSMEM_B (FMASK_B + 64*4)

__global__ void __launch_bounds__(128) flash_attn_k(
    const __nv_bfloat16* __restrict__ qkvh, const __nv_bfloat16* __restrict__ qkvl,
    const int* __restrict__ mask,
    __half* __restrict__ ctxh, __half* __restrict__ ctxl) {
    extern __shared__ char sm[];
    __nv_bfloat16* sb = (__nv_bfloat16*)sm;
    float* maskadd = (float*)(sm + FMASK_B);
    uint32_t sbase = smem_u32(sm);
    int tid = threadIdx.x, lane = tid & 31, w = tid >> 5;
    int bh = blockIdx.y, b = bh >> 3, h = bh & 7;
    int i0 = blockIdx.x * 64;

    #pragma unroll
    for (int i = 0; i < 4; i++) {
        int lin = i * 128 + tid;
        int r = lin >> 3, c8 = lin & 7;
        int gr = i0 + r; if (gr >= SEQ_) gr = SEQ_ - 1;
        size_t base = (size_t)(b * SEQ_ + gr) * NQKV + h * 64 + c8 * 8;
        *(uint4*)(sb + FQH + r * FTS + c8 * 8) = *(const uint4*)(qkvh + base);
        *(uint4*)(sb + FQL + r * FTS + c8 * 8) = *(const uint4*)(qkvl + base);
    }

    float m0 = -INFINITY, m1 = -INFINITY, l0 = 0.f, l1 = 0.f;
    float O[8][4];
    #pragma unroll
    for (int nt = 0; nt < 8; nt++)
        #pragma unroll
        for (int e = 0; e < 4; e++) O[nt][e] = 0.f;

    int a_r = w * 16 + (lane & 15);
    int a_c = (lane >> 4) * 8;
    int b_r = lane & 7;
    int b_c = ((lane >> 3) & 1) * 8;
    int g = lane >> 2;

    for (int j0 = 0; j0 < 960; j0 += 64) {
        #pragma unroll
        for (int i = 0; i < 4; i++) {
            int lin = i * 128 + tid;
            int r = lin >> 3, c8 = lin & 7;
            int gr = j0 + r; if (gr >= SEQ_) gr = SEQ_ - 1;
            size_t base = (size_t)(b * SEQ_ + gr) * NQKV + h * 64 + c8 * 8;
            *(uint4*)(sb + FKH + r * FTS + c8 * 8) = *(const uint4*)(qkvh + base + 512);
            *(uint4*)(sb + FKL + r * FTS + c8 * 8) = *(const uint4*)(qkvl + base + 512);
            uint4 vh4 = *(const uint4*)(qkvh + base + 1024);
            uint4 vl4 = *(const uint4*)(qkvl + base + 1024);
            const __nv_bfloat16* ph = (const __nv_bfloat16*)&vh4;
            const __nv_bfloat16* pl = (const __nv_bfloat16*)&vl4;
            int d0 = c8 * 8;
            int rs = r ^ (c8 << 3);    // swizzled j coordinate (c8 == d>>3 here)
            #pragma unroll
            for (int u = 0; u < 8; u++) {
                sb[FVH + (d0 + u) * FTS + rs] = ph[u];
                sb[FVL + (d0 + u) * FTS + rs] = pl[u];
            }
        }
        if (tid < 64) {
            int j = j0 + tid;
            maskadd[tid] = (j >= SEQ_) ? -INFINITY
                          : (mask[b * SEQ_ + j] == 0 ? -1e9f : 0.f);
        }
        __syncthreads();

        float S[8][4];
        #pragma unroll
        for (int nt = 0; nt < 8; nt++)
            #pragma unroll
            for (int e = 0; e < 4; e++) S[nt][e] = 0.f;
        #pragma unroll
        for (int kc = 0; kc < 4; kc++) {
            uint32_t aqh[4], aql[4];
            ldsm4(aqh, sbase + (FQH + a_r * FTS + kc * 16 + a_c) * 2);
            ldsm4(aql, sbase + (FQL + a_r * FTS + kc * 16 + a_c) * 2);
            #pragma unroll
            for (int nt = 0; nt < 8; nt++) {
                uint32_t bkh[2], bkl[2];
                ldsm2(bkh, sbase + (FKH + (nt * 8 + b_r) * FTS + kc * 16 + b_c) * 2);
                ldsm2(bkl, sbase + (FKL + (nt * 8 + b_r) * FTS + kc * 16 + b_c) * 2);
                mma16816(S[nt], aqh, bkh);
                mma16816(S[nt], aqh, bkl);
                mma16816(S[nt], aql, bkh);
            }
        }
        #pragma unroll
        for (int nt = 0; nt < 8; nt++) {
            int col = nt * 8 + (lane & 3) * 2;
            float ma0 = maskadd[col], ma1 = maskadd[col + 1];
            S[nt][0] = fmaf(S[nt][0], 0.125f, ma0);
            S[nt][1] = fmaf(S[nt][1], 0.125f, ma1);
            S[nt][2] = fmaf(S[nt][2], 0.125f, ma0);
            S[nt][3] = fmaf(S[nt][3], 0.125f, ma1);
        }
        float rm0 = -INFINITY, rm1 = -INFINITY;
        #pragma unroll
        for (int nt = 0; nt < 8; nt++) {
            rm0 = fmaxf(rm0, fmaxf(S[nt][0], S[nt][1]));
            rm1 = fmaxf(rm1, fmaxf(S[nt][2], S[nt][3]));
        }
        rm0 = fmaxf(rm0, __shfl_xor_sync(~0u, rm0, 1));
        rm0 = fmaxf(rm0, __shfl_xor_sync(~0u, rm0, 2));
        rm1 = fmaxf(rm1, __shfl_xor_sync(~0u, rm1, 1));
        rm1 = fmaxf(rm1, __shfl_xor_sync(~0u, rm1, 2));
        float nm0 = fmaxf(m0, rm0), nm1 = fmaxf(m1, rm1);
        float f0 = expf(m0 - nm0), f1 = expf(m1 - nm1);
        m0 = nm0; m1 = nm1;
        float s0 = 0.f, s1 = 0.f;
        #pragma unroll
        for (int nt = 0; nt < 8; nt++) {
            S[nt][0] = expf(S[nt][0] - m0);
            S[nt][1] = expf(S[nt][1] - m0);
            S[nt][2] = expf(S[nt][2] - m1);
            S[nt][3] = expf(S[nt][3] - m1);
            s0 += S[nt][0] + S[nt][1];
            s1 += S[nt][2] + S[nt][3];
        }
        s0 += __shfl_xor_sync(~0u, s0, 1);
        s0 += __shfl_xor_sync(~0u, s0, 2);
        s1 += __shfl_xor_sync(~0u, s1, 1);
        s1 += __shfl_xor_sync(~0u, s1, 2);
        l0 = l0 * f0 + s0;
        l1 = l1 * f1 + s1;
        #pragma unroll
        for (int nt = 0; nt < 8; nt++) {
            O[nt][0] *= f0; O[nt][1] *= f0;
            O[nt][2] *= f1; O[nt][3] *= f1;
        }
        #pragma unroll
        for (int kc = 0; kc < 4; kc++) {
            uint2 h0, l0r, h1, l1r;
            pack_hilo(make_float4(S[2*kc][0], S[2*kc][1], S[2*kc][2], S[2*kc][3]), h0, l0r);
            pack_hilo(make_float4(S[2*kc+1][0], S[2*kc+1][1], S[2*kc+1][2], S[2*kc+1][3]), h1, l1r);
            uint32_t aph[4] = { h0.x, h0.y, h1.x, h1.y };
            uint32_t apl[4] = { l0r.x, l0r.y, l1r.x, l1r.y };
            #pragma unroll
            for (int nt = 0; nt < 8; nt++) {
                // swizzled read: j block (kc*16 + b_c) XORed by nt (== d>>3, uniform)
                uint32_t vaddr = sbase + ((nt * 8 + b_r) * FTS + ((kc * 16 + b_c) ^ (nt << 3))) * 2;
                uint32_t bvh[2], bvl[2];
                ldsm2(bvh, vaddr + FVH * 2);
                ldsm2(bvl, vaddr + FVL * 2);
                mma16816(O[nt], aph, bvh);
                mma16816(O[nt], aph, bvl);
                mma16816(O[nt], apl, bvh);
            }
        }
        __syncthreads();
    }

    float inv0 = 1.f / l0, inv1 = 1.f / l1;
    int r0 = i0 + w * 16 + g, r1 = r0 + 8;
    #pragma unroll
    for (int nt = 0; nt < 8; nt++) {
        int d = h * DH_ + nt * 8 + (lane & 3) * 2;
        if (r0 < SEQ_) {
            float v0 = O[nt][0] * inv0, v1 = O[nt][1] * inv0;
            __half h0 = __float2half(v0), h1 = __float2half(v1);
            __half q0 = __float2half(v0 - __half2float(h0));
            __half q1 = __float2half(v1 - __half2float(h1));
            __half2 Hh(h0, h1), Lw(q0, q1);
            *(uint32_t*)(ctxh + (size_t)(b * SEQ_ + r0) * D_ + d) = *(uint32_t*)&Hh;
            *(uint32_t*)(ctxl + (size_t)(b * SEQ_ + r0) * D_ + d) = *(uint32_t*)&Lw;
        }
        if (r1 < SEQ_) {
            float v0 = O[nt][2] * inv1, v1 = O[nt][3] * inv1;
            __half h0 = __float2half(v0), h1 = __float2half(v1);
            __half q0 = __float2half(v0 - __half2float(h0));
            __half q1 = __float2half(v1 - __half2float(h1));
            __half2 Hh(h0, h1), Lw(q0, q1);
            *(uint32_t*)(ctxh + (size_t)(b * SEQ_ + r1) * D_ + d) = *(uint32_t*)&Hh;
            *(uint32_t*)(ctxl + (size_t)(b * SEQ_ + r1) * D_ + d) = *(uint32_t*)&Lw;
        }
    }
}

// ---------------- gather: feat [B,CIN,HW] -> xin fp16 planes ----------------
__global__ void gather_transpose_k(const float* __restrict__ feat, int HW, int t0,
                                   __half* __restrict__ xh, __half* __restrict__ xl) {
    __shared__ float tile[32][33];
    int b   = blockIdx.z;
    int hw0 = blockIdx.x * 32, c0 = blockIdx.y * 32;
    const float* fb = feat + (size_t)b * CIN_ * HW;
    #pragma unroll
    for (int kk = 0; kk < 32; kk += 8) {
        int c  = c0 + threadIdx.y + kk;
        int hw = hw0 + threadIdx.x;
        tile[threadIdx.y + kk][threadIdx.x] = (hw < HW) ? fb[(size_t)c * HW + hw] : 0.f;
    }
    __syncthreads();
    #pragma unroll
    for (int kk = 0; kk < 32; kk += 8) {
        int hw = hw0 + threadIdx.y + kk;
        int c  = c0 + threadIdx.x;
        if (hw < HW) {
            float v = tile[threadIdx.x][threadIdx.y + kk];
            __half h = __float2half(v);
            __half l = __float2half(v - __half2float(h));
            size_t idx = ((size_t)b * SEQ_ + t0 + hw) * CIN_ + c;
            xh[idx] = h; xl[idx] = l;
        }
    }
}

__global__ void zero_xin_row0_k(__half* __restrict__ xh, __half* __restrict__ xl) {
    int idx = blockIdx.x * 256 + threadIdx.x;
    if (idx >= B_ * CIN_) return;
    int b = idx / CIN_, c = idx % CIN_;
    size_t o = (size_t)b * SEQ_ * CIN_ + c;
    xh[o] = __float2half(0.f);
    xl[o] = __float2half(0.f);
}

// ---------------- embed epilogue (also emits x fp16 planes) -----------------
__global__ void embed_add_k(const float* __restrict__ conv_b,
                            const float* __restrict__ e_org,
                            const float* __restrict__ e_r1,
                            const float* __restrict__ e_r2,
                            const float* __restrict__ pos,
                            float* __restrict__ x,
                            __half* __restrict__ xh, __half* __restrict__ xl) {
    int idx = blockIdx.x * 256 + threadIdx.x;
    const int total = B_ * 911 * D_;
    if (idx >= total) return;
    int d = idx & 511;
    int rest = idx >> 9;
    int tt = rest % 911;
    int b  = rest / 911;
    int ti, tj; const float* ce;
    if (tt < 768)      { int hh = tt >> 5,  ww = tt & 31;  ce = e_org; ti = hh*GRIDN/24; tj = ww*GRIDN/32; }
    else if (tt < 876) { int u = tt - 768;  int hh = u/12, ww = u%12; ce = e_r1; ti = hh*GRIDN/9;  tj = ww*GRIDN/12; }
    else               { int u = tt - 876;  int hh = u/7,  ww = u%7;  ce = e_r2; ti = hh*GRIDN/5;  tj = ww*GRIDN/7;  }
    size_t o = ((size_t)(b * SEQ_ + tt + 1)) * D_ + d;
    float v = x[o] + conv_b[d] + ce[d] + pos[(size_t)(ti * GRIDN + tj) * D_ + d];
    x[o] = v;
    __half h = __float2half(v);
    __half l = __float2half(v - __half2float(h));
    xh[o] = h; xl[o] = l;
}

__global__ void cls_set_k(const float* __restrict__ c, float* __restrict__ x,
                          __half* __restrict__ xh, __half* __restrict__ xl) {
    int idx = blockIdx.x * 256 + threadIdx.x;
    if (idx >= B_ * D_) return;
    int b = idx >> 9, d = idx & 511;
    size_t o = (size_t)b * SEQ_ * D_ + d;
    float v = c[d];
    x[o] = v;
    __half h = __float2half(v);
    __half l = __float2half(v - __half2float(h));
    xh[o] = h; xl[o] = l;
}

// ---------------- residual + LayerNorm (emits fp16 planes) ------------------
__global__ __launch_bounds__(128) void add_ln_k(
    const float* __restrict__ xin, const float* __restrict__ add,
    const float* __restrict__ g, const float* __restrict__ beta,
    float* __restrict__ xout, __half* __restrict__ xh, __half* __restrict__ xl) {
    __shared__ float red[4];
    __shared__ float bval;
    int row = blockIdx.x, tid = threadIdx.x;
    float4 xv = ((const float4*)(xin + (size_t)row * D_))[tid];
    float4 av = ((const float4*)(add + (size_t)row * D_))[tid];
    float4 s;
    s.x = xv.x + av.x; s.y = xv.y + av.y; s.z = xv.z + av.z; s.w = xv.w + av.w;
    float sum = s.x + s.y + s.z + s.w;
    #pragma unroll
    for (int o = 16; o > 0; o >>= 1) sum += __shfl_xor_sync(~0u, sum, o);
    if ((tid & 31) == 0) red[tid >> 5] = sum;
    __syncthreads();
    if (tid == 0) bval = (red[0] + red[1] + red[2] + red[3]) * (1.f / D_);
    __syncthreads();
    float m = bval;
    float d0 = s.x - m, d1 = s.y - m, d2 = s.z - m, d3 = s.w - m;
    float sq = d0 * d0 + d1 * d1 + d2 * d2 + d3 * d3;
    #pragma unroll
    for (int o = 16; o > 0; o >>= 1) sq += __shfl_xor_sync(~0u, sq, o);
    __syncthreads();
    if ((tid & 31) == 0) red[tid >> 5] = sq;
    __syncthreads();
    if (tid == 0) bval = rsqrtf((red[0] + red[1] + red[2] + red[3]) * (1.f / D_) + 1e-6f);
    __syncthreads();
    float rs = bval;
    float4 gv = ((const float4*)g)[tid];
    float4 bv = ((const float4*)beta)[tid];
    float4 o;
    o.x = d0 * rs * gv.x + bv.x; o.y = d1 * rs * gv.y + bv.y;
    o.z = d2 * rs * gv.z + bv.z; o.w = d3 * rs * gv.w + bv.w;
    ((float4*)(xout + (size_t)row * D_))[tid] = o;
    uint2 hh, ll;
    pack_hilo_h(o, hh, ll);
    *(uint2*)(xh + (size_t)row * D_ + tid * 4) = hh;
    *(uint2*)(xl + (size_t)row * D_ + tid * 4) = ll;
}

// ---------------- head ------------------------------------------------------
__global__ __launch_bounds__(256) void head_mlp_k(
    const float* __restrict__ x, const float* __restrict__ w1,
    float* __restrict__ hm) {
    __shared__ float cls[512];
    int b = blockIdx.x;
    for (int d = threadIdx.x; d < 512; d += 256) cls[d] = x[(size_t)b * SEQ_ * D_ + d];
    __syncthreads();
    for (int n = threadIdx.x; n < DMLP_; n += 256) {
        const float* w = w1 + (size_t)n * 512;
        float s = 0.f;
        for (int d = 0; d < 512; d++) s += cls[d] * w[d];
        hm[b * DMLP_ + n] = gelu_f(s);
    }
}

__global__ __launch_bounds__(256) void head_out_k(
    const float* __restrict__ hm, const float* __restrict__ w2,
    float* __restrict__ out) {
    __shared__ float red[8];
    int b = blockIdx.x, tid = threadIdx.x;
    float s = 0.f;
    for (int n = tid; n < DMLP_; n += 256) s += hm[b * DMLP_ + n] * w2[n];
    #pragma unroll
    for (int o = 16; o > 0; o >>= 1) s += __shfl_xor_sync(~0u, s, o);
    if ((tid & 31) == 0) red[tid >> 5] = s;
    __syncthreads();
    if (tid == 0) {
        float t = 0; for (int w = 0; w < 8; w++) t += red[w];
        out[b] = t;
    }
}

// ---------------- host orchestration ----------------------------------------
extern "C" void kernel_launch(void* const* d_in, const int* in_sizes, int n_in,
                              void* d_out, int out_size) {
    const float* feat_org = (const float*)d_in[0];
    const float* feat_r1  = (const float*)d_in[1];
    const float* feat_r2  = (const float*)d_in[2];
    const float* conv_w   = (const float*)d_in[3];
    const float* conv_b   = (const float*)d_in[4];
    const float* e_org    = (const float*)d_in[5];
    const float* e_r1     = (const float*)d_in[6];
    const float* e_r2     = (const float*)d_in[7];
    const float* pos      = (const float*)d_in[8];
    const float* cls_tok  = (const float*)d_in[9];
    const float* Wq = (const float*)d_in[10]; const float* bq = (const float*)d_in[11];
    const float* Wk = (const float*)d_in[12]; const float* bk = (const float*)d_in[13];
    const float* Wv = (const float*)d_in[14]; const float* bv = (const float*)d_in[15];
    const float* Wo = (const float*)d_in[16]; const float* bo = (const float*)d_in[17];
    const float* ln1g = (const float*)d_in[18]; const float* ln1b = (const float*)d_in[19];
    const float* w1 = (const float*)d_in[20]; const float* b1 = (const float*)d_in[21];
    const float* w2 = (const float*)d_in[22]; const float* b2 = (const float*)d_in[23];
    const float* ln2g = (const float*)d_in[24]; const float* ln2b = (const float*)d_in[25];
    const float* pw1 = (const float*)d_in[26]; const float* pw2 = (const float*)d_in[27];
    const int*   mask = (const int*)d_in[28];

    __half *wconv, *wqkv, *wo, *w1h, *w2h, *xinh, *xinl, *xh, *xl, *ctxh, *ctxl, *h1h, *h1l;
    __nv_bfloat16 *qkvh, *qkvl;
    float *x, *att, *bqkv, *hmlp;
    cudaGetSymbolAddress((void**)&wconv, g_wconv);
    cudaGetSymbolAddress((void**)&wqkv, g_wqkv);
    cudaGetSymbolAddress((void**)&wo, g_wo);
    cudaGetSymbolAddress((void**)&w1h, g_w1);
    cudaGetSymbolAddress((void**)&w2h, g_w2);
    cudaGetSymbolAddress((void**)&xinh, g_xinh);
    cudaGetSymbolAddress((void**)&xinl, g_xinl);
    cudaGetSymbolAddress((void**)&xh, g_xh);
    cudaGetSymbolAddress((void**)&xl, g_xl);
    cudaGetSymbolAddress((void**)&qkvh, g_qkvh);
    cudaGetSymbolAddress((void**)&qkvl, g_qkvl);
    cudaGetSymbolAddress((void**)&ctxh, g_ctxh);
    cudaGetSymbolAddress((void**)&ctxl, g_ctxl);
    cudaGetSymbolAddress((void**)&h1h, g_h1h);
    cudaGetSymbolAddress((void**)&h1l, g_h1l);
    cudaGetSymbolAddress((void**)&x, g_x);
    cudaGetSymbolAddress((void**)&att, g_att);
    cudaGetSymbolAddress((void**)&bqkv, g_bqkv);
    cudaGetSymbolAddress((void**)&hmlp, g_hmlp);

    cudaFuncSetAttribute(fp16_gemm_nt, cudaFuncAttributeMaxDynamicSharedMemorySize, GSMEM_B);
    cudaFuncSetAttribute(flash_attn_k, cudaFuncAttributeMaxDynamicSharedMemorySize, FSMEM_B);

    // launches 0-4 (so launch idx 5 = embed GEMM for ncu -s 5)
    dim3 tb32(32, 8);
    gather_transpose_k<<<dim3(24, CIN_ / 32, B_), tb32>>>(feat_org, 768, 1,   xinh, xinl);
    gather_transpose_k<<<dim3(4,  CIN_ / 32, B_), tb32>>>(feat_r1,  108, 769, xinh, xinl);
    gather_transpose_k<<<dim3(2,  CIN_ / 32, B_), tb32>>>(feat_r2,  35,  877, xinh, xinl);
    zero_xin_row0_k<<<(B_*CIN_ + 255)/256, 256>>>(xinh, xinl);
    cvt_all_k<<<19456 + 36, 256>>>(conv_w, Wq, Wk, Wv, Wo, w1, w2, bq, bk, bv,
                                   wconv, wqkv, wo, w1h, w2h, bqkv);

    fp16_gemm_nt<<<dim3(4, 57), 256, GSMEM_B>>>(M_, D_, CIN_, xinh, xinl, wconv,
        nullptr, x, nullptr, nullptr, 0, 0);
    embed_add_k<<<(B_ * 911 * D_ + 255) / 256, 256>>>(conv_b, e_org, e_r1, e_r2, pos, x, xh, xl);
    cls_set_k<<<(B_ * D_ + 255) / 256, 256>>>(cls_tok, x, xh, xl);

    for (int i = 0; i < L_; i++) {
        fp16_gemm_nt<<<dim3(12, 57), 256, GSMEM_B>>>(M_, NQKV, D_, xh, xl,
            wqkv + (size_t)i*NQKV*D_, bqkv + i*NQKV, nullptr, qkvh, qkvl, 2, 0);

        flash_attn_k<<<dim3(15, B_ * H_), 128, FSMEM_B>>>(qkvh, qkvl, mask, ctxh, ctxl);

        fp16_gemm_nt<<<dim3(4, 57), 256, GSMEM_B>>>(M_, D_, D_, ctxh, ctxl,
            wo + (size_t)i*D_*D_, bo + i*D_, att, nullptr, nullptr, 0, 0);
        add_ln_k<<<M_, 128>>>(x, att, ln1g + i*D_, ln1b + i*D_, x, xh, xl);

        fp16_gemm_nt<<<dim3(16, 57), 256, GSMEM_B>>>(M_, DFF_, D_, xh, xl,
            w1h + (size_t)i*DFF_*D_, b1 + i*DFF_, nullptr, h1h, h1l, 1, 1);
        fp16_gemm_nt<<<dim3(4, 57), 256, GSMEM_B>>>(M_, D_, DFF_, h1h, h1l,
            w2h + (size_t)i*D_*DFF_, b2 + i*D_, att, nullptr, nullptr, 0, 0);
        add_ln_k<<<M_, 128>>>(x, att, ln2g + i*D_, ln2b + i*D_, x, xh, xl);
    }

    head_mlp_k<<<B_, 256>>>(x, pw1, hmlp);
    head_out_k<<<B_, 256>>>(hmlp, pw2, (float*)d_out);
}

// round 8
// speedup vs baseline: 4.0067x; 1.0556x over previous
#include <cuda_runtime.h>
#include <cuda_bf16.h>
#include <cuda_fp16.h>
#include <math.h>
#include <cstdint>

// ---------------- problem constants ----------------
#define B_    8
#define D_    512
#define H_    8
#define DH_   64
#define L_    6
#define DFF_  2048
#define GRIDN 10
#define DMLP_ 1024
#define CIN_  2048
#define SEQ_  912
#define M_    (B_*SEQ_)    // 7296
#define NQKV  1536

// ---------------- scratch ----------------
__device__ __half g_wconv[D_*CIN_];
__device__ __half g_wqkv [L_*NQKV*D_];
__device__ __half g_wo   [L_*D_*D_];
__device__ __half g_w1   [L_*DFF_*D_];
__device__ __half g_w2   [L_*D_*DFF_];
__device__ __half g_xinh[M_*CIN_];
__device__ __half g_xinl[M_*CIN_];
__device__ __half g_xh[M_*D_];
__device__ __half g_xl[M_*D_];
__device__ __nv_bfloat16 g_qkvh[(size_t)M_*NQKV];
__device__ __nv_bfloat16 g_qkvl[(size_t)M_*NQKV];
__device__ __half g_ctxh[M_*D_];
__device__ __half g_ctxl[M_*D_];
__device__ __half g_h1h[M_*DFF_];
__device__ __half g_h1l[M_*DFF_];
__device__ float g_x  [M_*D_];
__device__ float g_att[M_*D_];
__device__ float g_bqkv[L_*NQKV];
__device__ float g_hmlp[B_*DMLP_];

__device__ __forceinline__ float gelu_f(float x) {
    return 0.5f * x * (1.0f + erff(x * 0.70710678118654752f));
}
__device__ __forceinline__ uint32_t smem_u32(const void* p) {
    uint32_t a;
    asm("{ .reg .u64 t; cvta.to.shared.u64 t, %1; cvt.u32.u64 %0, t; }" : "=r"(a) : "l"(p));
    return a;
}
__device__ __forceinline__ void mma16816h(float* c, const uint32_t* a, const uint32_t* b) {
    asm volatile(
        "mma.sync.aligned.m16n8k16.row.col.f32.f16.f16.f32 "
        "{%0,%1,%2,%3}, {%4,%5,%6,%7}, {%8,%9}, {%0,%1,%2,%3};"
        : "+f"(c[0]), "+f"(c[1]), "+f"(c[2]), "+f"(c[3])
        : "r"(a[0]), "r"(a[1]), "r"(a[2]), "r"(a[3]), "r"(b[0]), "r"(b[1]));
}
__device__ __forceinline__ void mma16816(float* c, const uint32_t* a, const uint32_t* b) {
    asm volatile(
        "mma.sync.aligned.m16n8k16.row.col.f32.bf16.bf16.f32 "
        "{%0,%1,%2,%3}, {%4,%5,%6,%7}, {%8,%9}, {%0,%1,%2,%3};"
        : "+f"(c[0]), "+f"(c[1]), "+f"(c[2]), "+f"(c[3])
        : "r"(a[0]), "r"(a[1]), "r"(a[2]), "r"(a[3]), "r"(b[0]), "r"(b[1]));
}
__device__ __forceinline__ void ldsm4(uint32_t* r, uint32_t addr) {
    asm volatile("ldmatrix.sync.aligned.m8n8.x4.shared.b16 {%0,%1,%2,%3}, [%4];"
        : "=r"(r[0]), "=r"(r[1]), "=r"(r[2]), "=r"(r[3]) : "r"(addr));
}
__device__ __forceinline__ void ldsm2(uint32_t* r, uint32_t addr) {
    asm volatile("ldmatrix.sync.aligned.m8n8.x2.shared.b16 {%0,%1}, [%2];"
        : "=r"(r[0]), "=r"(r[1]) : "r"(addr));
}
__device__ __forceinline__ void cpasync16(uint32_t dst, const void* src) {
    asm volatile("cp.async.cg.shared.global [%0], [%1], 16;" :: "r"(dst), "l"(src));
}
__device__ __forceinline__ void pack_hilo(float4 v, uint2& h, uint2& l) {
    __nv_bfloat16 h0 = __float2bfloat16(v.x);
    __nv_bfloat16 h1 = __float2bfloat16(v.y);
    __nv_bfloat16 h2 = __float2bfloat16(v.z);
    __nv_bfloat16 h3 = __float2bfloat16(v.w);
    __nv_bfloat16 l0 = __float2bfloat16(v.x - __bfloat162float(h0));
    __nv_bfloat16 l1 = __float2bfloat16(v.y - __bfloat162float(h1));
    __nv_bfloat16 l2 = __float2bfloat16(v.z - __bfloat162float(h2));
    __nv_bfloat16 l3 = __float2bfloat16(v.w - __bfloat162float(h3));
    __nv_bfloat162 H01(h0, h1), H23(h2, h3), L01(l0, l1), L23(l2, l3);
    h.x = *(uint32_t*)&H01; h.y = *(uint32_t*)&H23;
    l.x = *(uint32_t*)&L01; l.y = *(uint32_t*)&L23;
}
__device__ __forceinline__ void pack_hilo_h(float4 v, uint2& h, uint2& l) {
    __half h0 = __float2half(v.x), h1 = __float2half(v.y);
    __half h2 = __float2half(v.z), h3 = __float2half(v.w);
    __half l0 = __float2half(v.x - __half2float(h0));
    __half l1 = __float2half(v.y - __half2float(h1));
    __half l2 = __float2half(v.z - __half2float(h2));
    __half l3 = __float2half(v.w - __half2float(h3));
    __half2 H01(h0, h1), H23(h2, h3), L01(l0, l1), L23(l2, l3);
    h.x = *(uint32_t*)&H01; h.y = *(uint32_t*)&H23;
    l.x = *(uint32_t*)&L01; l.y = *(uint32_t*)&L23;
}

// ============================================================================
// mega weight conversion (fp32 -> fp16, qkv stack, bias stack)
// ============================================================================
__device__ __forceinline__ void cvt4(const float* s, long e, __half* d, long de) {
    float4 v = *(const float4*)(s + e);
    __half2 a(__float2half(v.x), __float2half(v.y));
    __half2 b(__float2half(v.z), __float2half(v.w));
    uint2 u; u.x = *(uint32_t*)&a; u.y = *(uint32_t*)&b;
    *(uint2*)(d + de) = u;
}
__global__ void cvt_all_k(const float* __restrict__ conv_w,
                          const float* __restrict__ Wq, const float* __restrict__ Wk,
                          const float* __restrict__ Wv, const float* __restrict__ Wo,
                          const float* __restrict__ w1, const float* __restrict__ w2,
                          const float* __restrict__ bq, const float* __restrict__ bk,
                          const float* __restrict__ bv,
                          __half* __restrict__ wconv, __half* __restrict__ wqkv,
                          __half* __restrict__ wo, __half* __restrict__ w1h,
                          __half* __restrict__ w2h, float* __restrict__ bqkv) {
    long vb = blockIdx.x;
    int tid = threadIdx.x;
    if (vb >= 19456) {
        int i = (int)(vb - 19456) * 256 + tid;
        if (i < L_ * NQKV) {
            int layer = i / NQKV, c = i % NQKV;
            float v = (c < 512) ? bq[layer * 512 + c]
                    : (c < 1024) ? bk[layer * 512 + c - 512]
                                 : bv[layer * 512 + c - 1024];
            bqkv[i] = v;
        }
        return;
    }
    long v = vb * 256 + tid;
    if (v < 262144) {
        long e = v * 4;
        cvt4(conv_w, e, wconv, e);
    } else if (v < 1441792) {
        const float* src; int rowbase; long e;
        if (v < 655360)      { src = Wq; rowbase = 0;    e = (v - 262144) * 4; }
        else if (v < 1048576){ src = Wk; rowbase = 512;  e = (v - 655360) * 4; }
        else                 { src = Wv; rowbase = 1024; e = (v - 1048576) * 4; }
        long layer = e >> 18;
        long rem = e & 262143;
        long row = rem >> 9, col = rem & 511;
        cvt4(src, e, wqkv, layer * NQKV * D_ + (rowbase + row) * D_ + col);
    } else if (v < 1835008) {
        long e = (v - 1441792) * 4;
        cvt4(Wo, e, wo, e);
    } else if (v < 3407872) {
        long e = (v - 1835008) * 4;
        cvt4(w1, e, w1h, e);
    } else {
        long e = (v - 3407872) * 4;
        cvt4(w2, e, w2h, e);
    }
}

// ============================================================================
// fp16 2-term GEMM NT: C = (Ah+Al)[M,K] @ Bf[N,K]^T ; BK=64, 2-stage cp.async
// ============================================================================
#define GTS 72
#define GTILE_E (128*GTS)          // 9216 halves
#define GTILE_B (GTILE_E*2)        // 18432 B
#define GSTAGE_B (3*GTILE_B)       // 55296 B (Ah, Al, Bf)
#define GSMEM_B (2*GSTAGE_B)       // 110592 B

__global__ void __launch_bounds__(256, 2) fp16_gemm_nt(
    int M, int N, int K,
    const __half* __restrict__ Ah, const __half* __restrict__ Al,
    const __half* __restrict__ Bf,
    const float* __restrict__ bias,
    float* __restrict__ outF, void* __restrict__ outH, void* __restrict__ outL,
    int outdt, int act) {
    extern __shared__ char smc[];
    uint32_t sb = smem_u32(smc);
    int tid = threadIdx.x, lane = tid & 31, wid = tid >> 5;
    int wm = wid & 1, wn = wid >> 1;
    int bm = blockIdx.y * 128, bn = blockIdx.x * 128;

    float acc[4][4][4];
    #pragma unroll
    for (int i = 0; i < 4; i++)
        #pragma unroll
        for (int j = 0; j < 4; j++)
            #pragma unroll
            for (int e = 0; e < 4; e++) acc[i][j][e] = 0.f;

    #define ISSUE(c) do {                                                      \
        int k0 = (c) * 64;                                                     \
        uint32_t dst = sb + ((c) & 1) * GSTAGE_B;                              \
        _Pragma("unroll")                                                      \
        for (int i = 0; i < 4; i++) {                                          \
            int seg = tid + i * 256;                                           \
            int row = seg >> 3, s8 = seg & 7;                                  \
            uint32_t off = (uint32_t)(row * GTS + s8 * 8) * 2;                 \
            cpasync16(dst + off,               Ah + (size_t)(bm + row) * K + k0 + s8 * 8); \
            cpasync16(dst + GTILE_B + off,     Al + (size_t)(bm + row) * K + k0 + s8 * 8); \
            cpasync16(dst + 2 * GTILE_B + off, Bf + (size_t)(bn + row) * K + k0 + s8 * 8); \
        }                                                                      \
        asm volatile("cp.async.commit_group;" ::: "memory");                   \
    } while (0)

    int nch = K >> 6;
    ISSUE(0); ISSUE(1);

    int a_r = wm * 64 + (lane & 15);
    int a_c = (lane >> 4) * 8;
    int b_r = wn * 32 + (lane & 7);
    int b_c = ((lane >> 3) & 1) * 8;

    for (int c = 0; c < nch; c++) {
        asm volatile("cp.async.wait_group 1;" ::: "memory");
        __syncthreads();
        uint32_t rbase = sb + (c & 1) * GSTAGE_B;
        #pragma unroll
        for (int ks = 0; ks < 4; ks++) {
            uint32_t af[4][4], bf[4][2];
            #pragma unroll
            for (int nt = 0; nt < 4; nt++)
                ldsm2(bf[nt], rbase + 2 * GTILE_B + ((b_r + nt * 8) * GTS + ks * 16 + b_c) * 2);
            #pragma unroll
            for (int mt = 0; mt < 4; mt++)
                ldsm4(af[mt], rbase + ((a_r + mt * 16) * GTS + ks * 16 + a_c) * 2);
            #pragma unroll
            for (int mt = 0; mt < 4; mt++)
                #pragma unroll
                for (int nt = 0; nt < 4; nt++)
                    mma16816h(acc[mt][nt], af[mt], bf[nt]);
            #pragma unroll
            for (int mt = 0; mt < 4; mt++)
                ldsm4(af[mt], rbase + GTILE_B + ((a_r + mt * 16) * GTS + ks * 16 + a_c) * 2);
            #pragma unroll
            for (int mt = 0; mt < 4; mt++)
                #pragma unroll
                for (int nt = 0; nt < 4; nt++)
                    mma16816h(acc[mt][nt], af[mt], bf[nt]);
        }
        __syncthreads();
        if (c + 2 < nch) ISSUE(c + 2);
        else asm volatile("cp.async.commit_group;" ::: "memory");  // keep group count in sync
    }

    #pragma unroll
    for (int mt = 0; mt < 4; mt++) {
        int m0 = bm + wm * 64 + mt * 16 + (lane >> 2);
        #pragma unroll
        for (int nt = 0; nt < 4; nt++) {
            int col = bn + wn * 32 + nt * 8 + (lane & 3) * 2;
            float b0 = bias ? bias[col]     : 0.f;
            float b1 = bias ? bias[col + 1] : 0.f;
            float v0 = acc[mt][nt][0] + b0, v1 = acc[mt][nt][1] + b1;
            float v2 = acc[mt][nt][2] + b0, v3 = acc[mt][nt][3] + b1;
            if (act == 1) { v0 = gelu_f(v0); v1 = gelu_f(v1); v2 = gelu_f(v2); v3 = gelu_f(v3); }
            if (outF) {
                float2 p0; p0.x = v0; p0.y = v1;
                float2 p1; p1.x = v2; p1.y = v3;
                *(float2*)(outF + (size_t)m0 * N + col)       = p0;
                *(float2*)(outF + (size_t)(m0 + 8) * N + col) = p1;
            } else if (outdt == 1) {
                __half h0 = __float2half(v0), h1 = __float2half(v1);
                __half h2 = __float2half(v2), h3 = __float2half(v3);
                __half q0 = __float2half(v0 - __half2float(h0));
                __half q1 = __float2half(v1 - __half2float(h1));
                __half q2 = __float2half(v2 - __half2float(h2));
                __half q3 = __float2half(v3 - __half2float(h3));
                __half2 H01(h0, h1), H23(h2, h3), L01(q0, q1), L23(q2, q3);
                *(uint32_t*)((__half*)outH + (size_t)m0 * N + col)       = *(uint32_t*)&H01;
                *(uint32_t*)((__half*)outH + (size_t)(m0 + 8) * N + col) = *(uint32_t*)&H23;
                *(uint32_t*)((__half*)outL + (size_t)m0 * N + col)       = *(uint32_t*)&L01;
                *(uint32_t*)((__half*)outL + (size_t)(m0 + 8) * N + col) = *(uint32_t*)&L23;
            } else {
                __nv_bfloat16 h0 = __float2bfloat16(v0), h1 = __float2bfloat16(v1);
                __nv_bfloat16 h2 = __float2bfloat16(v2), h3 = __float2bfloat16(v3);
                __nv_bfloat16 q0 = __float2bfloat16(v0 - __bfloat162float(h0));
                __nv_bfloat16 q1 = __float2bfloat16(v1 - __bfloat162float(h1));
                __nv_bfloat16 q2 = __float2bfloat16(v2 - __bfloat162float(h2));
                __nv_bfloat16 q3 = __float2bfloat16(v3 - __bfloat162float(h3));
                __nv_bfloat162 H01(h0, h1), H23(h2, h3), L01(q0, q1), L23(q2, q3);
                *(uint32_t*)((__nv_bfloat16*)outH + (size_t)m0 * N + col)       = *(uint32_t*)&H01;
                *(uint32_t*)((__nv_bfloat16*)outH + (size_t)(m0 + 8) * N + col) = *(uint32_t*)&H23;
                *(uint32_t*)((__nv_bfloat16*)outL + (size_t)m0 * N + col)       = *(uint32_t*)&L01;
                *(uint32_t*)((__nv_bfloat16*)outL + (size_t)(m0 + 8) * N + col) = *(uint32_t*)&L23;
            }
        }
    }
    #undef ISSUE
}

// ============================================================================
// Fused flash attention (bf16x3) — V smem XOR-swizzled
// ============================================================================
#define FTS 72
#define FQH 0
#define FQL (64*FTS)
#define FKH (2*64*FTS)
#define FKL (3*64*FTS)
#define FVH (4*64*FTS)
#define FVL (5*64*FTS)
#define FMASK_B (6*64*FTS*2)
#define FSMEM_B (FMASK_B + 64*4)

__global__ void __launch_bounds__(128) flash_attn_k(
    const __nv_bfloat16* __restrict__ qkvh, const __nv_bfloat16* __restrict__ qkvl,
    const int* __restrict__ mask,
    __half* __restrict__ ctxh, __half* __restrict__ ctxl) {
    extern __shared__ char sm[];
    __nv_bfloat16* sb = (__nv_bfloat16*)sm;
    float* maskadd = (float*)(sm + FMASK_B);
    uint32_t sbase = smem_u32(sm);
    int tid = threadIdx.x, lane = tid & 31, w = tid >> 5;
    int bh = blockIdx.y, b = bh >> 3, h = bh & 7;
    int i0 = blockIdx.x * 64;

    #pragma unroll
    for (int i = 0; i < 4; i++) {
        int lin = i * 128 + tid;
        int r = lin >> 3, c8 = lin & 7;
        int gr = i0 + r; if (gr >= SEQ_) gr = SEQ_ - 1;
        size_t base = (size_t)(b * SEQ_ + gr) * NQKV + h * 64 + c8 * 8;
        *(uint4*)(sb + FQH + r * FTS + c8 * 8) = *(const uint4*)(qkvh + base);
        *(uint4*)(sb + FQL + r * FTS + c8 * 8) = *(const uint4*)(qkvl + base);
    }

    float m0 = -INFINITY, m1 = -INFINITY, l0 = 0.f, l1 = 0.f;
    float O[8][4];
    #pragma unroll
    for (int nt = 0; nt < 8; nt++)
        #pragma unroll
        for (int e = 0; e < 4; e++) O[nt][e] = 0.f;

    int a_r = w * 16 + (lane & 15);
    int a_c = (lane >> 4) * 8;
    int b_r = lane & 7;
    int b_c = ((lane >> 3) & 1) * 8;
    int g = lane >> 2;

    for (int j0 = 0; j0 < 960; j0 += 64) {
        #pragma unroll
        for (int i = 0; i < 4; i++) {
            int lin = i * 128 + tid;
            int r = lin >> 3, c8 = lin & 7;
            int gr = j0 + r; if (gr >= SEQ_) gr = SEQ_ - 1;
            size_t base = (size_t)(b * SEQ_ + gr) * NQKV + h * 64 + c8 * 8;
            *(uint4*)(sb + FKH + r * FTS + c8 * 8) = *(const uint4*)(qkvh + base + 512);
            *(uint4*)(sb + FKL + r * FTS + c8 * 8) = *(const uint4*)(qkvl + base + 512);
            uint4 vh4 = *(const uint4*)(qkvh + base + 1024);
            uint4 vl4 = *(const uint4*)(qkvl + base + 1024);
            const __nv_bfloat16* ph = (const __nv_bfloat16*)&vh4;
            const __nv_bfloat16* pl = (const __nv_bfloat16*)&vl4;
            int d0 = c8 * 8;
            int rs = r ^ (c8 << 3);
            #pragma unroll
            for (int u = 0; u < 8; u++) {
                sb[FVH + (d0 + u) * FTS + rs] = ph[u];
                sb[FVL + (d0 + u) * FTS + rs] = pl[u];
            }
        }
        if (tid < 64) {
            int j = j0 + tid;
            maskadd[tid] = (j >= SEQ_) ? -INFINITY
                          : (mask[b * SEQ_ + j] == 0 ? -1e9f : 0.f);
        }
        __syncthreads();

        float S[8][4];
        #pragma unroll
        for (int nt = 0; nt < 8; nt++)
            #pragma unroll
            for (int e = 0; e < 4; e++) S[nt][e] = 0.f;
        #pragma unroll
        for (int kc = 0; kc < 4; kc++) {
            uint32_t aqh[4], aql[4];
            ldsm4(aqh, sbase + (FQH + a_r * FTS + kc * 16 + a_c) * 2);
            ldsm4(aql, sbase + (FQL + a_r * FTS + kc * 16 + a_c) * 2);
            #pragma unroll
            for (int nt = 0; nt < 8; nt++) {
                uint32_t bkh[2], bkl[2];
                ldsm2(bkh, sbase + (FKH + (nt * 8 + b_r) * FTS + kc * 16 + b_c) * 2);
                ldsm2(bkl, sbase + (FKL + (nt * 8 + b_r) * FTS + kc * 16 + b_c) * 2);
                mma16816(S[nt], aqh, bkh);
                mma16816(S[nt], aqh, bkl);
                mma16816(S[nt], aql, bkh);
            }
        }
        #pragma unroll
        for (int nt = 0; nt < 8; nt++) {
            int col = nt * 8 + (lane & 3) * 2;
            float ma0 = maskadd[col], ma1 = maskadd[col + 1];
            S[nt][0] = fmaf(S[nt][0], 0.125f, ma0);
            S[nt][1] = fmaf(S[nt][1], 0.125f, ma1);
            S[nt][2] = fmaf(S[nt][2], 0.125f, ma0);
            S[nt][3] = fmaf(S[nt][3], 0.125f, ma1);
        }
        float rm0 = -INFINITY, rm1 = -INFINITY;
        #pragma unroll
        for (int nt = 0; nt < 8; nt++) {
            rm0 = fmaxf(rm0, fmaxf(S[nt][0], S[nt][1]));
            rm1 = fmaxf(rm1, fmaxf(S[nt][2], S[nt][3]));
        }
        rm0 = fmaxf(rm0, __shfl_xor_sync(~0u, rm0, 1));
        rm0 = fmaxf(rm0, __shfl_xor_sync(~0u, rm0, 2));
        rm1 = fmaxf(rm1, __shfl_xor_sync(~0u, rm1, 1));
        rm1 = fmaxf(rm1, __shfl_xor_sync(~0u, rm1, 2));
        float nm0 = fmaxf(m0, rm0), nm1 = fmaxf(m1, rm1);
        float f0 = expf(m0 - nm0), f1 = expf(m1 - nm1);
        m0 = nm0; m1 = nm1;
        float s0 = 0.f, s1 = 0.f;
        #pragma unroll
        for (int nt = 0; nt < 8; nt++) {
            S[nt][0] = expf(S[nt][0] - m0);
            S[nt][1] = expf(S[nt][1] - m0);
            S[nt][2] = expf(S[nt][2] - m1);
            S[nt][3] = expf(S[nt][3] - m1);
            s0 += S[nt][0] + S[nt][1];
            s1 += S[nt][2] + S[nt][3];
        }
        s0 += __shfl_xor_sync(~0u, s0, 1);
        s0 += __shfl_xor_sync(~0u, s0, 2);
        s1 += __shfl_xor_sync(~0u, s1, 1);
        s1 += __shfl_xor_sync(~0u, s1, 2);
        l0 = l0 * f0 + s0;
        l1 = l1 * f1 + s1;
        #pragma unroll
        for (int nt = 0; nt < 8; nt++) {
            O[nt][0] *= f0; O[nt][1] *= f0;
            O[nt][2] *= f1; O[nt][3] *= f1;
        }
        #pragma unroll
        for (int kc = 0; kc < 4; kc++) {
            uint2 h0, l0r, h1, l1r;
            pack_hilo(make_float4(S[2*kc][0], S[2*kc][1], S[2*kc][2], S[2*kc][3]), h0, l0r);
            pack_hilo(make_float4(S[2*kc+1][0], S[2*kc+1][1], S[2*kc+1][2], S[2*kc+1][3]), h1, l1r);
            uint32_t aph[4] = { h0.x, h0.y, h1.x, h1.y };
            uint32_t apl[4] = { l0r.x, l0r.y, l1r.x, l1r.y };
            #pragma unroll
            for (int nt = 0; nt < 8; nt++) {
                uint32_t vaddr = sbase + ((nt * 8 + b_r) * FTS + ((kc * 16 + b_c) ^ (nt << 3))) * 2;
                uint32_t bvh[2], bvl[2];
                ldsm2(bvh, vaddr + FVH * 2);
                ldsm2(bvl, vaddr + FVL * 2);
                mma16816(O[nt], aph, bvh);
                mma16816(O[nt], aph, bvl);
                mma16816(O[nt], apl, bvh);
            }
        }
        __syncthreads();
    }

    float inv0 = 1.f / l0, inv1 = 1.f / l1;
    int r0 = i0 + w * 16 + g, r1 = r0 + 8;
    #pragma unroll
    for (int nt = 0; nt < 8; nt++) {
        int d = h * DH_ + nt * 8 + (lane & 3) * 2;
        if (r0 < SEQ_) {
            float v0 = O[nt][0] * inv0, v1 = O[nt][1] * inv0;
            __half h0 = __float2half(v0), h1 = __float2half(v1);
            __half q0 = __float2half(v0 - __half2float(h0));
            __half q1 = __float2half(v1 - __half2float(h1));
            __half2 Hh(h0, h1), Lw(q0, q1);
            *(uint32_t*)(ctxh + (size_t)(b * SEQ_ + r0) * D_ + d) = *(uint32_t*)&Hh;
            *(uint32_t*)(ctxl + (size_t)(b * SEQ_ + r0) * D_ + d) = *(uint32_t*)&Lw;
        }
        if (r1 < SEQ_) {
            float v0 = O[nt][2] * inv1, v1 = O[nt][3] * inv1;
            __half h0 = __float2half(v0), h1 = __float2half(v1);
            __half q0 = __float2half(v0 - __half2float(h0));
            __half q1 = __float2half(v1 - __half2float(h1));
            __half2 Hh(h0, h1), Lw(q0, q1);
            *(uint32_t*)(ctxh + (size_t)(b * SEQ_ + r1) * D_ + d) = *(uint32_t*)&Hh;
            *(uint32_t*)(ctxl + (size_t)(b * SEQ_ + r1) * D_ + d) = *(uint32_t*)&Lw;
        }
    }
}

// ---------------- gather (all three feature maps in one launch) -------------
__global__ void gather_all_k(const float* __restrict__ f_org,
                             const float* __restrict__ f_r1,
                             const float* __restrict__ f_r2,
                             __half* __restrict__ xh, __half* __restrict__ xl) {
    __shared__ float tile[32][33];
    int bx = blockIdx.x;
    const float* feat; int HW, t0, hw0;
    if (bx < 24)      { feat = f_org; HW = 768; t0 = 1;   hw0 = bx * 32; }
    else if (bx < 28) { feat = f_r1;  HW = 108; t0 = 769; hw0 = (bx - 24) * 32; }
    else              { feat = f_r2;  HW = 35;  t0 = 877; hw0 = (bx - 28) * 32; }
    int b  = blockIdx.z;
    int c0 = blockIdx.y * 32;
    const float* fb = feat + (size_t)b * CIN_ * HW;
    #pragma unroll
    for (int kk = 0; kk < 32; kk += 8) {
        int c  = c0 + threadIdx.y + kk;
        int hw = hw0 + threadIdx.x;
        tile[threadIdx.y + kk][threadIdx.x] = (hw < HW) ? fb[(size_t)c * HW + hw] : 0.f;
    }
    __syncthreads();
    #pragma unroll
    for (int kk = 0; kk < 32; kk += 8) {
        int hw = hw0 + threadIdx.y + kk;
        int c  = c0 + threadIdx.x;
        if (hw < HW) {
            float v = tile[threadIdx.x][threadIdx.y + kk];
            __half h = __float2half(v);
            __half l = __float2half(v - __half2float(h));
            size_t idx = ((size_t)b * SEQ_ + t0 + hw) * CIN_ + c;
            xh[idx] = h; xl[idx] = l;
        }
    }
}

__global__ void zero_xin_row0_k(__half* __restrict__ xh, __half* __restrict__ xl) {
    int idx = blockIdx.x * 256 + threadIdx.x;
    if (idx >= B_ * CIN_) return;
    int b = idx / CIN_, c = idx % CIN_;
    size_t o = (size_t)b * SEQ_ * CIN_ + c;
    xh[o] = __float2half(0.f);
    xl[o] = __float2half(0.f);
}

// ---------------- embed epilogue (emits x fp16 planes) ----------------------
__global__ void embed_add_k(const float* __restrict__ conv_b,
                            const float* __restrict__ e_org,
                            const float* __restrict__ e_r1,
                            const float* __restrict__ e_r2,
                            const float* __restrict__ pos,
                            float* __restrict__ x,
                            __half* __restrict__ xh, __half* __restrict__ xl) {
    int idx = blockIdx.x * 256 + threadIdx.x;
    const int total = B_ * 911 * D_;
    if (idx >= total) return;
    int d = idx & 511;
    int rest = idx >> 9;
    int tt = rest % 911;
    int b  = rest / 911;
    int ti, tj; const float* ce;
    if (tt < 768)      { int hh = tt >> 5,  ww = tt & 31;  ce = e_org; ti = hh*GRIDN/24; tj = ww*GRIDN/32; }
    else if (tt < 876) { int u = tt - 768;  int hh = u/12, ww = u%12; ce = e_r1; ti = hh*GRIDN/9;  tj = ww*GRIDN/12; }
    else               { int u = tt - 876;  int hh = u/7,  ww = u%7;  ce = e_r2; ti = hh*GRIDN/5;  tj = ww*GRIDN/7;  }
    size_t o = ((size_t)(b * SEQ_ + tt + 1)) * D_ + d;
    float v = x[o] + conv_b[d] + ce[d] + pos[(size_t)(ti * GRIDN + tj) * D_ + d];
    x[o] = v;
    __half h = __float2half(v);
    __half l = __float2half(v - __half2float(h));
    xh[o] = h; xl[o] = l;
}

__global__ void cls_set_k(const float* __restrict__ c, float* __restrict__ x,
                          __half* __restrict__ xh, __half* __restrict__ xl) {
    int idx = blockIdx.x * 256 + threadIdx.x;
    if (idx >= B_ * D_) return;
    int b = idx >> 9, d = idx & 511;
    size_t o = (size_t)b * SEQ_ * D_ + d;
    float v = c[d];
    x[o] = v;
    __half h = __float2half(v);
    __half l = __float2half(v - __half2float(h));
    xh[o] = h; xl[o] = l;
}

// ---------------- residual + LayerNorm (emits fp16 planes) ------------------
__global__ __launch_bounds__(128) void add_ln_k(
    const float* __restrict__ xin, const float* __restrict__ add,
    const float* __restrict__ g, const float* __restrict__ beta,
    float* __restrict__ xout, __half* __restrict__ xh, __half* __restrict__ xl) {
    __shared__ float red[4];
    __shared__ float bval;
    int row = blockIdx.x, tid = threadIdx.x;
    float4 xv = ((const float4*)(xin + (size_t)row * D_))[tid];
    float4 av = ((const float4*)(add + (size_t)row * D_))[tid];
    float4 s;
    s.x = xv.x + av.x; s.y = xv.y + av.y; s.z = xv.z + av.z; s.w = xv.w + av.w;
    float sum = s.x + s.y + s.z + s.w;
    #pragma unroll
    for (int o = 16; o > 0; o >>= 1) sum += __shfl_xor_sync(~0u, sum, o);
    if ((tid & 31) == 0) red[tid >> 5] = sum;
    __syncthreads();
    if (tid == 0) bval = (red[0] + red[1] + red[2] + red[3]) * (1.f / D_);
    __syncthreads();
    float m = bval;
    float d0 = s.x - m, d1 = s.y - m, d2 = s.z - m, d3 = s.w - m;
    float sq = d0 * d0 + d1 * d1 + d2 * d2 + d3 * d3;
    #pragma unroll
    for (int o = 16; o > 0; o >>= 1) sq += __shfl_xor_sync(~0u, sq, o);
    __syncthreads();
    if ((tid & 31) == 0) red[tid >> 5] = sq;
    __syncthreads();
    if (tid == 0) bval = rsqrtf((red[0] + red[1] + red[2] + red[3]) * (1.f / D_) + 1e-6f);
    __syncthreads();
    float rs = bval;
    float4 gv = ((const float4*)g)[tid];
    float4 bv = ((const float4*)beta)[tid];
    float4 o;
    o.x = d0 * rs * gv.x + bv.x; o.y = d1 * rs * gv.y + bv.y;
    o.z = d2 * rs * gv.z + bv.z; o.w = d3 * rs * gv.w + bv.w;
    ((float4*)(xout + (size_t)row * D_))[tid] = o;
    uint2 hh, ll;
    pack_hilo_h(o, hh, ll);
    *(uint2*)(xh + (size_t)row * D_ + tid * 4) = hh;
    *(uint2*)(xl + (size_t)row * D_ + tid * 4) = ll;
}

// ---------------- head ------------------------------------------------------
__global__ __launch_bounds__(256) void head_mlp_k(
    const float* __restrict__ x, const float* __restrict__ w1,
    float* __restrict__ hm) {
    __shared__ float cls[512];
    int b = blockIdx.x;
    for (int d = threadIdx.x; d < 512; d += 256) cls[d] = x[(size_t)b * SEQ_ * D_ + d];
    __syncthreads();
    for (int n = threadIdx.x; n < DMLP_; n += 256) {
        const float* w = w1 + (size_t)n * 512;
        float s = 0.f;
        for (int d = 0; d < 512; d++) s += cls[d] * w[d];
        hm[b * DMLP_ + n] = gelu_f(s);
    }
}

__global__ __launch_bounds__(256) void head_out_k(
    const float* __restrict__ hm, const float* __restrict__ w2,
    float* __restrict__ out) {
    __shared__ float red[8];
    int b = blockIdx.x, tid = threadIdx.x;
    float s = 0.f;
    for (int n = tid; n < DMLP_; n += 256) s += hm[b * DMLP_ + n] * w2[n];
    #pragma unroll
    for (int o = 16; o > 0; o >>= 1) s += __shfl_xor_sync(~0u, s, o);
    if ((tid & 31) == 0) red[tid >> 5] = s;
    __syncthreads();
    if (tid == 0) {
        float t = 0; for (int w = 0; w < 8; w++) t += red[w];
        out[b] = t;
    }
}

// ---------------- host orchestration ----------------------------------------
extern "C" void kernel_launch(void* const* d_in, const int* in_sizes, int n_in,
                              void* d_out, int out_size) {
    const float* feat_org = (const float*)d_in[0];
    const float* feat_r1  = (const float*)d_in[1];
    const float* feat_r2  = (const float*)d_in[2];
    const float* conv_w   = (const float*)d_in[3];
    const float* conv_b   = (const float*)d_in[4];
    const float* e_org    = (const float*)d_in[5];
    const float* e_r1     = (const float*)d_in[6];
    const float* e_r2     = (const float*)d_in[7];
    const float* pos      = (const float*)d_in[8];
    const float* cls_tok  = (const float*)d_in[9];
    const float* Wq = (const float*)d_in[10]; const float* bq = (const float*)d_in[11];
    const float* Wk = (const float*)d_in[12]; const float* bk = (const float*)d_in[13];
    const float* Wv = (const float*)d_in[14]; const float* bv = (const float*)d_in[15];
    const float* Wo = (const float*)d_in[16]; const float* bo = (const float*)d_in[17];
    const float* ln1g = (const float*)d_in[18]; const float* ln1b = (const float*)d_in[19];
    const float* w1 = (const float*)d_in[20]; const float* b1 = (const float*)d_in[21];
    const float* w2 = (const float*)d_in[22]; const float* b2 = (const float*)d_in[23];
    const float* ln2g = (const float*)d_in[24]; const float* ln2b = (const float*)d_in[25];
    const float* pw1 = (const float*)d_in[26]; const float* pw2 = (const float*)d_in[27];
    const int*   mask = (const int*)d_in[28];

    __half *wconv, *wqkv, *wo, *w1h, *w2h, *xinh, *xinl, *xh, *xl, *ctxh, *ctxl, *h1h, *h1l;
    __nv_bfloat16 *qkvh, *qkvl;
    float *x, *att, *bqkv, *hmlp;
    cudaGetSymbolAddress((void**)&wconv, g_wconv);
    cudaGetSymbolAddress((void**)&wqkv, g_wqkv);
    cudaGetSymbolAddress((void**)&wo, g_wo);
    cudaGetSymbolAddress((void**)&w1h, g_w1);
    cudaGetSymbolAddress((void**)&w2h, g_w2);
    cudaGetSymbolAddress((void**)&xinh, g_xinh);
    cudaGetSymbolAddress((void**)&xinl, g_xinl);
    cudaGetSymbolAddress((void**)&xh, g_xh);
    cudaGetSymbolAddress((void**)&xl, g_xl);
    cudaGetSymbolAddress((void**)&qkvh, g_qkvh);
    cudaGetSymbolAddress((void**)&qkvl, g_qkvl);
    cudaGetSymbolAddress((void**)&ctxh, g_ctxh);
    cudaGetSymbolAddress((void**)&ctxl, g_ctxl);
    cudaGetSymbolAddress((void**)&h1h, g_h1h);
    cudaGetSymbolAddress((void**)&h1l, g_h1l);
    cudaGetSymbolAddress((void**)&x, g_x);
    cudaGetSymbolAddress((void**)&att, g_att);
    cudaGetSymbolAddress((void**)&bqkv, g_bqkv);
    cudaGetSymbolAddress((void**)&hmlp, g_hmlp);

    cudaFuncSetAttribute(fp16_gemm_nt, cudaFuncAttributeMaxDynamicSharedMemorySize, GSMEM_B);
    cudaFuncSetAttribute(flash_attn_k, cudaFuncAttributeMaxDynamicSharedMemorySize, FSMEM_B);

    // launch order: idx 3 = embed GEMM (ncu profiles our index 3)
    cvt_all_k<<<19456 + 36, 256>>>(conv_w, Wq, Wk, Wv, Wo, w1, w2, bq, bk, bv,
                                   wconv, wqkv, wo, w1h, w2h, bqkv);          // 0
    gather_all_k<<<dim3(30, CIN_ / 32, B_), dim3(32, 8)>>>(feat_org, feat_r1, feat_r2, xinh, xinl); // 1
    zero_xin_row0_k<<<(B_*CIN_ + 255)/256, 256>>>(xinh, xinl);                 // 2
    fp16_gemm_nt<<<dim3(4, 57), 256, GSMEM_B>>>(M_, D_, CIN_, xinh, xinl, wconv,
        nullptr, x, nullptr, nullptr, 0, 0);                                   // 3 (profiled)
    embed_add_k<<<(B_ * 911 * D_ + 255) / 256, 256>>>(conv_b, e_org, e_r1, e_r2, pos, x, xh, xl);
    cls_set_k<<<(B_ * D_ + 255) / 256, 256>>>(cls_tok, x, xh, xl);

    for (int i = 0; i < L_; i++) {
        fp16_gemm_nt<<<dim3(12, 57), 256, GSMEM_B>>>(M_, NQKV, D_, xh, xl,
            wqkv + (size_t)i*NQKV*D_, bqkv + i*NQKV, nullptr, qkvh, qkvl, 2, 0);

        flash_attn_k<<<dim3(15, B_ * H_), 128, FSMEM_B>>>(qkvh, qkvl, mask, ctxh, ctxl);

        fp16_gemm_nt<<<dim3(4, 57), 256, GSMEM_B>>>(M_, D_, D_, ctxh, ctxl,
            wo + (size_t)i*D_*D_, bo + i*D_, att, nullptr, nullptr, 0, 0);
        add_ln_k<<<M_, 128>>>(x, att, ln1g + i*D_, ln1b + i*D_, x, xh, xl);

        fp16_gemm_nt<<<dim3(16, 57), 256, GSMEM_B>>>(M_, DFF_, D_, xh, xl,
            w1h + (size_t)i*DFF_*D_, b1 + i*DFF_, nullptr, h1h, h1l, 1, 1);
        fp16_gemm_nt<<<dim3(4, 57), 256, GSMEM_B>>>(M_, D_, DFF_, h1h, h1l,
            w2h + (size_t)i*D_*DFF_, b2 + i*D_, att, nullptr, nullptr, 0, 0);
        add_ln_k<<<M_, 128>>>(x, att, ln2g + i*D_, ln2b + i*D_, x, xh, xl);
    }

    head_mlp_k<<<B_, 256>>>(x, pw1, hmlp);
    head_out_k<<<B_, 256>>>(hmlp, pw2, (float*)d_out);
}